// round 12
// baseline (speedup 1.0000x reference)
#include <cuda_runtime.h>
#include <cuda_bf16.h>
#include <math.h>

// Problem constants
#define B_  16
#define CIN 512
#define L_  1024
#define COUT 1024
#define K_  5
#define DW  512
#define HW  196
#define KCONV (CIN * K_)   // 2560
#define PP  224            // padded p dimension

// Output layout (concatenated tuple): out, word_embed, img_conv, attn
#define OUT_WE   8388608u
#define OUT_IMG  16777216u
#define OUT_ATTN 18382848u

typedef __nv_bfloat16 bf16;

// ---------------------------------------------------------------------------
// Scratch (device globals; allocation-free rule)
// ---------------------------------------------------------------------------
__device__ float g_w[COUT * KCONV];            // normalized conv weights (co, c, t)
__device__ float g_h[B_ * DW * L_];            // GLU output fp32 (b, ch, l)
__device__ bf16 g_xTh[B_ * L_ * CIN], g_xTl[B_ * L_ * CIN];   // x^T split (b, l, c)
__device__ bf16 g_cwp[8 * 80 * 8192];          // conv W fragment-packed tiles (16KB each)
__device__ bf16 g_w1p[4 * 16 * 2 * 5120];      // fc1 W packed tiles
__device__ bf16 g_w2p[4 * 16 * 2 * 5120];      // fc2 W packed tiles
__device__ bf16 g_hTh[B_ * L_ * DW], g_hTl[B_ * L_ * DW];     // h split (b, l, c)
__device__ bf16 g_qh[B_ * L_ * DW],  g_ql[B_ * L_ * DW];      // q split (b, l, a)
__device__ bf16 g_cxh[B_ * L_ * DW], g_cxl[B_ * L_ * DW];     // ctx split (b, l, a)
__device__ bf16 g_fTh[B_ * PP * DW], g_fTl[B_ * PP * DW];     // feat^T split (b, p, a)
__device__ bf16 g_fh[B_ * DW * PP],  g_fl[B_ * DW * PP];      // feat split (b, a, p)

__device__ __forceinline__ void split2(float v, bf16& h, bf16& l) {
    h = __float2bfloat16(v);
    l = __float2bfloat16(v - __bfloat162float(h));
}

// ---- async copy primitives ----
__device__ __forceinline__ void cp16(void* dst, const void* src) {
    unsigned d = (unsigned)__cvta_generic_to_shared(dst);
    asm volatile("cp.async.cg.shared.global [%0], [%1], 16;\n" :: "r"(d), "l"(src));
}
#define CP_COMMIT() asm volatile("cp.async.commit_group;\n")
#define CP_WAIT0()  asm volatile("cp.async.wait_group 0;\n")
#define CP_WAIT1()  asm volatile("cp.async.wait_group 1;\n")

#define MBAR_INIT(addr, cnt) \
    asm volatile("mbarrier.init.shared.b64 [%0], %1;" :: "r"(addr), "r"(cnt) : "memory")
#define MBAR_EXPECT(addr, tx) \
    asm volatile("mbarrier.arrive.expect_tx.shared.b64 _, [%0], %1;" :: "r"(addr), "r"(tx) : "memory")

__device__ __forceinline__ void mbar_wait(unsigned mbar, unsigned parity) {
    asm volatile(
        "{\n\t.reg .pred P;\n\t"
        "W_%=:\n\t"
        "mbarrier.try_wait.parity.acquire.cta.shared::cta.b64 P, [%0], %1;\n\t"
        "@!P bra W_%=;\n\t}"
        :: "r"(mbar), "r"(parity) : "memory");
}

__device__ __forceinline__ void bulk_g2s(unsigned dst_smem, const void* src,
                                         unsigned bytes, unsigned mbar) {
    asm volatile(
        "cp.async.bulk.shared::cluster.global.mbarrier::complete_tx::bytes "
        "[%0], [%1], %2, [%3];"
        :: "r"(dst_smem), "l"(src), "r"(bytes), "r"(mbar) : "memory");
}

// ---------------------------------------------------------------------------
// Prep kernels
// ---------------------------------------------------------------------------
__global__ void wnorm_kernel(const float* __restrict__ v,
                             const float* __restrict__ g) {
    int co = blockIdx.x;
    const float* vr = v + (size_t)co * KCONV;
    float s = 0.f;
    for (int i = threadIdx.x; i < KCONV; i += 256) { float t = vr[i]; s += t * t; }
    __shared__ float red[256];
    red[threadIdx.x] = s;
    __syncthreads();
    for (int st = 128; st > 0; st >>= 1) {
        if (threadIdx.x < st) red[threadIdx.x] += red[threadIdx.x + st];
        __syncthreads();
    }
    float scale = g[co] / sqrtf(red[0]);
    float* wr = g_w + (size_t)co * KCONV;
    for (int i = threadIdx.x; i < KCONV; i += 256) wr[i] = scale * vr[i];
}

// pack conv weights into MMA-fragment order.
// tile (mb, kc), kc = t*16 + ci. Tile = 1024 16B-chunks:
//   chunk u: lane=u&31, mt=(u>>5)&3, wm=(u>>7)&1, ks=(u>>8)&1, plane=(u>>9)&1
//   chunk = 4 words w: row = wm*64+mt*16+(lane>>2) + ((w&1)?8:0),
//                      k   = ks*16+(lane&3)*2 + (w>>1)*8  (2 bf16: k, k+1)
__global__ void pack_conv_kernel() {
    const int kc = blockIdx.x, mb = blockIdx.y;
    const int t = kc / 16, ci = kc % 16;
    bf16* dst = g_cwp + (size_t)(mb * 80 + kc) * 8192;
    for (int u = threadIdx.x; u < 1024; u += 256) {
        int lane2 = u & 31, mt = (u >> 5) & 3, wm2 = (u >> 7) & 1;
        int ks = (u >> 8) & 1, plane = (u >> 9) & 1;
        int row0 = wm2 * 64 + mt * 16 + (lane2 >> 2);
        int kb = ks * 16 + (lane2 & 3) * 2;
        unsigned words[4];
#pragma unroll
        for (int w = 0; w < 4; w++) {
            int row = row0 + ((w & 1) ? 8 : 0);
            int k = kb + (w >> 1) * 8;
            int m = mb * 128 + row;
            int co = (m & 1) ? (512 + (m >> 1)) : (m >> 1);
            unsigned short p0, p1;
#pragma unroll
            for (int e = 0; e < 2; e++) {
                int c = ci * 32 + k + e;
                float v = g_w[(size_t)co * KCONV + c * K_ + t];
                bf16 hi, lo; split2(v, hi, lo);
                bf16 sel = plane ? lo : hi;
                unsigned short us = *(unsigned short*)&sel;
                if (e == 0) p0 = us; else p1 = us;
            }
            words[w] = (unsigned)p0 | ((unsigned)p1 << 16);
        }
        *(uint4*)(dst + u * 8) = make_uint4(words[0], words[1], words[2], words[3]);
    }
}

// pack fc weights: W [m=512][k=512] row-major -> tiles [mb 4][kc 16][plane][128][40]
__global__ void pack_fc_kernel(const float* __restrict__ W, bf16* __restrict__ dstall) {
    const int kc = blockIdx.x, mb = blockIdx.y, zz = blockIdx.z;
    bf16* dst = dstall + ((size_t)(mb * 16 + kc)) * 2 * 5120;
    for (int i = threadIdx.x; i < 1024; i += 256) {
        int idx = zz * 1024 + i;
        int row = idx >> 5, kcol = idx & 31;
        float v = W[(size_t)(mb * 128 + row) * 512 + kc * 32 + kcol];
        bf16 hi, lo; split2(v, hi, lo);
        dst[row * 40 + kcol] = hi;
        dst[5120 + row * 40 + kcol] = lo;
    }
}

// x (b,c,l) -> xT split (b,l,c)
__global__ void xT_kernel(const float* __restrict__ x) {
    __shared__ float t[32][33];
    const int b = blockIdx.z, l0 = blockIdx.x * 32, c0 = blockIdx.y * 32;
    const int tx = threadIdx.x, ty0 = threadIdx.y;
#pragma unroll
    for (int j = 0; j < 4; j++) {
        int ty = ty0 + j * 8;
        t[ty][tx] = x[((size_t)b * CIN + c0 + ty) * L_ + l0 + tx];
    }
    __syncthreads();
#pragma unroll
    for (int j = 0; j < 4; j++) {
        int ty = ty0 + j * 8;
        float v = t[tx][ty];
        bf16 hi, lo; split2(v, hi, lo);
        size_t off = ((size_t)b * L_ + l0 + ty) * 512 + c0 + tx;
        g_xTh[off] = hi; g_xTl[off] = lo;
    }
}

// feat^T split (b, p, a); p>=196 rows zero.
__global__ void featT_kernel(const float* __restrict__ img) {
    __shared__ float t[32][33];
    const int b = blockIdx.z, p0 = blockIdx.x * 32, a0 = blockIdx.y * 32;
    const int tx = threadIdx.x, ty0 = threadIdx.y;
#pragma unroll
    for (int j = 0; j < 4; j++) {
        int ty = ty0 + j * 8;
        int a = a0 + ty, p = p0 + tx;
        t[ty][tx] = (p < HW) ? img[((size_t)b * 512 + a) * HW + p] : 0.f;
    }
    __syncthreads();
#pragma unroll
    for (int j = 0; j < 4; j++) {
        int ty = ty0 + j * 8;
        float v = t[tx][ty];
        bf16 hi, lo; split2(v, hi, lo);
        size_t off = ((size_t)b * PP + p0 + ty) * 512 + a0 + tx;
        g_fTh[off] = hi; g_fTl[off] = lo;
    }
}

__global__ void featpad_kernel(const float* __restrict__ img) {
    int idx = blockIdx.x * 256 + threadIdx.x;
    if (idx >= B_ * 512 * PP) return;
    int p = idx % PP, ba = idx / PP;
    float v = (p < HW) ? img[(size_t)ba * HW + p] : 0.f;
    bf16 hi, lo; split2(v, hi, lo);
    g_fh[idx] = hi; g_fl[idx] = lo;
}

// ---------------------------------------------------------------------------
// MMA helper
// ---------------------------------------------------------------------------
__device__ __forceinline__ void mma_bf16(float* c, const unsigned* a,
                                         unsigned b0, unsigned b1) {
    asm volatile(
        "mma.sync.aligned.m16n8k16.row.col.f32.bf16.bf16.f32 "
        "{%0,%1,%2,%3}, {%4,%5,%6,%7}, {%8,%9}, {%0,%1,%2,%3};\n"
        : "+f"(c[0]), "+f"(c[1]), "+f"(c[2]), "+f"(c[3])
        : "r"(a[0]), "r"(a[1]), "r"(a[2]), "r"(a[3]), "r"(b0), "r"(b1));
}

#define APAD 40
#define BK 32

// ---------------------------------------------------------------------------
// Conv GEMM (R12): tile 128m x 256n, 1 CTA/SM, 8 warps (wm 2 x wn 4),
// warp tile 4mt x 8nt. A in fragment order (LDS.128), bulk-staged,
// double-buffered. B = xT rows [l0-4, l0+256), pitch 40, t-shift reuse x5.
//   smem: A 2x16384 @0 ; B 2x41600 @32768 ; mbar @115968
// ---------------------------------------------------------------------------
#define CV_A_STAGE 16384
#define CV_B_OFF   32768
#define CV_BPLANE  20800     // 260 rows * 40 * 2B
#define CV_B_STAGE 41600
#define CV_MBAR    115968
#define CV_SMEM    116096

__global__ __launch_bounds__(256, 1) void conv_gemm(const float* __restrict__ bias) {
    extern __shared__ __align__(16) unsigned char dynsm[];
    const int b = blockIdx.z, mb = blockIdx.y, l0 = blockIdx.x * 256;
    const int tid = threadIdx.x;
    const int lane = tid & 31, warp = tid >> 5;
    const int wm = warp >> 2, wn = warp & 3;

    unsigned smem_base = (unsigned)__cvta_generic_to_shared(dynsm);
    unsigned mbar0 = smem_base + CV_MBAR, mbar1 = mbar0 + 8;
    if (tid == 0) { MBAR_INIT(mbar0, 1); MBAR_INIT(mbar1, 1); }
    __syncthreads();

    float acc[4][8][4];
#pragma unroll
    for (int mt = 0; mt < 4; mt++)
#pragma unroll
        for (int nt = 0; nt < 8; nt++)
#pragma unroll
            for (int j = 0; j < 4; j++) acc[mt][nt][j] = 0.f;

    auto issueA = [&](int s, int kc) {
        if (tid == 0) {
            unsigned mbx = s ? mbar1 : mbar0;
            MBAR_EXPECT(mbx, CV_A_STAGE);
            const char* src = (const char*)g_cwp + (size_t)(mb * 80 + kc) * CV_A_STAGE;
            bulk_g2s(smem_base + s * CV_A_STAGE, src, CV_A_STAGE, mbx);
        }
    };
    auto issueB = [&](int sb, int ci) {
        int c0 = ci * 32;
        unsigned char* dst0 = dynsm + CV_B_OFF + sb * CV_B_STAGE;
        // 2 planes x 260 rows x 4 chunks = 2080 cp16
#pragma unroll
        for (int ii = 0; ii < 9; ii++) {
            int u = ii * 256 + tid;
            if (u < 2080) {
                int plane = (u >= 1040) ? 1 : 0;
                int v = u - plane * 1040;
                int r = v >> 2, j = v & 3;
                if (!(l0 == 0 && r < 4)) {
                    const bf16* src = (plane ? g_xTl : g_xTh) +
                        ((size_t)b * L_ + l0 - 4 + r) * 512 + c0 + j * 8;
                    cp16(dst0 + plane * CV_BPLANE + r * 80 + j * 16, src);
                }
            }
        }
        if (l0 == 0 && tid < 160) {
            int plane = tid / 80, v = tid % 80, r = v / 20, w = v % 20;
            *(unsigned*)(dst0 + plane * CV_BPLANE + r * 80 + w * 4) = 0u;
        }
    };

    // prologue
    issueB(0, 0);
    CP_COMMIT();
    issueA(0, 0);
    int ph0 = 0, ph1 = 0;

    for (int i = 0; i < 80; i++) {
        const int ci = i / 5, t = i - ci * 5, s = i & 1;
        if (i + 1 < 80) {
            int ni = i + 1, nci = ni / 5, nt2 = ni - nci * 5;
            issueA(ni & 1, nt2 * 16 + nci);
            if (nt2 == 0) { issueB(nci & 1, nci); CP_COMMIT(); }
        }
        if (s == 0) { mbar_wait(mbar0, ph0); ph0 ^= 1; }
        else        { mbar_wait(mbar1, ph1); ph1 ^= 1; }
        if (t == 0) CP_WAIT0();
        __syncthreads();

        const unsigned char* Ab = dynsm + s * CV_A_STAGE;
        const bf16* Bh = (const bf16*)(dynsm + CV_B_OFF + (ci & 1) * CV_B_STAGE);
        const bf16* Bl = (const bf16*)((const unsigned char*)Bh + CV_BPLANE);

#pragma unroll
        for (int ks = 0; ks < 2; ks++) {
            unsigned ah[4][4], al[4][4];
#pragma unroll
            for (int mt = 0; mt < 4; mt++) {
                uint4 va = *(const uint4*)(Ab + (size_t)((((ks) * 2 + wm) * 4 + mt) * 32 + lane) * 16);
                ah[mt][0] = va.x; ah[mt][1] = va.y; ah[mt][2] = va.z; ah[mt][3] = va.w;
                uint4 vb = *(const uint4*)(Ab + 8192 + (size_t)((((ks) * 2 + wm) * 4 + mt) * 32 + lane) * 16);
                al[mt][0] = vb.x; al[mt][1] = vb.y; al[mt][2] = vb.z; al[mt][3] = vb.w;
            }
            const int kb = ks * 16 + (lane & 3) * 2;
#pragma unroll
            for (int nt = 0; nt < 8; nt++) {
                int row = wn * 64 + nt * 8 + (lane >> 2) + t;
                unsigned bh0 = *(const unsigned*)&Bh[row * APAD + kb];
                unsigned bh1 = *(const unsigned*)&Bh[row * APAD + kb + 8];
                unsigned bl0 = *(const unsigned*)&Bl[row * APAD + kb];
                unsigned bl1 = *(const unsigned*)&Bl[row * APAD + kb + 8];
#pragma unroll
                for (int mt = 0; mt < 4; mt++) {
                    mma_bf16(acc[mt][nt], ah[mt], bh0, bh1);
                    mma_bf16(acc[mt][nt], ah[mt], bl0, bl1);
                    mma_bf16(acc[mt][nt], al[mt], bh0, bh1);
                }
            }
        }
        __syncthreads();
    }

    // ---- epilogue: four 64-col passes through Cs[128][65] ----
    float* Cs = (float*)dynsm;
    const int ch0 = mb * 64;
#pragma unroll 1
    for (int p = 0; p < 4; p++) {
        if (wn == p) {
#pragma unroll
            for (int mt = 0; mt < 4; mt++)
#pragma unroll
                for (int nt = 0; nt < 8; nt++) {
                    int r = wm * 64 + mt * 16 + (lane >> 2);
                    int cl = nt * 8 + (lane & 3) * 2;
                    Cs[r * 65 + cl]           = acc[mt][nt][0];
                    Cs[r * 65 + cl + 1]       = acc[mt][nt][1];
                    Cs[(r + 8) * 65 + cl]     = acc[mt][nt][2];
                    Cs[(r + 8) * 65 + cl + 1] = acc[mt][nt][3];
                }
        }
        __syncthreads();
        const int lbase = l0 + p * 64;
        // GLU + fp32 h write (l-fast), stash hv into Cs a-half rows
#pragma unroll
        for (int i = 0; i < 16; i++) {
            int e = i * 256 + tid;
            int chl = e >> 6, ll = e & 63;
            float av = Cs[(chl * 2) * 65 + ll] + __ldg(&bias[ch0 + chl]);
            float bv = Cs[(chl * 2 + 1) * 65 + ll] + __ldg(&bias[512 + ch0 + chl]);
            float hv = av / (1.f + expf(-bv));
            g_h[((size_t)b * 512 + ch0 + chl) * L_ + lbase + ll] = hv;
            Cs[(chl * 2) * 65 + ll] = hv;
        }
        __syncthreads();
        // transposed bf16 split write (c-fast) -> hT (b,l,c)
#pragma unroll
        for (int i = 0; i < 16; i++) {
            int e = i * 256 + tid;
            int chl = e & 63, ll = e >> 6;
            float hv = Cs[(chl * 2) * 65 + ll];
            bf16 hi, lo; split2(hv, hi, lo);
            size_t off = ((size_t)b * L_ + lbase + ll) * 512 + ch0 + chl;
            g_hTh[off] = hi; g_hTl[off] = lo;
        }
        __syncthreads();
    }
}

// ---------------------------------------------------------------------------
// fc GEMM (MODE 1: fc1, MODE 2: fc2). Unchanged from R11.
//   smem: A stages 2x20480 @0 ; B stages 2x20480 @40960 ; mbar[2] @81920
// ---------------------------------------------------------------------------
#define FC_A_STAGE 20480
#define FC_B_OFF   40960
#define FC_B_STAGE 20480
#define FC_MBAR    81920
#define FC_SMEM    82048

template <int MODE>
__global__ __launch_bounds__(256, 2) void fc_gemm(
    const float* __restrict__ bias, const float* __restrict__ e1,
    float* __restrict__ outp) {
    extern __shared__ __align__(16) unsigned char dynsm[];
    const int b = blockIdx.z, mb = blockIdx.y, l0 = blockIdx.x * 128;
    const int m0 = mb * 128;
    const int tid = threadIdx.x;
    const int lane = tid & 31, warp = tid >> 5;
    const int wm = warp >> 1, wn = warp & 1;

    const bf16* Wp  = (MODE == 1) ? g_w1p : g_w2p;
    const bf16* Bgh = (MODE == 1) ? g_hTh : g_cxh;   // (b, l, k)
    const bf16* Bgl = (MODE == 1) ? g_hTl : g_cxl;

    unsigned smem_base = (unsigned)__cvta_generic_to_shared(dynsm);
    unsigned mbar0 = smem_base + FC_MBAR, mbar1 = mbar0 + 8;
    if (tid == 0) { MBAR_INIT(mbar0, 1); MBAR_INIT(mbar1, 1); }
    __syncthreads();

    float acc[2][8][4];
#pragma unroll
    for (int mt = 0; mt < 2; mt++)
#pragma unroll
        for (int nt = 0; nt < 8; nt++)
#pragma unroll
            for (int j = 0; j < 4; j++) acc[mt][nt][j] = 0.f;

    auto issueA = [&](int s, int kc) {
        if (tid == 0) {
            unsigned mbx = s ? mbar1 : mbar0;
            MBAR_EXPECT(mbx, FC_A_STAGE);
            const char* src = (const char*)Wp + ((size_t)(mb * 16 + kc)) * FC_A_STAGE;
            bulk_g2s(smem_base + s * FC_A_STAGE, src, FC_A_STAGE, mbx);
        }
    };
    auto issueB = [&](int s, int kc) {
        unsigned char* dst0 = dynsm + FC_B_OFF + s * FC_B_STAGE;
#pragma unroll
        for (int ii = 0; ii < 4; ii++) {
            int u = ii * 256 + tid;
            int plane = u >> 9, v = u & 511;
            int r = v >> 2, j = v & 3;
            const bf16* src = (plane ? Bgl : Bgh) +
                ((size_t)b * L_ + l0 + r) * 512 + kc * 32 + j * 8;
            cp16(dst0 + plane * 10240 + r * 80 + j * 16, src);
        }
    };

    issueA(0, 0);
    issueB(0, 0);
    CP_COMMIT();
    int ph0 = 0, ph1 = 0;

    for (int i = 0; i < 16; i++) {
        const int s = i & 1;
        if (i < 15) {
            issueA(s ^ 1, i + 1);
            issueB(s ^ 1, i + 1);
            CP_COMMIT();
        }
        if (s == 0) { mbar_wait(mbar0, ph0); ph0 ^= 1; }
        else        { mbar_wait(mbar1, ph1); ph1 ^= 1; }
        if (i < 15) CP_WAIT1(); else CP_WAIT0();
        __syncthreads();

        const bf16* Ah = (const bf16*)(dynsm + s * FC_A_STAGE);
        const bf16* Al = Ah + 5120;
        const bf16* Bh = (const bf16*)(dynsm + FC_B_OFF + s * FC_B_STAGE);
        const bf16* Bl = Bh + 5120;

#pragma unroll
        for (int ks = 0; ks < 2; ks++) {
            const int kb = ks * 16 + (lane & 3) * 2;
            unsigned ah[2][4], al[2][4];
#pragma unroll
            for (int mt = 0; mt < 2; mt++) {
                int rbw = wm * 32 + mt * 16 + (lane >> 2);
                ah[mt][0] = *(const unsigned*)&Ah[rbw * APAD + kb];
                ah[mt][1] = *(const unsigned*)&Ah[(rbw + 8) * APAD + kb];
                ah[mt][2] = *(const unsigned*)&Ah[rbw * APAD + kb + 8];
                ah[mt][3] = *(const unsigned*)&Ah[(rbw + 8) * APAD + kb + 8];
                al[mt][0] = *(const unsigned*)&Al[rbw * APAD + kb];
                al[mt][1] = *(const unsigned*)&Al[(rbw + 8) * APAD + kb];
                al[mt][2] = *(const unsigned*)&Al[rbw * APAD + kb + 8];
                al[mt][3] = *(const unsigned*)&Al[(rbw + 8) * APAD + kb + 8];
            }
#pragma unroll
            for (int nt = 0; nt < 8; nt++) {
                int col = wn * 64 + nt * 8 + (lane >> 2);
                unsigned bh0 = *(const unsigned*)&Bh[col * APAD + kb];
                unsigned bh1 = *(const unsigned*)&Bh[col * APAD + kb + 8];
                unsigned bl0 = *(const unsigned*)&Bl[col * APAD + kb];
                unsigned bl1 = *(const unsigned*)&Bl[col * APAD + kb + 8];
#pragma unroll
                for (int mt = 0; mt < 2; mt++) {
                    mma_bf16(acc[mt][nt], ah[mt], bh0, bh1);
                    mma_bf16(acc[mt][nt], ah[mt], bl0, bl1);
                    mma_bf16(acc[mt][nt], al[mt], bh0, bh1);
                }
            }
        }
        __syncthreads();
    }

    // ---- epilogue ----
    float* Cs = (float*)dynsm;
#pragma unroll 1
    for (int p = 0; p < 2; p++) {
        if (wn == p) {
#pragma unroll
            for (int mt = 0; mt < 2; mt++)
#pragma unroll
                for (int nt = 0; nt < 8; nt++) {
                    int r = wm * 32 + mt * 16 + (lane >> 2);
                    int cl = nt * 8 + (lane & 3) * 2;
                    Cs[r * 65 + cl]           = acc[mt][nt][0];
                    Cs[r * 65 + cl + 1]       = acc[mt][nt][1];
                    Cs[(r + 8) * 65 + cl]     = acc[mt][nt][2];
                    Cs[(r + 8) * 65 + cl + 1] = acc[mt][nt][3];
                }
        }
        __syncthreads();
        const int lbase = l0 + p * 64;
        if (MODE == 1) {
#pragma unroll
            for (int i = 0; i < 32; i++) {
                int e = i * 256 + tid;
                int a = e & 127, ll = e >> 7;
                Cs[a * 65 + ll] += __ldg(&bias[m0 + a]) +
                    e1[((size_t)b * L_ + lbase + ll) * 512 + m0 + a];
            }
            __syncthreads();
#pragma unroll
            for (int i = 0; i < 32; i++) {
                int e = i * 256 + tid;
                int a = e & 127, ll = e >> 7;
                float v = Cs[a * 65 + ll];
                bf16 hi, lo; split2(v, hi, lo);
                size_t off = ((size_t)b * L_ + lbase + ll) * 512 + m0 + a;
                g_qh[off] = hi; g_ql[off] = lo;
            }
        } else {
#pragma unroll
            for (int i = 0; i < 32; i++) {
                int e = i * 256 + tid;
                int cl_ = e >> 6, ll = e & 63;
                size_t off = ((size_t)b * 512 + m0 + cl_) * L_ + lbase + ll;
                outp[off] = Cs[cl_ * 65 + ll] + __ldg(&bias[m0 + cl_])
                          + g_h[off] + e1[off];
            }
        }
        __syncthreads();
    }
}

// ---------------------------------------------------------------------------
// Tensor-core attention (unchanged). ctx emitted (b, l, a).
// ---------------------------------------------------------------------------
#define SSP 228
#define ATTN_SMEM_BYTES 231424

__global__ __launch_bounds__(256, 1) void attn_tc_kernel(float* __restrict__ attn_out) {
    extern __shared__ __align__(16) unsigned char dynsm[];
    float* ss  = (float*)dynsm;                    // [128][SSP]
    bf16* As_h = (bf16*)(dynsm + 116736);
    bf16* As_l = As_h + 128 * APAD;
    bf16* Bs_h = As_l + 128 * APAD;
    bf16* Bs_l = Bs_h + PP * APAD;
    float* Cs  = (float*)(dynsm + 116736);
    bf16* Bc_h = (bf16*)(dynsm + 173056);
    bf16* Bc_l = Bc_h + 64 * SSP;

    const int b  = blockIdx.y;
    const int l0 = blockIdx.x * 128;
    const int tid = threadIdx.x;
    const int lane = tid & 31, warp = tid >> 5;
    const int wm = warp >> 1, wn = warp & 1;

    // ================= Phase S: score GEMM =================
    float acc[2][14][4];
#pragma unroll
    for (int mt = 0; mt < 2; mt++)
#pragma unroll
        for (int nt = 0; nt < 14; nt++)
#pragma unroll
            for (int j = 0; j < 4; j++) acc[mt][nt][j] = 0.f;

    for (int k0 = 0; k0 < 512; k0 += BK) {
#pragma unroll
        for (int i = 0; i < 8; i++) {
            int u = i * 256 + tid;
            int row = u >> 4, kp = (u & 15) << 1;
            size_t ga = ((size_t)b * L_ + l0 + row) * 512 + k0 + kp;
            *(unsigned*)&As_h[row * APAD + kp] = *(const unsigned*)&g_qh[ga];
            *(unsigned*)&As_l[row * APAD + kp] = *(const unsigned*)&g_ql[ga];
        }
#pragma unroll
        for (int i = 0; i < 14; i++) {
            int u = i * 256 + tid;
            int row = u >> 4, kp = (u & 15) << 1;
            size_t gb = ((size_t)b * PP + row) * 512 + k0 + kp;
            *(unsigned*)&Bs_h[row * APAD + kp] = *(const unsigned*)&g_fTh[gb];
            *(unsigned*)&Bs_l[row * APAD + kp] = *(const unsigned*)&g_fTl[gb];
        }
        __syncthreads();

#pragma unroll
        for (int ks = 0; ks < BK; ks += 16) {
            const int kb = ks + (lane & 3) * 2;
            unsigned ah[2][4], al[2][4];
#pragma unroll
            for (int mt = 0; mt < 2; mt++) {
                int rb = wm * 32 + mt * 16 + (lane >> 2);
                ah[mt][0] = *(unsigned*)&As_h[rb * APAD + kb];
                ah[mt][1] = *(unsigned*)&As_h[(rb + 8) * APAD + kb];
                ah[mt][2] = *(unsigned*)&As_h[rb * APAD + kb + 8];
                ah[mt][3] = *(unsigned*)&As_h[(rb + 8) * APAD + kb + 8];
                al[mt][0] = *(unsigned*)&As_l[rb * APAD + kb];
                al[mt][1] = *(unsigned*)&As_l[(rb + 8) * APAD + kb];
                al[mt][2] = *(unsigned*)&As_l[rb * APAD + kb + 8];
                al[mt][3] = *(unsigned*)&As_l[(rb + 8) * APAD + kb + 8];
            }
#pragma unroll
            for (int nt = 0; nt < 14; nt++) {
                int col = wn * 112 + nt * 8 + (lane >> 2);
                unsigned bh0 = *(unsigned*)&Bs_h[col * APAD + kb];
                unsigned bh1 = *(unsigned*)&Bs_h[col * APAD + kb + 8];
                unsigned bl0 = *(unsigned*)&Bs_l[col * APAD + kb];
                unsigned bl1 = *(unsigned*)&Bs_l[col * APAD + kb + 8];
#pragma unroll
                for (int mt = 0; mt < 2; mt++) {
                    mma_bf16(acc[mt][nt], ah[mt], bh0, bh1);
                    mma_bf16(acc[mt][nt], ah[mt], bl0, bl1);
                    mma_bf16(acc[mt][nt], al[mt], bh0, bh1);
                }
            }
        }
        __syncthreads();
    }

#pragma unroll
    for (int mt = 0; mt < 2; mt++)
#pragma unroll
        for (int nt = 0; nt < 14; nt++) {
            int r = wm * 32 + mt * 16 + (lane >> 2);
            int cl = wn * 112 + nt * 8 + (lane & 3) * 2;
            ss[r * SSP + cl]           = acc[mt][nt][0];
            ss[r * SSP + cl + 1]       = acc[mt][nt][1];
            ss[(r + 8) * SSP + cl]     = acc[mt][nt][2];
            ss[(r + 8) * SSP + cl + 1] = acc[mt][nt][3];
        }
    __syncthreads();

    // ================= Softmax =================
    for (int r = 0; r < 16; r++) {
        int row = warp * 16 + r;
        float v[7];
        float mx = -1e30f;
#pragma unroll
        for (int k = 0; k < 7; k++) {
            int p = lane + 32 * k;
            v[k] = (p < HW) ? ss[row * SSP + p] : -1e30f;
            mx = fmaxf(mx, v[k]);
        }
#pragma unroll
        for (int off = 16; off > 0; off >>= 1)
            mx = fmaxf(mx, __shfl_xor_sync(0xffffffffu, mx, off));
        float s = 0.f;
#pragma unroll
        for (int k = 0; k < 7; k++) {
            int p = lane + 32 * k;
            if (p < HW) { v[k] = expf(v[k] - mx); s += v[k]; }
        }
#pragma unroll
        for (int off = 16; off > 0; off >>= 1)
            s += __shfl_xor_sync(0xffffffffu, s, off);
        float inv = 1.f / s;
        float* ao = attn_out + ((size_t)b * L_ + l0 + row) * HW;
#pragma unroll
        for (int k = 0; k < 7; k++) {
            int p = lane + 32 * k;
            if (p < HW) {
                float a = v[k] * inv;
                ss[row * SSP + p] = a;
                ao[p] = a;
            } else {
                ss[row * SSP + p] = 0.f;
            }
        }
    }
    __syncthreads();

    // ================= Phase C: ctx GEMM =================
#pragma unroll 1
    for (int a0 = 0; a0 < 512; a0 += 64) {
#pragma unroll
        for (int i = 0; i < 28; i++) {
            int u = i * 256 + tid;
            int row = u / 112, pc = (u - row * 112) * 2;
            size_t gb = ((size_t)b * 512 + a0 + row) * PP + pc;
            *(unsigned*)&Bc_h[row * SSP + pc] = *(const unsigned*)&g_fh[gb];
            *(unsigned*)&Bc_l[row * SSP + pc] = *(const unsigned*)&g_fl[gb];
        }
        __syncthreads();

        float ac2[2][4][4];
#pragma unroll
        for (int mt = 0; mt < 2; mt++)
#pragma unroll
            for (int nt = 0; nt < 4; nt++)
#pragma unroll
                for (int j = 0; j < 4; j++) ac2[mt][nt][j] = 0.f;

#pragma unroll 2
        for (int p0 = 0; p0 < PP; p0 += 16) {
            const int kb = p0 + (lane & 3) * 2;
            unsigned ah[2][4], al[2][4];
#pragma unroll
            for (int mt = 0; mt < 2; mt++) {
                int rb = wm * 32 + mt * 16 + (lane >> 2);
#pragma unroll
                for (int f = 0; f < 4; f++) {
                    int rr = rb + ((f & 1) ? 8 : 0);
                    int cc = kb + ((f & 2) ? 8 : 0);
                    float2 v = *(const float2*)&ss[rr * SSP + cc];
                    bf16 h0 = __float2bfloat16(v.x);
                    bf16 h1 = __float2bfloat16(v.y);
                    __nv_bfloat162 hp; hp.x = h0; hp.y = h1;
                    __nv_bfloat162 lp;
                    lp.x = __float2bfloat16(v.x - __bfloat162float(h0));
                    lp.y = __float2bfloat16(v.y - __bfloat162float(h1));
                    ah[mt][f] = *(unsigned*)&hp;
                    al[mt][f] = *(unsigned*)&lp;
                }
            }
#pragma unroll
            for (int nt = 0; nt < 4; nt++) {
                int col = wn * 32 + nt * 8 + (lane >> 2);
                unsigned bh0 = *(unsigned*)&Bc_h[col * SSP + kb];
                unsigned bh1 = *(unsigned*)&Bc_h[col * SSP + kb + 8];
                unsigned bl0 = *(unsigned*)&Bc_l[col * SSP + kb];
                unsigned bl1 = *(unsigned*)&Bc_l[col * SSP + kb + 8];
#pragma unroll
                for (int mt = 0; mt < 2; mt++) {
                    mma_bf16(ac2[mt][nt], ah[mt], bh0, bh1);
                    mma_bf16(ac2[mt][nt], ah[mt], bl0, bl1);
                    mma_bf16(ac2[mt][nt], al[mt], bh0, bh1);
                }
            }
        }

#pragma unroll
        for (int mt = 0; mt < 2; mt++)
#pragma unroll
            for (int nt = 0; nt < 4; nt++) {
                int r = wm * 32 + mt * 16 + (lane >> 2);
                int cl = wn * 32 + nt * 8 + (lane & 3) * 2;
                Cs[r * 65 + cl]           = ac2[mt][nt][0];
                Cs[r * 65 + cl + 1]       = ac2[mt][nt][1];
                Cs[(r + 8) * 65 + cl]     = ac2[mt][nt][2];
                Cs[(r + 8) * 65 + cl + 1] = ac2[mt][nt][3];
            }
        __syncthreads();

        // write ctx split bf16, layout (b, l, a), coalesced over a
#pragma unroll
        for (int i = 0; i < 32; i++) {
            int e = i * 256 + tid;
            int a = e & 63, l = e >> 6;
            float v = Cs[l * 65 + a];
            bf16 hi, lo; split2(v, hi, lo);
            size_t off = ((size_t)b * L_ + l0 + l) * 512 + a0 + a;
            g_cxh[off] = hi; g_cxl[off] = lo;
        }
        __syncthreads();
    }
}

// ---------------------------------------------------------------------------
extern "C" void kernel_launch(void* const* d_in, const int* in_sizes, int n_in,
                              void* d_out, int out_size) {
    (void)in_sizes; (void)n_in; (void)out_size;
    const float* x      = (const float*)d_in[0];
    const float* we     = (const float*)d_in[1];
    const float* img    = (const float*)d_in[2];
    /* d_in[3] prev_attn unused */
    const float* conv_v = (const float*)d_in[4];
    const float* conv_g = (const float*)d_in[5];
    const float* conv_b = (const float*)d_in[6];
    const float* fc1_w  = (const float*)d_in[7];
    const float* fc1_b  = (const float*)d_in[8];
    const float* fc2_w  = (const float*)d_in[9];
    const float* fc2_b  = (const float*)d_in[10];
    float* out = (float*)d_out;

    // passthrough copies
    cudaMemcpyAsync(out + OUT_WE, we, (size_t)B_ * L_ * DW * sizeof(float),
                    cudaMemcpyDeviceToDevice, 0);
    cudaMemcpyAsync(out + OUT_IMG, img, (size_t)B_ * DW * HW * sizeof(float),
                    cudaMemcpyDeviceToDevice, 0);

    void *p_w1p, *p_w2p;
    cudaGetSymbolAddress(&p_w1p, g_w1p);
    cudaGetSymbolAddress(&p_w2p, g_w2p);

    // prep
    wnorm_kernel<<<COUT, 256>>>(conv_v, conv_g);
    pack_conv_kernel<<<dim3(80, 8), 256>>>();
    pack_fc_kernel<<<dim3(16, 4, 4), 256>>>(fc1_w, (bf16*)p_w1p);
    pack_fc_kernel<<<dim3(16, 4, 4), 256>>>(fc2_w, (bf16*)p_w2p);
    xT_kernel<<<dim3(L_ / 32, CIN / 32, B_), dim3(32, 8)>>>(x);
    featT_kernel<<<dim3(PP / 32, 512 / 32, B_), dim3(32, 8)>>>(img);
    featpad_kernel<<<(B_ * 512 * PP + 255) / 256, 256>>>(img);

    // opt-in dynamic smem
    cudaFuncSetAttribute(conv_gemm, cudaFuncAttributeMaxDynamicSharedMemorySize, CV_SMEM);
    cudaFuncSetAttribute(fc_gemm<1>, cudaFuncAttributeMaxDynamicSharedMemorySize, FC_SMEM);
    cudaFuncSetAttribute(fc_gemm<2>, cudaFuncAttributeMaxDynamicSharedMemorySize, FC_SMEM);
    cudaFuncSetAttribute(attn_tc_kernel, cudaFuncAttributeMaxDynamicSharedMemorySize,
                         ATTN_SMEM_BYTES);

    // conv + GLU  (M=1024 interleaved, N=1024, K=2560), tile 128x256
    conv_gemm<<<dim3(L_ / 256, 8, B_), 256, CV_SMEM>>>(conv_b);
    // fc1 (M=512, N=1024, K=512) -> q bf16 (b,l,a)
    fc_gemm<1><<<dim3(L_ / 128, 4, B_), 256, FC_SMEM>>>(fc1_b, we, nullptr);
    // tensor-core attention -> attn output + ctx (b,l,a)
    attn_tc_kernel<<<dim3(L_ / 128, B_), 256, ATTN_SMEM_BYTES>>>(out + OUT_ATTN);
    // fc2 + residuals (M=512, N=1024, K=512)
    fc_gemm<2><<<dim3(L_ / 128, 4, B_), 256, FC_SMEM>>>(fc2_b, x, out);
}

// round 13
// speedup vs baseline: 1.0795x; 1.0795x over previous
#include <cuda_runtime.h>
#include <cuda_bf16.h>
#include <math.h>

// Problem constants
#define B_  16
#define CIN 512
#define L_  1024
#define COUT 1024
#define K_  5
#define DW  512
#define HW  196
#define KCONV (CIN * K_)   // 2560
#define PP  224            // padded p dimension

// Output layout (concatenated tuple): out, word_embed, img_conv, attn
#define OUT_WE   8388608u
#define OUT_IMG  16777216u
#define OUT_ATTN 18382848u

typedef __nv_bfloat16 bf16;

// ---------------------------------------------------------------------------
// Scratch (device globals; allocation-free rule)
// ---------------------------------------------------------------------------
__device__ float g_w[COUT * KCONV];            // normalized conv weights (co, c, t)
__device__ float g_h[B_ * DW * L_];            // GLU output fp32 (b, ch, l)
__device__ bf16 g_xTh[B_ * L_ * CIN], g_xTl[B_ * L_ * CIN];   // x^T split (b, l, c)
__device__ bf16 g_cwp[8 * 80 * 8192];          // conv W fragment-packed tiles (16KB)
__device__ bf16 g_w1p[4 * 16 * 8192];          // fc1 W fragment-packed tiles (16KB)
__device__ bf16 g_w2p[4 * 16 * 8192];          // fc2 W fragment-packed tiles (16KB)
__device__ bf16 g_hTh[B_ * L_ * DW], g_hTl[B_ * L_ * DW];     // h split (b, l, c)
__device__ bf16 g_qh[B_ * L_ * DW],  g_ql[B_ * L_ * DW];      // q split (b, l, a)
__device__ bf16 g_cxh[B_ * L_ * DW], g_cxl[B_ * L_ * DW];     // ctx split (b, l, a)
__device__ bf16 g_fTh[B_ * PP * DW], g_fTl[B_ * PP * DW];     // feat^T split (b, p, a)
__device__ bf16 g_fh[B_ * DW * PP],  g_fl[B_ * DW * PP];      // feat split (b, a, p)

__device__ __forceinline__ void split2(float v, bf16& h, bf16& l) {
    h = __float2bfloat16(v);
    l = __float2bfloat16(v - __bfloat162float(h));
}

// ---- async copy primitives ----
__device__ __forceinline__ void cp16(void* dst, const void* src) {
    unsigned d = (unsigned)__cvta_generic_to_shared(dst);
    asm volatile("cp.async.cg.shared.global [%0], [%1], 16;\n" :: "r"(d), "l"(src));
}
#define CP_COMMIT() asm volatile("cp.async.commit_group;\n")
#define CP_WAIT0()  asm volatile("cp.async.wait_group 0;\n")
#define CP_WAIT1()  asm volatile("cp.async.wait_group 1;\n")

#define MBAR_INIT(addr, cnt) \
    asm volatile("mbarrier.init.shared.b64 [%0], %1;" :: "r"(addr), "r"(cnt) : "memory")
#define MBAR_EXPECT(addr, tx) \
    asm volatile("mbarrier.arrive.expect_tx.shared.b64 _, [%0], %1;" :: "r"(addr), "r"(tx) : "memory")

__device__ __forceinline__ void mbar_wait(unsigned mbar, unsigned parity) {
    asm volatile(
        "{\n\t.reg .pred P;\n\t"
        "W_%=:\n\t"
        "mbarrier.try_wait.parity.acquire.cta.shared::cta.b64 P, [%0], %1;\n\t"
        "@!P bra W_%=;\n\t}"
        :: "r"(mbar), "r"(parity) : "memory");
}

__device__ __forceinline__ void bulk_g2s(unsigned dst_smem, const void* src,
                                         unsigned bytes, unsigned mbar) {
    asm volatile(
        "cp.async.bulk.shared::cluster.global.mbarrier::complete_tx::bytes "
        "[%0], [%1], %2, [%3];"
        :: "r"(dst_smem), "l"(src), "r"(bytes), "r"(mbar) : "memory");
}

// ---------------------------------------------------------------------------
// Prep kernels
// ---------------------------------------------------------------------------
__global__ void wnorm_kernel(const float* __restrict__ v,
                             const float* __restrict__ g) {
    int co = blockIdx.x;
    const float* vr = v + (size_t)co * KCONV;
    float s = 0.f;
    for (int i = threadIdx.x; i < KCONV; i += 256) { float t = vr[i]; s += t * t; }
    __shared__ float red[256];
    red[threadIdx.x] = s;
    __syncthreads();
    for (int st = 128; st > 0; st >>= 1) {
        if (threadIdx.x < st) red[threadIdx.x] += red[threadIdx.x + st];
        __syncthreads();
    }
    float scale = g[co] / sqrtf(red[0]);
    float* wr = g_w + (size_t)co * KCONV;
    for (int i = threadIdx.x; i < KCONV; i += 256) wr[i] = scale * vr[i];
}

// Fragment-order pack layout (tile = 1024 16B-chunks = 16KB):
//   chunk u: lane=u&31, mt=(u>>5)&1, wm=(u>>6)&3, ks=(u>>8)&1, plane=(u>>9)&1
//   4 words w: row = wm*32+mt*16+(lane>>2)+((w&1)?8:0)
//              k   = ks*16+(lane&3)*2+(w>>1)*8   (2 bf16: k, k+1)

// conv: tile (mb, kc), kc = t*16 + ci; element k maps to c = ci*32 + k
__global__ void pack_conv_kernel() {
    const int kc = blockIdx.x, mb = blockIdx.y;
    const int t = kc / 16, ci = kc % 16;
    bf16* dst = g_cwp + (size_t)(mb * 80 + kc) * 8192;
    for (int u = threadIdx.x; u < 1024; u += 256) {
        int lane2 = u & 31, mt = (u >> 5) & 1, wm2 = (u >> 6) & 3;
        int ks = (u >> 8) & 1, plane = (u >> 9) & 1;
        int row0 = wm2 * 32 + mt * 16 + (lane2 >> 2);
        int kb = ks * 16 + (lane2 & 3) * 2;
        unsigned words[4];
#pragma unroll
        for (int w = 0; w < 4; w++) {
            int row = row0 + ((w & 1) ? 8 : 0);
            int k = kb + (w >> 1) * 8;
            int m = mb * 128 + row;
            int co = (m & 1) ? (512 + (m >> 1)) : (m >> 1);
            unsigned short p0, p1;
#pragma unroll
            for (int e = 0; e < 2; e++) {
                int c = ci * 32 + k + e;
                float v = g_w[(size_t)co * KCONV + c * K_ + t];
                bf16 hi, lo; split2(v, hi, lo);
                bf16 sel = plane ? lo : hi;
                unsigned short us = *(unsigned short*)&sel;
                if (e == 0) p0 = us; else p1 = us;
            }
            words[w] = (unsigned)p0 | ((unsigned)p1 << 16);
        }
        *(uint4*)(dst + u * 8) = make_uint4(words[0], words[1], words[2], words[3]);
    }
}

// fc: W [m=512][k=512] row-major -> fragment-order tiles [mb 4][kc 16]
__global__ void pack_fc_kernel(const float* __restrict__ W, bf16* __restrict__ dstall) {
    const int kc = blockIdx.x, mb = blockIdx.y, zz = blockIdx.z;
    bf16* dst = dstall + (size_t)(mb * 16 + kc) * 8192;
    int u = zz * 256 + threadIdx.x;   // 4 z-slices x 256 = 1024 chunks
    {
        int lane2 = u & 31, mt = (u >> 5) & 1, wm2 = (u >> 6) & 3;
        int ks = (u >> 8) & 1, plane = (u >> 9) & 1;
        int row0 = wm2 * 32 + mt * 16 + (lane2 >> 2);
        int kb = ks * 16 + (lane2 & 3) * 2;
        unsigned words[4];
#pragma unroll
        for (int w = 0; w < 4; w++) {
            int row = row0 + ((w & 1) ? 8 : 0);
            int k = kb + (w >> 1) * 8;
            unsigned short p0, p1;
#pragma unroll
            for (int e = 0; e < 2; e++) {
                float v = W[(size_t)(mb * 128 + row) * 512 + kc * 32 + k + e];
                bf16 hi, lo; split2(v, hi, lo);
                bf16 sel = plane ? lo : hi;
                unsigned short us = *(unsigned short*)&sel;
                if (e == 0) p0 = us; else p1 = us;
            }
            words[w] = (unsigned)p0 | ((unsigned)p1 << 16);
        }
        *(uint4*)(dst + u * 8) = make_uint4(words[0], words[1], words[2], words[3]);
    }
}

// x (b,c,l) -> xT split (b,l,c)
__global__ void xT_kernel(const float* __restrict__ x) {
    __shared__ float t[32][33];
    const int b = blockIdx.z, l0 = blockIdx.x * 32, c0 = blockIdx.y * 32;
    const int tx = threadIdx.x, ty0 = threadIdx.y;
#pragma unroll
    for (int j = 0; j < 4; j++) {
        int ty = ty0 + j * 8;
        t[ty][tx] = x[((size_t)b * CIN + c0 + ty) * L_ + l0 + tx];
    }
    __syncthreads();
#pragma unroll
    for (int j = 0; j < 4; j++) {
        int ty = ty0 + j * 8;
        float v = t[tx][ty];
        bf16 hi, lo; split2(v, hi, lo);
        size_t off = ((size_t)b * L_ + l0 + ty) * 512 + c0 + tx;
        g_xTh[off] = hi; g_xTl[off] = lo;
    }
}

// feat^T split (b, p, a); p>=196 rows zero.
__global__ void featT_kernel(const float* __restrict__ img) {
    __shared__ float t[32][33];
    const int b = blockIdx.z, p0 = blockIdx.x * 32, a0 = blockIdx.y * 32;
    const int tx = threadIdx.x, ty0 = threadIdx.y;
#pragma unroll
    for (int j = 0; j < 4; j++) {
        int ty = ty0 + j * 8;
        int a = a0 + ty, p = p0 + tx;
        t[ty][tx] = (p < HW) ? img[((size_t)b * 512 + a) * HW + p] : 0.f;
    }
    __syncthreads();
#pragma unroll
    for (int j = 0; j < 4; j++) {
        int ty = ty0 + j * 8;
        float v = t[tx][ty];
        bf16 hi, lo; split2(v, hi, lo);
        size_t off = ((size_t)b * PP + p0 + ty) * 512 + a0 + tx;
        g_fTh[off] = hi; g_fTl[off] = lo;
    }
}

__global__ void featpad_kernel(const float* __restrict__ img) {
    int idx = blockIdx.x * 256 + threadIdx.x;
    if (idx >= B_ * 512 * PP) return;
    int p = idx % PP, ba = idx / PP;
    float v = (p < HW) ? img[(size_t)ba * HW + p] : 0.f;
    bf16 hi, lo; split2(v, hi, lo);
    g_fh[idx] = hi; g_fl[idx] = lo;
}

// ---------------------------------------------------------------------------
// MMA helper
// ---------------------------------------------------------------------------
__device__ __forceinline__ void mma_bf16(float* c, const unsigned* a,
                                         unsigned b0, unsigned b1) {
    asm volatile(
        "mma.sync.aligned.m16n8k16.row.col.f32.bf16.bf16.f32 "
        "{%0,%1,%2,%3}, {%4,%5,%6,%7}, {%8,%9}, {%0,%1,%2,%3};\n"
        : "+f"(c[0]), "+f"(c[1]), "+f"(c[2]), "+f"(c[3])
        : "r"(a[0]), "r"(a[1]), "r"(a[2]), "r"(a[3]), "r"(b0), "r"(b1));
}

#define APAD 40
#define BK 32

// ---------------------------------------------------------------------------
// Conv GEMM (R13 = R11 shape + fragment-order A).
// Tile 128m x 128n, 2 CTA/SM, 8 warps (wm 4 x wn 2), warp tile 2mt x 8nt.
//   smem: A 2x16384 @0 ; B 2x21760 @32768 ; mbar @76288
// ---------------------------------------------------------------------------
#define CV_A_STAGE 16384
#define CV_B_OFF   32768
#define CV_B_STAGE 21760
#define CV_MBAR    76288
#define CV_SMEM    76416

__global__ __launch_bounds__(256, 2) void conv_gemm(const float* __restrict__ bias) {
    extern __shared__ __align__(16) unsigned char dynsm[];
    const int b = blockIdx.z, mb = blockIdx.y, l0 = blockIdx.x * 128;
    const int tid = threadIdx.x;
    const int lane = tid & 31, warp = tid >> 5;
    const int wm = warp >> 1, wn = warp & 1;

    unsigned smem_base = (unsigned)__cvta_generic_to_shared(dynsm);
    unsigned mbar0 = smem_base + CV_MBAR, mbar1 = mbar0 + 8;
    if (tid == 0) { MBAR_INIT(mbar0, 1); MBAR_INIT(mbar1, 1); }
    __syncthreads();

    float acc[2][8][4];
#pragma unroll
    for (int mt = 0; mt < 2; mt++)
#pragma unroll
        for (int nt = 0; nt < 8; nt++)
#pragma unroll
            for (int j = 0; j < 4; j++) acc[mt][nt][j] = 0.f;

    auto issueA = [&](int s, int kc) {
        if (tid == 0) {
            unsigned mbx = s ? mbar1 : mbar0;
            MBAR_EXPECT(mbx, CV_A_STAGE);
            const char* src = (const char*)g_cwp + (size_t)(mb * 80 + kc) * CV_A_STAGE;
            bulk_g2s(smem_base + s * CV_A_STAGE, src, CV_A_STAGE, mbx);
        }
    };
    auto issueB = [&](int sb, int ci) {
        int c0 = ci * 32;
        unsigned char* dst0 = dynsm + CV_B_OFF + sb * CV_B_STAGE;
        // 2 planes x 132 rows x 4 chunks = 1056 cp16
#pragma unroll
        for (int ii = 0; ii < 5; ii++) {
            int u = ii * 256 + tid;
            if (u < 1056) {
                int plane = (u >= 528) ? 1 : 0;
                int v = u - plane * 528;
                int r = v >> 2, j = v & 3;
                if (!(l0 == 0 && r < 4)) {
                    const bf16* src = (plane ? g_xTl : g_xTh) +
                        ((size_t)b * L_ + l0 - 4 + r) * 512 + c0 + j * 8;
                    cp16(dst0 + plane * 10880 + r * 80 + j * 16, src);
                }
            }
        }
        if (l0 == 0 && tid < 160) {
            int plane = tid / 80, v = tid % 80, r = v / 20, w = v % 20;
            *(unsigned*)(dst0 + plane * 10880 + r * 80 + w * 4) = 0u;
        }
    };

    // prologue
    issueB(0, 0);
    CP_COMMIT();
    issueA(0, 0);
    int ph0 = 0, ph1 = 0;

    for (int i = 0; i < 80; i++) {
        const int ci = i / 5, t = i - ci * 5, s = i & 1;
        if (i + 1 < 80) {
            int ni = i + 1, nci = ni / 5, nt2 = ni - nci * 5;
            issueA(ni & 1, nt2 * 16 + nci);
            if (nt2 == 0) { issueB(nci & 1, nci); CP_COMMIT(); }
        }
        if (s == 0) { mbar_wait(mbar0, ph0); ph0 ^= 1; }
        else        { mbar_wait(mbar1, ph1); ph1 ^= 1; }
        if (t == 0) CP_WAIT0();
        __syncthreads();

        const unsigned char* Ab = dynsm + s * CV_A_STAGE;
        const bf16* Bh = (const bf16*)(dynsm + CV_B_OFF + (ci & 1) * CV_B_STAGE);
        const bf16* Bl = (const bf16*)((const unsigned char*)Bh + 10880);

#pragma unroll
        for (int ks = 0; ks < 2; ks++) {
            unsigned ah[2][4], al[2][4];
#pragma unroll
            for (int mt = 0; mt < 2; mt++) {
                int chunk = (((ks * 4 + wm) * 2 + mt) * 32 + lane) * 16;
                uint4 va = *(const uint4*)(Ab + chunk);
                ah[mt][0] = va.x; ah[mt][1] = va.y; ah[mt][2] = va.z; ah[mt][3] = va.w;
                uint4 vb = *(const uint4*)(Ab + 8192 + chunk);
                al[mt][0] = vb.x; al[mt][1] = vb.y; al[mt][2] = vb.z; al[mt][3] = vb.w;
            }
            const int kb = ks * 16 + (lane & 3) * 2;
#pragma unroll
            for (int nt = 0; nt < 8; nt++) {
                int row = wn * 64 + nt * 8 + (lane >> 2) + t;
                unsigned bh0 = *(const unsigned*)&Bh[row * APAD + kb];
                unsigned bh1 = *(const unsigned*)&Bh[row * APAD + kb + 8];
                unsigned bl0 = *(const unsigned*)&Bl[row * APAD + kb];
                unsigned bl1 = *(const unsigned*)&Bl[row * APAD + kb + 8];
#pragma unroll
                for (int mt = 0; mt < 2; mt++) {
                    mma_bf16(acc[mt][nt], ah[mt], bh0, bh1);
                    mma_bf16(acc[mt][nt], ah[mt], bl0, bl1);
                    mma_bf16(acc[mt][nt], al[mt], bh0, bh1);
                }
            }
        }
        __syncthreads();
    }

    // ---- epilogue: two 64-col passes through Cs[128][65] ----
    float* Cs = (float*)dynsm;
    const int ch0 = mb * 64;
#pragma unroll 1
    for (int p = 0; p < 2; p++) {
        if (wn == p) {
#pragma unroll
            for (int mt = 0; mt < 2; mt++)
#pragma unroll
                for (int nt = 0; nt < 8; nt++) {
                    int r = wm * 32 + mt * 16 + (lane >> 2);
                    int cl = nt * 8 + (lane & 3) * 2;
                    Cs[r * 65 + cl]           = acc[mt][nt][0];
                    Cs[r * 65 + cl + 1]       = acc[mt][nt][1];
                    Cs[(r + 8) * 65 + cl]     = acc[mt][nt][2];
                    Cs[(r + 8) * 65 + cl + 1] = acc[mt][nt][3];
                }
        }
        __syncthreads();
        const int lbase = l0 + p * 64;
        // GLU + fp32 h write (l-fast), stash hv into Cs a-half rows
#pragma unroll
        for (int i = 0; i < 16; i++) {
            int e = i * 256 + tid;
            int chl = e >> 6, ll = e & 63;
            float av = Cs[(chl * 2) * 65 + ll] + __ldg(&bias[ch0 + chl]);
            float bv = Cs[(chl * 2 + 1) * 65 + ll] + __ldg(&bias[512 + ch0 + chl]);
            float hv = av / (1.f + expf(-bv));
            g_h[((size_t)b * 512 + ch0 + chl) * L_ + lbase + ll] = hv;
            Cs[(chl * 2) * 65 + ll] = hv;
        }
        __syncthreads();
        // transposed bf16 split write (c-fast) -> hT (b,l,c)
#pragma unroll
        for (int i = 0; i < 16; i++) {
            int e = i * 256 + tid;
            int chl = e & 63, ll = e >> 6;
            float hv = Cs[(chl * 2) * 65 + ll];
            bf16 hi, lo; split2(hv, hi, lo);
            size_t off = ((size_t)b * L_ + lbase + ll) * 512 + ch0 + chl;
            g_hTh[off] = hi; g_hTl[off] = lo;
        }
        __syncthreads();
    }
}

// ---------------------------------------------------------------------------
// fc GEMM (MODE 1: fc1, MODE 2: fc2), fragment-order A.
//   smem: A 2x16384 @0 ; B 2x20480 @32768 ; mbar @73728
// ---------------------------------------------------------------------------
#define FC_A_STAGE 16384
#define FC_B_OFF   32768
#define FC_B_STAGE 20480
#define FC_MBAR    73728
#define FC_SMEM    73856

template <int MODE>
__global__ __launch_bounds__(256, 2) void fc_gemm(
    const float* __restrict__ bias, const float* __restrict__ e1,
    float* __restrict__ outp) {
    extern __shared__ __align__(16) unsigned char dynsm[];
    const int b = blockIdx.z, mb = blockIdx.y, l0 = blockIdx.x * 128;
    const int m0 = mb * 128;
    const int tid = threadIdx.x;
    const int lane = tid & 31, warp = tid >> 5;
    const int wm = warp >> 1, wn = warp & 1;

    const bf16* Wp  = (MODE == 1) ? g_w1p : g_w2p;
    const bf16* Bgh = (MODE == 1) ? g_hTh : g_cxh;   // (b, l, k)
    const bf16* Bgl = (MODE == 1) ? g_hTl : g_cxl;

    unsigned smem_base = (unsigned)__cvta_generic_to_shared(dynsm);
    unsigned mbar0 = smem_base + FC_MBAR, mbar1 = mbar0 + 8;
    if (tid == 0) { MBAR_INIT(mbar0, 1); MBAR_INIT(mbar1, 1); }
    __syncthreads();

    float acc[2][8][4];
#pragma unroll
    for (int mt = 0; mt < 2; mt++)
#pragma unroll
        for (int nt = 0; nt < 8; nt++)
#pragma unroll
            for (int j = 0; j < 4; j++) acc[mt][nt][j] = 0.f;

    auto issueA = [&](int s, int kc) {
        if (tid == 0) {
            unsigned mbx = s ? mbar1 : mbar0;
            MBAR_EXPECT(mbx, FC_A_STAGE);
            const char* src = (const char*)Wp + (size_t)(mb * 16 + kc) * FC_A_STAGE;
            bulk_g2s(smem_base + s * FC_A_STAGE, src, FC_A_STAGE, mbx);
        }
    };
    auto issueB = [&](int s, int kc) {
        unsigned char* dst0 = dynsm + FC_B_OFF + s * FC_B_STAGE;
#pragma unroll
        for (int ii = 0; ii < 4; ii++) {
            int u = ii * 256 + tid;
            int plane = u >> 9, v = u & 511;
            int r = v >> 2, j = v & 3;
            const bf16* src = (plane ? Bgl : Bgh) +
                ((size_t)b * L_ + l0 + r) * 512 + kc * 32 + j * 8;
            cp16(dst0 + plane * 10240 + r * 80 + j * 16, src);
        }
    };

    issueA(0, 0);
    issueB(0, 0);
    CP_COMMIT();
    int ph0 = 0, ph1 = 0;

    for (int i = 0; i < 16; i++) {
        const int s = i & 1;
        if (i < 15) {
            issueA(s ^ 1, i + 1);
            issueB(s ^ 1, i + 1);
            CP_COMMIT();
        }
        if (s == 0) { mbar_wait(mbar0, ph0); ph0 ^= 1; }
        else        { mbar_wait(mbar1, ph1); ph1 ^= 1; }
        if (i < 15) CP_WAIT1(); else CP_WAIT0();
        __syncthreads();

        const unsigned char* Ab = dynsm + s * FC_A_STAGE;
        const bf16* Bh = (const bf16*)(dynsm + FC_B_OFF + s * FC_B_STAGE);
        const bf16* Bl = (const bf16*)((const unsigned char*)Bh + 10240);

#pragma unroll
        for (int ks = 0; ks < 2; ks++) {
            unsigned ah[2][4], al[2][4];
#pragma unroll
            for (int mt = 0; mt < 2; mt++) {
                int chunk = (((ks * 4 + wm) * 2 + mt) * 32 + lane) * 16;
                uint4 va = *(const uint4*)(Ab + chunk);
                ah[mt][0] = va.x; ah[mt][1] = va.y; ah[mt][2] = va.z; ah[mt][3] = va.w;
                uint4 vb = *(const uint4*)(Ab + 8192 + chunk);
                al[mt][0] = vb.x; al[mt][1] = vb.y; al[mt][2] = vb.z; al[mt][3] = vb.w;
            }
            const int kb = ks * 16 + (lane & 3) * 2;
#pragma unroll
            for (int nt = 0; nt < 8; nt++) {
                int col = wn * 64 + nt * 8 + (lane >> 2);
                unsigned bh0 = *(const unsigned*)&Bh[col * APAD + kb];
                unsigned bh1 = *(const unsigned*)&Bh[col * APAD + kb + 8];
                unsigned bl0 = *(const unsigned*)&Bl[col * APAD + kb];
                unsigned bl1 = *(const unsigned*)&Bl[col * APAD + kb + 8];
#pragma unroll
                for (int mt = 0; mt < 2; mt++) {
                    mma_bf16(acc[mt][nt], ah[mt], bh0, bh1);
                    mma_bf16(acc[mt][nt], ah[mt], bl0, bl1);
                    mma_bf16(acc[mt][nt], al[mt], bh0, bh1);
                }
            }
        }
        __syncthreads();
    }

    // ---- epilogue ----
    float* Cs = (float*)dynsm;
#pragma unroll 1
    for (int p = 0; p < 2; p++) {
        if (wn == p) {
#pragma unroll
            for (int mt = 0; mt < 2; mt++)
#pragma unroll
                for (int nt = 0; nt < 8; nt++) {
                    int r = wm * 32 + mt * 16 + (lane >> 2);
                    int cl = nt * 8 + (lane & 3) * 2;
                    Cs[r * 65 + cl]           = acc[mt][nt][0];
                    Cs[r * 65 + cl + 1]       = acc[mt][nt][1];
                    Cs[(r + 8) * 65 + cl]     = acc[mt][nt][2];
                    Cs[(r + 8) * 65 + cl + 1] = acc[mt][nt][3];
                }
        }
        __syncthreads();
        const int lbase = l0 + p * 64;
        if (MODE == 1) {
#pragma unroll
            for (int i = 0; i < 32; i++) {
                int e = i * 256 + tid;
                int a = e & 127, ll = e >> 7;
                Cs[a * 65 + ll] += __ldg(&bias[m0 + a]) +
                    e1[((size_t)b * L_ + lbase + ll) * 512 + m0 + a];
            }
            __syncthreads();
#pragma unroll
            for (int i = 0; i < 32; i++) {
                int e = i * 256 + tid;
                int a = e & 127, ll = e >> 7;
                float v = Cs[a * 65 + ll];
                bf16 hi, lo; split2(v, hi, lo);
                size_t off = ((size_t)b * L_ + lbase + ll) * 512 + m0 + a;
                g_qh[off] = hi; g_ql[off] = lo;
            }
        } else {
#pragma unroll
            for (int i = 0; i < 32; i++) {
                int e = i * 256 + tid;
                int cl_ = e >> 6, ll = e & 63;
                size_t off = ((size_t)b * 512 + m0 + cl_) * L_ + lbase + ll;
                outp[off] = Cs[cl_ * 65 + ll] + __ldg(&bias[m0 + cl_])
                          + g_h[off] + e1[off];
            }
        }
        __syncthreads();
    }
}

// ---------------------------------------------------------------------------
// Tensor-core attention (unchanged). ctx emitted (b, l, a).
// ---------------------------------------------------------------------------
#define SSP 228
#define ATTN_SMEM_BYTES 231424

__global__ __launch_bounds__(256, 1) void attn_tc_kernel(float* __restrict__ attn_out) {
    extern __shared__ __align__(16) unsigned char dynsm[];
    float* ss  = (float*)dynsm;                    // [128][SSP]
    bf16* As_h = (bf16*)(dynsm + 116736);
    bf16* As_l = As_h + 128 * APAD;
    bf16* Bs_h = As_l + 128 * APAD;
    bf16* Bs_l = Bs_h + PP * APAD;
    float* Cs  = (float*)(dynsm + 116736);
    bf16* Bc_h = (bf16*)(dynsm + 173056);
    bf16* Bc_l = Bc_h + 64 * SSP;

    const int b  = blockIdx.y;
    const int l0 = blockIdx.x * 128;
    const int tid = threadIdx.x;
    const int lane = tid & 31, warp = tid >> 5;
    const int wm = warp >> 1, wn = warp & 1;

    // ================= Phase S: score GEMM =================
    float acc[2][14][4];
#pragma unroll
    for (int mt = 0; mt < 2; mt++)
#pragma unroll
        for (int nt = 0; nt < 14; nt++)
#pragma unroll
            for (int j = 0; j < 4; j++) acc[mt][nt][j] = 0.f;

    for (int k0 = 0; k0 < 512; k0 += BK) {
#pragma unroll
        for (int i = 0; i < 8; i++) {
            int u = i * 256 + tid;
            int row = u >> 4, kp = (u & 15) << 1;
            size_t ga = ((size_t)b * L_ + l0 + row) * 512 + k0 + kp;
            *(unsigned*)&As_h[row * APAD + kp] = *(const unsigned*)&g_qh[ga];
            *(unsigned*)&As_l[row * APAD + kp] = *(const unsigned*)&g_ql[ga];
        }
#pragma unroll
        for (int i = 0; i < 14; i++) {
            int u = i * 256 + tid;
            int row = u >> 4, kp = (u & 15) << 1;
            size_t gb = ((size_t)b * PP + row) * 512 + k0 + kp;
            *(unsigned*)&Bs_h[row * APAD + kp] = *(const unsigned*)&g_fTh[gb];
            *(unsigned*)&Bs_l[row * APAD + kp] = *(const unsigned*)&g_fTl[gb];
        }
        __syncthreads();

#pragma unroll
        for (int ks = 0; ks < BK; ks += 16) {
            const int kb = ks + (lane & 3) * 2;
            unsigned ah[2][4], al[2][4];
#pragma unroll
            for (int mt = 0; mt < 2; mt++) {
                int rb = wm * 32 + mt * 16 + (lane >> 2);
                ah[mt][0] = *(unsigned*)&As_h[rb * APAD + kb];
                ah[mt][1] = *(unsigned*)&As_h[(rb + 8) * APAD + kb];
                ah[mt][2] = *(unsigned*)&As_h[rb * APAD + kb + 8];
                ah[mt][3] = *(unsigned*)&As_h[(rb + 8) * APAD + kb + 8];
                al[mt][0] = *(unsigned*)&As_l[rb * APAD + kb];
                al[mt][1] = *(unsigned*)&As_l[(rb + 8) * APAD + kb];
                al[mt][2] = *(unsigned*)&As_l[rb * APAD + kb + 8];
                al[mt][3] = *(unsigned*)&As_l[(rb + 8) * APAD + kb + 8];
            }
#pragma unroll
            for (int nt = 0; nt < 14; nt++) {
                int col = wn * 112 + nt * 8 + (lane >> 2);
                unsigned bh0 = *(unsigned*)&Bs_h[col * APAD + kb];
                unsigned bh1 = *(unsigned*)&Bs_h[col * APAD + kb + 8];
                unsigned bl0 = *(unsigned*)&Bs_l[col * APAD + kb];
                unsigned bl1 = *(unsigned*)&Bs_l[col * APAD + kb + 8];
#pragma unroll
                for (int mt = 0; mt < 2; mt++) {
                    mma_bf16(acc[mt][nt], ah[mt], bh0, bh1);
                    mma_bf16(acc[mt][nt], ah[mt], bl0, bl1);
                    mma_bf16(acc[mt][nt], al[mt], bh0, bh1);
                }
            }
        }
        __syncthreads();
    }

#pragma unroll
    for (int mt = 0; mt < 2; mt++)
#pragma unroll
        for (int nt = 0; nt < 14; nt++) {
            int r = wm * 32 + mt * 16 + (lane >> 2);
            int cl = wn * 112 + nt * 8 + (lane & 3) * 2;
            ss[r * SSP + cl]           = acc[mt][nt][0];
            ss[r * SSP + cl + 1]       = acc[mt][nt][1];
            ss[(r + 8) * SSP + cl]     = acc[mt][nt][2];
            ss[(r + 8) * SSP + cl + 1] = acc[mt][nt][3];
        }
    __syncthreads();

    // ================= Softmax =================
    for (int r = 0; r < 16; r++) {
        int row = warp * 16 + r;
        float v[7];
        float mx = -1e30f;
#pragma unroll
        for (int k = 0; k < 7; k++) {
            int p = lane + 32 * k;
            v[k] = (p < HW) ? ss[row * SSP + p] : -1e30f;
            mx = fmaxf(mx, v[k]);
        }
#pragma unroll
        for (int off = 16; off > 0; off >>= 1)
            mx = fmaxf(mx, __shfl_xor_sync(0xffffffffu, mx, off));
        float s = 0.f;
#pragma unroll
        for (int k = 0; k < 7; k++) {
            int p = lane + 32 * k;
            if (p < HW) { v[k] = expf(v[k] - mx); s += v[k]; }
        }
#pragma unroll
        for (int off = 16; off > 0; off >>= 1)
            s += __shfl_xor_sync(0xffffffffu, s, off);
        float inv = 1.f / s;
        float* ao = attn_out + ((size_t)b * L_ + l0 + row) * HW;
#pragma unroll
        for (int k = 0; k < 7; k++) {
            int p = lane + 32 * k;
            if (p < HW) {
                float a = v[k] * inv;
                ss[row * SSP + p] = a;
                ao[p] = a;
            } else {
                ss[row * SSP + p] = 0.f;
            }
        }
    }
    __syncthreads();

    // ================= Phase C: ctx GEMM =================
#pragma unroll 1
    for (int a0 = 0; a0 < 512; a0 += 64) {
#pragma unroll
        for (int i = 0; i < 28; i++) {
            int u = i * 256 + tid;
            int row = u / 112, pc = (u - row * 112) * 2;
            size_t gb = ((size_t)b * 512 + a0 + row) * PP + pc;
            *(unsigned*)&Bc_h[row * SSP + pc] = *(const unsigned*)&g_fh[gb];
            *(unsigned*)&Bc_l[row * SSP + pc] = *(const unsigned*)&g_fl[gb];
        }
        __syncthreads();

        float ac2[2][4][4];
#pragma unroll
        for (int mt = 0; mt < 2; mt++)
#pragma unroll
            for (int nt = 0; nt < 4; nt++)
#pragma unroll
                for (int j = 0; j < 4; j++) ac2[mt][nt][j] = 0.f;

#pragma unroll 2
        for (int p0 = 0; p0 < PP; p0 += 16) {
            const int kb = p0 + (lane & 3) * 2;
            unsigned ah[2][4], al[2][4];
#pragma unroll
            for (int mt = 0; mt < 2; mt++) {
                int rb = wm * 32 + mt * 16 + (lane >> 2);
#pragma unroll
                for (int f = 0; f < 4; f++) {
                    int rr = rb + ((f & 1) ? 8 : 0);
                    int cc = kb + ((f & 2) ? 8 : 0);
                    float2 v = *(const float2*)&ss[rr * SSP + cc];
                    bf16 h0 = __float2bfloat16(v.x);
                    bf16 h1 = __float2bfloat16(v.y);
                    __nv_bfloat162 hp; hp.x = h0; hp.y = h1;
                    __nv_bfloat162 lp;
                    lp.x = __float2bfloat16(v.x - __bfloat162float(h0));
                    lp.y = __float2bfloat16(v.y - __bfloat162float(h1));
                    ah[mt][f] = *(unsigned*)&hp;
                    al[mt][f] = *(unsigned*)&lp;
                }
            }
#pragma unroll
            for (int nt = 0; nt < 4; nt++) {
                int col = wn * 32 + nt * 8 + (lane >> 2);
                unsigned bh0 = *(unsigned*)&Bc_h[col * SSP + kb];
                unsigned bh1 = *(unsigned*)&Bc_h[col * SSP + kb + 8];
                unsigned bl0 = *(unsigned*)&Bc_l[col * SSP + kb];
                unsigned bl1 = *(unsigned*)&Bc_l[col * SSP + kb + 8];
#pragma unroll
                for (int mt = 0; mt < 2; mt++) {
                    mma_bf16(ac2[mt][nt], ah[mt], bh0, bh1);
                    mma_bf16(ac2[mt][nt], ah[mt], bl0, bl1);
                    mma_bf16(ac2[mt][nt], al[mt], bh0, bh1);
                }
            }
        }

#pragma unroll
        for (int mt = 0; mt < 2; mt++)
#pragma unroll
            for (int nt = 0; nt < 4; nt++) {
                int r = wm * 32 + mt * 16 + (lane >> 2);
                int cl = wn * 32 + nt * 8 + (lane & 3) * 2;
                Cs[r * 65 + cl]           = ac2[mt][nt][0];
                Cs[r * 65 + cl + 1]       = ac2[mt][nt][1];
                Cs[(r + 8) * 65 + cl]     = ac2[mt][nt][2];
                Cs[(r + 8) * 65 + cl + 1] = ac2[mt][nt][3];
            }
        __syncthreads();

        // write ctx split bf16, layout (b, l, a), coalesced over a
#pragma unroll
        for (int i = 0; i < 32; i++) {
            int e = i * 256 + tid;
            int a = e & 63, l = e >> 6;
            float v = Cs[l * 65 + a];
            bf16 hi, lo; split2(v, hi, lo);
            size_t off = ((size_t)b * L_ + l0 + l) * 512 + a0 + a;
            g_cxh[off] = hi; g_cxl[off] = lo;
        }
        __syncthreads();
    }
}

// ---------------------------------------------------------------------------
extern "C" void kernel_launch(void* const* d_in, const int* in_sizes, int n_in,
                              void* d_out, int out_size) {
    (void)in_sizes; (void)n_in; (void)out_size;
    const float* x      = (const float*)d_in[0];
    const float* we     = (const float*)d_in[1];
    const float* img    = (const float*)d_in[2];
    /* d_in[3] prev_attn unused */
    const float* conv_v = (const float*)d_in[4];
    const float* conv_g = (const float*)d_in[5];
    const float* conv_b = (const float*)d_in[6];
    const float* fc1_w  = (const float*)d_in[7];
    const float* fc1_b  = (const float*)d_in[8];
    const float* fc2_w  = (const float*)d_in[9];
    const float* fc2_b  = (const float*)d_in[10];
    float* out = (float*)d_out;

    // passthrough copies
    cudaMemcpyAsync(out + OUT_WE, we, (size_t)B_ * L_ * DW * sizeof(float),
                    cudaMemcpyDeviceToDevice, 0);
    cudaMemcpyAsync(out + OUT_IMG, img, (size_t)B_ * DW * HW * sizeof(float),
                    cudaMemcpyDeviceToDevice, 0);

    void *p_w1p, *p_w2p;
    cudaGetSymbolAddress(&p_w1p, g_w1p);
    cudaGetSymbolAddress(&p_w2p, g_w2p);

    // prep
    wnorm_kernel<<<COUT, 256>>>(conv_v, conv_g);
    pack_conv_kernel<<<dim3(80, 8), 256>>>();
    pack_fc_kernel<<<dim3(16, 4, 4), 256>>>(fc1_w, (bf16*)p_w1p);
    pack_fc_kernel<<<dim3(16, 4, 4), 256>>>(fc2_w, (bf16*)p_w2p);
    xT_kernel<<<dim3(L_ / 32, CIN / 32, B_), dim3(32, 8)>>>(x);
    featT_kernel<<<dim3(PP / 32, 512 / 32, B_), dim3(32, 8)>>>(img);
    featpad_kernel<<<(B_ * 512 * PP + 255) / 256, 256>>>(img);

    // opt-in dynamic smem
    cudaFuncSetAttribute(conv_gemm, cudaFuncAttributeMaxDynamicSharedMemorySize, CV_SMEM);
    cudaFuncSetAttribute(fc_gemm<1>, cudaFuncAttributeMaxDynamicSharedMemorySize, FC_SMEM);
    cudaFuncSetAttribute(fc_gemm<2>, cudaFuncAttributeMaxDynamicSharedMemorySize, FC_SMEM);
    cudaFuncSetAttribute(attn_tc_kernel, cudaFuncAttributeMaxDynamicSharedMemorySize,
                         ATTN_SMEM_BYTES);

    // conv + GLU  (M=1024 interleaved, N=1024, K=2560), tile 128x128
    conv_gemm<<<dim3(L_ / 128, 8, B_), 256, CV_SMEM>>>(conv_b);
    // fc1 (M=512, N=1024, K=512) -> q bf16 (b,l,a)
    fc_gemm<1><<<dim3(L_ / 128, 4, B_), 256, FC_SMEM>>>(fc1_b, we, nullptr);
    // tensor-core attention -> attn output + ctx (b,l,a)
    attn_tc_kernel<<<dim3(L_ / 128, B_), 256, ATTN_SMEM_BYTES>>>(out + OUT_ATTN);
    // fc2 + residuals (M=512, N=1024, K=512)
    fc_gemm<2><<<dim3(L_ / 128, 4, B_), 256, FC_SMEM>>>(fc2_b, x, out);
}

// round 14
// speedup vs baseline: 1.1063x; 1.0248x over previous
#include <cuda_runtime.h>
#include <cuda_bf16.h>
#include <math.h>

// Problem constants
#define B_  16
#define CIN 512
#define L_  1024
#define COUT 1024
#define K_  5
#define DW  512
#define HW  196
#define KCONV (CIN * K_)   // 2560
#define PP  224            // padded p dimension

// Output layout (concatenated tuple): out, word_embed, img_conv, attn
#define OUT_WE   8388608u
#define OUT_IMG  16777216u
#define OUT_ATTN 18382848u

typedef __nv_bfloat16 bf16;

// ---------------------------------------------------------------------------
// Scratch (device globals; allocation-free rule)
// ---------------------------------------------------------------------------
__device__ float g_w[COUT * KCONV];            // normalized conv weights (co, c, t)
__device__ float g_h[B_ * DW * L_];            // GLU output fp32 (b, ch, l)
__device__ bf16 g_xTh[B_ * L_ * CIN], g_xTl[B_ * L_ * CIN];   // x^T split (b, l, c)
__device__ bf16 g_cwp[8 * 80 * 8192];          // conv W fragment-packed tiles (16KB)
__device__ bf16 g_w1p[4 * 16 * 8192];          // fc1 W fragment-packed tiles (16KB)
__device__ bf16 g_w2p[4 * 16 * 8192];          // fc2 W fragment-packed tiles (16KB)
__device__ bf16 g_hTh[B_ * L_ * DW], g_hTl[B_ * L_ * DW];     // h split (b, l, c)
__device__ bf16 g_qh[B_ * L_ * DW],  g_ql[B_ * L_ * DW];      // q split (b, l, a)
__device__ bf16 g_cxh[B_ * L_ * DW], g_cxl[B_ * L_ * DW];     // ctx split (b, l, a)
__device__ bf16 g_fTh[B_ * PP * DW], g_fTl[B_ * PP * DW];     // feat^T split (b, p, a)
__device__ bf16 g_fh[B_ * DW * PP],  g_fl[B_ * DW * PP];      // feat split (b, a, p)

__device__ __forceinline__ void split2(float v, bf16& h, bf16& l) {
    h = __float2bfloat16(v);
    l = __float2bfloat16(v - __bfloat162float(h));
}

// ---- async copy primitives ----
__device__ __forceinline__ void cp16(void* dst, const void* src) {
    unsigned d = (unsigned)__cvta_generic_to_shared(dst);
    asm volatile("cp.async.cg.shared.global [%0], [%1], 16;\n" :: "r"(d), "l"(src));
}
#define CP_COMMIT() asm volatile("cp.async.commit_group;\n")
#define CP_WAIT0()  asm volatile("cp.async.wait_group 0;\n")

#define MBAR_INIT(addr, cnt) \
    asm volatile("mbarrier.init.shared.b64 [%0], %1;" :: "r"(addr), "r"(cnt) : "memory")
#define MBAR_EXPECT(addr, tx) \
    asm volatile("mbarrier.arrive.expect_tx.shared.b64 _, [%0], %1;" :: "r"(addr), "r"(tx) : "memory")

__device__ __forceinline__ void mbar_wait(unsigned mbar, unsigned parity) {
    asm volatile(
        "{\n\t.reg .pred P;\n\t"
        "W_%=:\n\t"
        "mbarrier.try_wait.parity.acquire.cta.shared::cta.b64 P, [%0], %1;\n\t"
        "@!P bra W_%=;\n\t}"
        :: "r"(mbar), "r"(parity) : "memory");
}

__device__ __forceinline__ void bulk_g2s(unsigned dst_smem, const void* src,
                                         unsigned bytes, unsigned mbar) {
    asm volatile(
        "cp.async.bulk.shared::cluster.global.mbarrier::complete_tx::bytes "
        "[%0], [%1], %2, [%3];"
        :: "r"(dst_smem), "l"(src), "r"(bytes), "r"(mbar) : "memory");
}

// ---------------------------------------------------------------------------
// Prep kernels
// ---------------------------------------------------------------------------
__global__ void wnorm_kernel(const float* __restrict__ v,
                             const float* __restrict__ g) {
    int co = blockIdx.x;
    const float* vr = v + (size_t)co * KCONV;
    float s = 0.f;
    for (int i = threadIdx.x; i < KCONV; i += 256) { float t = vr[i]; s += t * t; }
    __shared__ float red[256];
    red[threadIdx.x] = s;
    __syncthreads();
    for (int st = 128; st > 0; st >>= 1) {
        if (threadIdx.x < st) red[threadIdx.x] += red[threadIdx.x + st];
        __syncthreads();
    }
    float scale = g[co] / sqrtf(red[0]);
    float* wr = g_w + (size_t)co * KCONV;
    for (int i = threadIdx.x; i < KCONV; i += 256) wr[i] = scale * vr[i];
}

// Fragment-order pack layout (tile = 1024 16B-chunks = 16KB):
//   chunk u: lane=u&31, mt=(u>>5)&1, wm=(u>>6)&3, ks=(u>>8)&1, plane=(u>>9)&1
//   4 words w: row = wm*32+mt*16+(lane>>2)+((w&1)?8:0)
//              k   = ks*16+(lane&3)*2+(w>>1)*8   (2 bf16: k, k+1)

// conv: tile (mb, kc), kc = t*16 + ci; element k maps to c = ci*32 + k
__global__ void pack_conv_kernel() {
    const int kc = blockIdx.x, mb = blockIdx.y;
    const int t = kc / 16, ci = kc % 16;
    bf16* dst = g_cwp + (size_t)(mb * 80 + kc) * 8192;
    for (int u = threadIdx.x; u < 1024; u += 256) {
        int lane2 = u & 31, mt = (u >> 5) & 1, wm2 = (u >> 6) & 3;
        int ks = (u >> 8) & 1, plane = (u >> 9) & 1;
        int row0 = wm2 * 32 + mt * 16 + (lane2 >> 2);
        int kb = ks * 16 + (lane2 & 3) * 2;
        unsigned words[4];
#pragma unroll
        for (int w = 0; w < 4; w++) {
            int row = row0 + ((w & 1) ? 8 : 0);
            int k = kb + (w >> 1) * 8;
            int m = mb * 128 + row;
            int co = (m & 1) ? (512 + (m >> 1)) : (m >> 1);
            unsigned short p0, p1;
#pragma unroll
            for (int e = 0; e < 2; e++) {
                int c = ci * 32 + k + e;
                float v = g_w[(size_t)co * KCONV + c * K_ + t];
                bf16 hi, lo; split2(v, hi, lo);
                bf16 sel = plane ? lo : hi;
                unsigned short us = *(unsigned short*)&sel;
                if (e == 0) p0 = us; else p1 = us;
            }
            words[w] = (unsigned)p0 | ((unsigned)p1 << 16);
        }
        *(uint4*)(dst + u * 8) = make_uint4(words[0], words[1], words[2], words[3]);
    }
}

// fc pack (both W1 and W2 in one launch): blockIdx.z in [0,8): z>=4 -> W2
__global__ void pack_fc_kernel(const float* __restrict__ W1, const float* __restrict__ W2,
                               bf16* __restrict__ d1, bf16* __restrict__ d2) {
    const int kc = blockIdx.x, mb = blockIdx.y;
    const int zsel = blockIdx.z >> 2, zz = blockIdx.z & 3;
    const float* W = zsel ? W2 : W1;
    bf16* dst = (zsel ? d2 : d1) + (size_t)(mb * 16 + kc) * 8192;
    int u = zz * 256 + threadIdx.x;
    {
        int lane2 = u & 31, mt = (u >> 5) & 1, wm2 = (u >> 6) & 3;
        int ks = (u >> 8) & 1, plane = (u >> 9) & 1;
        int row0 = wm2 * 32 + mt * 16 + (lane2 >> 2);
        int kb = ks * 16 + (lane2 & 3) * 2;
        unsigned words[4];
#pragma unroll
        for (int w = 0; w < 4; w++) {
            int row = row0 + ((w & 1) ? 8 : 0);
            int k = kb + (w >> 1) * 8;
            unsigned short p0, p1;
#pragma unroll
            for (int e = 0; e < 2; e++) {
                float v = W[(size_t)(mb * 128 + row) * 512 + kc * 32 + k + e];
                bf16 hi, lo; split2(v, hi, lo);
                bf16 sel = plane ? lo : hi;
                unsigned short us = *(unsigned short*)&sel;
                if (e == 0) p0 = us; else p1 = us;
            }
            words[w] = (unsigned)p0 | ((unsigned)p1 << 16);
        }
        *(uint4*)(dst + u * 8) = make_uint4(words[0], words[1], words[2], words[3]);
    }
}

// x (b,c,l) -> xT split (b,l,c)
__global__ void xT_kernel(const float* __restrict__ x) {
    __shared__ float t[32][33];
    const int b = blockIdx.z, l0 = blockIdx.x * 32, c0 = blockIdx.y * 32;
    const int tx = threadIdx.x, ty0 = threadIdx.y;
#pragma unroll
    for (int j = 0; j < 4; j++) {
        int ty = ty0 + j * 8;
        t[ty][tx] = x[((size_t)b * CIN + c0 + ty) * L_ + l0 + tx];
    }
    __syncthreads();
#pragma unroll
    for (int j = 0; j < 4; j++) {
        int ty = ty0 + j * 8;
        float v = t[tx][ty];
        bf16 hi, lo; split2(v, hi, lo);
        size_t off = ((size_t)b * L_ + l0 + ty) * 512 + c0 + tx;
        g_xTh[off] = hi; g_xTl[off] = lo;
    }
}

// feat^T split (b, p, a) AND feat pad split (b, a, PP); p>=196 zero.
__global__ void featT_kernel(const float* __restrict__ img) {
    __shared__ float t[32][33];
    const int b = blockIdx.z, p0 = blockIdx.x * 32, a0 = blockIdx.y * 32;
    const int tx = threadIdx.x, ty0 = threadIdx.y;
#pragma unroll
    for (int j = 0; j < 4; j++) {
        int ty = ty0 + j * 8;
        int a = a0 + ty, p = p0 + tx;
        float v = (p < HW) ? img[((size_t)b * 512 + a) * HW + p] : 0.f;
        t[ty][tx] = v;
        // direct (b, a, PP) padded split write, coalesced over p
        bf16 hi, lo; split2(v, hi, lo);
        size_t offf = ((size_t)b * 512 + a) * PP + p;
        g_fh[offf] = hi; g_fl[offf] = lo;
    }
    __syncthreads();
#pragma unroll
    for (int j = 0; j < 4; j++) {
        int ty = ty0 + j * 8;
        float v = t[tx][ty];
        bf16 hi, lo; split2(v, hi, lo);
        size_t off = ((size_t)b * PP + p0 + ty) * 512 + a0 + tx;
        g_fTh[off] = hi; g_fTl[off] = lo;
    }
}

// ---------------------------------------------------------------------------
// MMA helper
// ---------------------------------------------------------------------------
__device__ __forceinline__ void mma_bf16(float* c, const unsigned* a,
                                         unsigned b0, unsigned b1) {
    asm volatile(
        "mma.sync.aligned.m16n8k16.row.col.f32.bf16.bf16.f32 "
        "{%0,%1,%2,%3}, {%4,%5,%6,%7}, {%8,%9}, {%0,%1,%2,%3};\n"
        : "+f"(c[0]), "+f"(c[1]), "+f"(c[2]), "+f"(c[3])
        : "r"(a[0]), "r"(a[1]), "r"(a[2]), "r"(a[3]), "r"(b0), "r"(b1));
}

#define APAD 40
#define BK 32

// ---------------------------------------------------------------------------
// Conv GEMM. Tile 128m x 128n, 2 CTA/SM, 8 warps (wm 4 x wn 2), 2mt x 8nt.
// Single sync per iter: issue-next moved after wait+sync, trailing sync gone.
//   smem: A 2x16384 @0 ; B 2x21760 @32768 ; mbar @76288
// ---------------------------------------------------------------------------
#define CV_A_STAGE 16384
#define CV_B_OFF   32768
#define CV_B_STAGE 21760
#define CV_MBAR    76288
#define CV_SMEM    76416

__global__ __launch_bounds__(256, 2) void conv_gemm(const float* __restrict__ bias) {
    extern __shared__ __align__(16) unsigned char dynsm[];
    const int b = blockIdx.z, mb = blockIdx.y, l0 = blockIdx.x * 128;
    const int tid = threadIdx.x;
    const int lane = tid & 31, warp = tid >> 5;
    const int wm = warp >> 1, wn = warp & 1;

    unsigned smem_base = (unsigned)__cvta_generic_to_shared(dynsm);
    unsigned mbar0 = smem_base + CV_MBAR, mbar1 = mbar0 + 8;
    if (tid == 0) { MBAR_INIT(mbar0, 1); MBAR_INIT(mbar1, 1); }
    __syncthreads();

    float acc[2][8][4];
#pragma unroll
    for (int mt = 0; mt < 2; mt++)
#pragma unroll
        for (int nt = 0; nt < 8; nt++)
#pragma unroll
            for (int j = 0; j < 4; j++) acc[mt][nt][j] = 0.f;

    auto issueA = [&](int s, int kc) {
        if (tid == 0) {
            unsigned mbx = s ? mbar1 : mbar0;
            MBAR_EXPECT(mbx, CV_A_STAGE);
            const char* src = (const char*)g_cwp + (size_t)(mb * 80 + kc) * CV_A_STAGE;
            bulk_g2s(smem_base + s * CV_A_STAGE, src, CV_A_STAGE, mbx);
        }
    };
    auto issueB = [&](int sb, int ci) {
        int c0 = ci * 32;
        unsigned char* dst0 = dynsm + CV_B_OFF + sb * CV_B_STAGE;
        // 2 planes x 132 rows x 4 chunks = 1056 cp16
#pragma unroll
        for (int ii = 0; ii < 5; ii++) {
            int u = ii * 256 + tid;
            if (u < 1056) {
                int plane = (u >= 528) ? 1 : 0;
                int v = u - plane * 528;
                int r = v >> 2, j = v & 3;
                if (!(l0 == 0 && r < 4)) {
                    const bf16* src = (plane ? g_xTl : g_xTh) +
                        ((size_t)b * L_ + l0 - 4 + r) * 512 + c0 + j * 8;
                    cp16(dst0 + plane * 10880 + r * 80 + j * 16, src);
                }
            }
        }
        if (l0 == 0 && tid < 160) {
            int plane = tid / 80, v = tid % 80, r = v / 20, w = v % 20;
            *(unsigned*)(dst0 + plane * 10880 + r * 80 + w * 4) = 0u;
        }
    };

    // prologue
    issueB(0, 0);
    CP_COMMIT();
    issueA(0, 0);
    int ph0 = 0, ph1 = 0;

    for (int i = 0; i < 80; i++) {
        const int ci = i / 5, t = i - ci * 5, s = i & 1;
        if (s == 0) { mbar_wait(mbar0, ph0); ph0 ^= 1; }
        else        { mbar_wait(mbar1, ph1); ph1 ^= 1; }
        if (t == 0) CP_WAIT0();
        __syncthreads();   // all warps done with iter i-1; safe to overwrite its stages

        if (i + 1 < 80) {
            int ni = i + 1, nci = ni / 5, nt2 = ni - nci * 5;
            issueA(ni & 1, nt2 * 16 + nci);
            if (nt2 == 0) { issueB(nci & 1, nci); CP_COMMIT(); }
        }

        const unsigned char* Ab = dynsm + s * CV_A_STAGE;
        const bf16* Bh = (const bf16*)(dynsm + CV_B_OFF + (ci & 1) * CV_B_STAGE);
        const bf16* Bl = (const bf16*)((const unsigned char*)Bh + 10880);

#pragma unroll
        for (int ks = 0; ks < 2; ks++) {
            unsigned ah[2][4], al[2][4];
#pragma unroll
            for (int mt = 0; mt < 2; mt++) {
                int chunk = (((ks * 4 + wm) * 2 + mt) * 32 + lane) * 16;
                uint4 va = *(const uint4*)(Ab + chunk);
                ah[mt][0] = va.x; ah[mt][1] = va.y; ah[mt][2] = va.z; ah[mt][3] = va.w;
                uint4 vb = *(const uint4*)(Ab + 8192 + chunk);
                al[mt][0] = vb.x; al[mt][1] = vb.y; al[mt][2] = vb.z; al[mt][3] = vb.w;
            }
            const int kb = ks * 16 + (lane & 3) * 2;
#pragma unroll
            for (int nt = 0; nt < 8; nt++) {
                int row = wn * 64 + nt * 8 + (lane >> 2) + t;
                unsigned bh0 = *(const unsigned*)&Bh[row * APAD + kb];
                unsigned bh1 = *(const unsigned*)&Bh[row * APAD + kb + 8];
                unsigned bl0 = *(const unsigned*)&Bl[row * APAD + kb];
                unsigned bl1 = *(const unsigned*)&Bl[row * APAD + kb + 8];
#pragma unroll
                for (int mt = 0; mt < 2; mt++) {
                    mma_bf16(acc[mt][nt], ah[mt], bh0, bh1);
                    mma_bf16(acc[mt][nt], ah[mt], bl0, bl1);
                    mma_bf16(acc[mt][nt], al[mt], bh0, bh1);
                }
            }
        }
    }
    __syncthreads();

    // ---- epilogue: two 64-col passes through Cs[128][65] ----
    float* Cs = (float*)dynsm;
    const int ch0 = mb * 64;
#pragma unroll 1
    for (int p = 0; p < 2; p++) {
        if (wn == p) {
#pragma unroll
            for (int mt = 0; mt < 2; mt++)
#pragma unroll
                for (int nt = 0; nt < 8; nt++) {
                    int r = wm * 32 + mt * 16 + (lane >> 2);
                    int cl = nt * 8 + (lane & 3) * 2;
                    Cs[r * 65 + cl]           = acc[mt][nt][0];
                    Cs[r * 65 + cl + 1]       = acc[mt][nt][1];
                    Cs[(r + 8) * 65 + cl]     = acc[mt][nt][2];
                    Cs[(r + 8) * 65 + cl + 1] = acc[mt][nt][3];
                }
        }
        __syncthreads();
        const int lbase = l0 + p * 64;
#pragma unroll
        for (int i = 0; i < 16; i++) {
            int e = i * 256 + tid;
            int chl = e >> 6, ll = e & 63;
            float av = Cs[(chl * 2) * 65 + ll] + __ldg(&bias[ch0 + chl]);
            float bv = Cs[(chl * 2 + 1) * 65 + ll] + __ldg(&bias[512 + ch0 + chl]);
            float hv = av / (1.f + expf(-bv));
            g_h[((size_t)b * 512 + ch0 + chl) * L_ + lbase + ll] = hv;
            Cs[(chl * 2) * 65 + ll] = hv;
        }
        __syncthreads();
#pragma unroll
        for (int i = 0; i < 16; i++) {
            int e = i * 256 + tid;
            int chl = e & 63, ll = e >> 6;
            float hv = Cs[(chl * 2) * 65 + ll];
            bf16 hi, lo; split2(hv, hi, lo);
            size_t off = ((size_t)b * L_ + lbase + ll) * 512 + ch0 + chl;
            g_hTh[off] = hi; g_hTl[off] = lo;
        }
        __syncthreads();
    }
}

// ---------------------------------------------------------------------------
// fc GEMM (MODE 1: fc1, MODE 2: fc2), fragment-order A, single sync/iter.
//   smem: A 2x16384 @0 ; B 2x20480 @32768 ; mbar @73728
// ---------------------------------------------------------------------------
#define FC_A_STAGE 16384
#define FC_B_OFF   32768
#define FC_B_STAGE 20480
#define FC_MBAR    73728
#define FC_SMEM    73856

template <int MODE>
__global__ __launch_bounds__(256, 2) void fc_gemm(
    const float* __restrict__ bias, const float* __restrict__ e1,
    float* __restrict__ outp) {
    extern __shared__ __align__(16) unsigned char dynsm[];
    const int b = blockIdx.z, mb = blockIdx.y, l0 = blockIdx.x * 128;
    const int m0 = mb * 128;
    const int tid = threadIdx.x;
    const int lane = tid & 31, warp = tid >> 5;
    const int wm = warp >> 1, wn = warp & 1;

    const bf16* Wp  = (MODE == 1) ? g_w1p : g_w2p;
    const bf16* Bgh = (MODE == 1) ? g_hTh : g_cxh;   // (b, l, k)
    const bf16* Bgl = (MODE == 1) ? g_hTl : g_cxl;

    unsigned smem_base = (unsigned)__cvta_generic_to_shared(dynsm);
    unsigned mbar0 = smem_base + FC_MBAR, mbar1 = mbar0 + 8;
    if (tid == 0) { MBAR_INIT(mbar0, 1); MBAR_INIT(mbar1, 1); }
    __syncthreads();

    float acc[2][8][4];
#pragma unroll
    for (int mt = 0; mt < 2; mt++)
#pragma unroll
        for (int nt = 0; nt < 8; nt++)
#pragma unroll
            for (int j = 0; j < 4; j++) acc[mt][nt][j] = 0.f;

    auto issueA = [&](int s, int kc) {
        if (tid == 0) {
            unsigned mbx = s ? mbar1 : mbar0;
            MBAR_EXPECT(mbx, FC_A_STAGE);
            const char* src = (const char*)Wp + (size_t)(mb * 16 + kc) * FC_A_STAGE;
            bulk_g2s(smem_base + s * FC_A_STAGE, src, FC_A_STAGE, mbx);
        }
    };
    auto issueB = [&](int s, int kc) {
        unsigned char* dst0 = dynsm + FC_B_OFF + s * FC_B_STAGE;
#pragma unroll
        for (int ii = 0; ii < 4; ii++) {
            int u = ii * 256 + tid;
            int plane = u >> 9, v = u & 511;
            int r = v >> 2, j = v & 3;
            const bf16* src = (plane ? Bgl : Bgh) +
                ((size_t)b * L_ + l0 + r) * 512 + kc * 32 + j * 8;
            cp16(dst0 + plane * 10240 + r * 80 + j * 16, src);
        }
    };

    issueA(0, 0);
    issueB(0, 0);
    CP_COMMIT();
    int ph0 = 0, ph1 = 0;

    for (int i = 0; i < 16; i++) {
        const int s = i & 1;
        if (s == 0) { mbar_wait(mbar0, ph0); ph0 ^= 1; }
        else        { mbar_wait(mbar1, ph1); ph1 ^= 1; }
        CP_WAIT0();
        __syncthreads();   // all warps done with iter i-1

        if (i < 15) {
            issueA(s ^ 1, i + 1);
            issueB(s ^ 1, i + 1);
            CP_COMMIT();
        }

        const unsigned char* Ab = dynsm + s * FC_A_STAGE;
        const bf16* Bh = (const bf16*)(dynsm + FC_B_OFF + s * FC_B_STAGE);
        const bf16* Bl = (const bf16*)((const unsigned char*)Bh + 10240);

#pragma unroll
        for (int ks = 0; ks < 2; ks++) {
            unsigned ah[2][4], al[2][4];
#pragma unroll
            for (int mt = 0; mt < 2; mt++) {
                int chunk = (((ks * 4 + wm) * 2 + mt) * 32 + lane) * 16;
                uint4 va = *(const uint4*)(Ab + chunk);
                ah[mt][0] = va.x; ah[mt][1] = va.y; ah[mt][2] = va.z; ah[mt][3] = va.w;
                uint4 vb = *(const uint4*)(Ab + 8192 + chunk);
                al[mt][0] = vb.x; al[mt][1] = vb.y; al[mt][2] = vb.z; al[mt][3] = vb.w;
            }
            const int kb = ks * 16 + (lane & 3) * 2;
#pragma unroll
            for (int nt = 0; nt < 8; nt++) {
                int col = wn * 64 + nt * 8 + (lane >> 2);
                unsigned bh0 = *(const unsigned*)&Bh[col * APAD + kb];
                unsigned bh1 = *(const unsigned*)&Bh[col * APAD + kb + 8];
                unsigned bl0 = *(const unsigned*)&Bl[col * APAD + kb];
                unsigned bl1 = *(const unsigned*)&Bl[col * APAD + kb + 8];
#pragma unroll
                for (int mt = 0; mt < 2; mt++) {
                    mma_bf16(acc[mt][nt], ah[mt], bh0, bh1);
                    mma_bf16(acc[mt][nt], ah[mt], bl0, bl1);
                    mma_bf16(acc[mt][nt], al[mt], bh0, bh1);
                }
            }
        }
    }
    __syncthreads();

    // ---- epilogue ----
    float* Cs = (float*)dynsm;
#pragma unroll 1
    for (int p = 0; p < 2; p++) {
        if (wn == p) {
#pragma unroll
            for (int mt = 0; mt < 2; mt++)
#pragma unroll
                for (int nt = 0; nt < 8; nt++) {
                    int r = wm * 32 + mt * 16 + (lane >> 2);
                    int cl = nt * 8 + (lane & 3) * 2;
                    Cs[r * 65 + cl]           = acc[mt][nt][0];
                    Cs[r * 65 + cl + 1]       = acc[mt][nt][1];
                    Cs[(r + 8) * 65 + cl]     = acc[mt][nt][2];
                    Cs[(r + 8) * 65 + cl + 1] = acc[mt][nt][3];
                }
        }
        __syncthreads();
        const int lbase = l0 + p * 64;
        if (MODE == 1) {
#pragma unroll
            for (int i = 0; i < 32; i++) {
                int e = i * 256 + tid;
                int a = e & 127, ll = e >> 7;
                Cs[a * 65 + ll] += __ldg(&bias[m0 + a]) +
                    e1[((size_t)b * L_ + lbase + ll) * 512 + m0 + a];
            }
            __syncthreads();
#pragma unroll
            for (int i = 0; i < 32; i++) {
                int e = i * 256 + tid;
                int a = e & 127, ll = e >> 7;
                float v = Cs[a * 65 + ll];
                bf16 hi, lo; split2(v, hi, lo);
                size_t off = ((size_t)b * L_ + lbase + ll) * 512 + m0 + a;
                g_qh[off] = hi; g_ql[off] = lo;
            }
        } else {
#pragma unroll
            for (int i = 0; i < 32; i++) {
                int e = i * 256 + tid;
                int cl_ = e >> 6, ll = e & 63;
                size_t off = ((size_t)b * 512 + m0 + cl_) * L_ + lbase + ll;
                outp[off] = Cs[cl_ * 65 + ll] + __ldg(&bias[m0 + cl_])
                          + g_h[off] + e1[off];
            }
        }
        __syncthreads();
    }
}

// ---------------------------------------------------------------------------
// Tensor-core attention. Softmax writes probs in place as bf16 hi/lo planes
// inside each row's 912B fp32 footprint (hi @ +0, lo @ +456); phase C loads
// fragments directly (no on-the-fly conversion). ctx emitted (b, l, a).
// ---------------------------------------------------------------------------
#define SSP 228
#define SS_ROW 912   // bytes per score row (fp32 228); bf16 planes live inside
#define ATTN_SMEM_BYTES 231424

__global__ __launch_bounds__(256, 1) void attn_tc_kernel(float* __restrict__ attn_out) {
    extern __shared__ __align__(16) unsigned char dynsm[];
    float* ss  = (float*)dynsm;                    // [128][SSP] fp32 scores
    bf16* As_h = (bf16*)(dynsm + 116736);
    bf16* As_l = As_h + 128 * APAD;
    bf16* Bs_h = As_l + 128 * APAD;
    bf16* Bs_l = Bs_h + PP * APAD;
    float* Cs  = (float*)(dynsm + 116736);
    bf16* Bc_h = (bf16*)(dynsm + 173056);
    bf16* Bc_l = Bc_h + 64 * SSP;

    const int b  = blockIdx.y;
    const int l0 = blockIdx.x * 128;
    const int tid = threadIdx.x;
    const int lane = tid & 31, warp = tid >> 5;
    const int wm = warp >> 1, wn = warp & 1;

    // ================= Phase S: score GEMM =================
    float acc[2][14][4];
#pragma unroll
    for (int mt = 0; mt < 2; mt++)
#pragma unroll
        for (int nt = 0; nt < 14; nt++)
#pragma unroll
            for (int j = 0; j < 4; j++) acc[mt][nt][j] = 0.f;

    for (int k0 = 0; k0 < 512; k0 += BK) {
#pragma unroll
        for (int i = 0; i < 8; i++) {
            int u = i * 256 + tid;
            int row = u >> 4, kp = (u & 15) << 1;
            size_t ga = ((size_t)b * L_ + l0 + row) * 512 + k0 + kp;
            *(unsigned*)&As_h[row * APAD + kp] = *(const unsigned*)&g_qh[ga];
            *(unsigned*)&As_l[row * APAD + kp] = *(const unsigned*)&g_ql[ga];
        }
#pragma unroll
        for (int i = 0; i < 14; i++) {
            int u = i * 256 + tid;
            int row = u >> 4, kp = (u & 15) << 1;
            size_t gb = ((size_t)b * PP + row) * 512 + k0 + kp;
            *(unsigned*)&Bs_h[row * APAD + kp] = *(const unsigned*)&g_fTh[gb];
            *(unsigned*)&Bs_l[row * APAD + kp] = *(const unsigned*)&g_fTl[gb];
        }
        __syncthreads();

#pragma unroll
        for (int ks = 0; ks < BK; ks += 16) {
            const int kb = ks + (lane & 3) * 2;
            unsigned ah[2][4], al[2][4];
#pragma unroll
            for (int mt = 0; mt < 2; mt++) {
                int rb = wm * 32 + mt * 16 + (lane >> 2);
                ah[mt][0] = *(unsigned*)&As_h[rb * APAD + kb];
                ah[mt][1] = *(unsigned*)&As_h[(rb + 8) * APAD + kb];
                ah[mt][2] = *(unsigned*)&As_h[rb * APAD + kb + 8];
                ah[mt][3] = *(unsigned*)&As_h[(rb + 8) * APAD + kb + 8];
                al[mt][0] = *(unsigned*)&As_l[rb * APAD + kb];
                al[mt][1] = *(unsigned*)&As_l[(rb + 8) * APAD + kb];
                al[mt][2] = *(unsigned*)&As_l[rb * APAD + kb + 8];
                al[mt][3] = *(unsigned*)&As_l[(rb + 8) * APAD + kb + 8];
            }
#pragma unroll
            for (int nt = 0; nt < 14; nt++) {
                int col = wn * 112 + nt * 8 + (lane >> 2);
                unsigned bh0 = *(unsigned*)&Bs_h[col * APAD + kb];
                unsigned bh1 = *(unsigned*)&Bs_h[col * APAD + kb + 8];
                unsigned bl0 = *(unsigned*)&Bs_l[col * APAD + kb];
                unsigned bl1 = *(unsigned*)&Bs_l[col * APAD + kb + 8];
#pragma unroll
                for (int mt = 0; mt < 2; mt++) {
                    mma_bf16(acc[mt][nt], ah[mt], bh0, bh1);
                    mma_bf16(acc[mt][nt], ah[mt], bl0, bl1);
                    mma_bf16(acc[mt][nt], al[mt], bh0, bh1);
                }
            }
        }
        __syncthreads();
    }

#pragma unroll
    for (int mt = 0; mt < 2; mt++)
#pragma unroll
        for (int nt = 0; nt < 14; nt++) {
            int r = wm * 32 + mt * 16 + (lane >> 2);
            int cl = wn * 112 + nt * 8 + (lane & 3) * 2;
            ss[r * SSP + cl]           = acc[mt][nt][0];
            ss[r * SSP + cl + 1]       = acc[mt][nt][1];
            ss[(r + 8) * SSP + cl]     = acc[mt][nt][2];
            ss[(r + 8) * SSP + cl + 1] = acc[mt][nt][3];
        }
    __syncthreads();

    // ===== Softmax: reads fp32 row, writes attn_out + in-place bf16 planes =====
    for (int r = 0; r < 16; r++) {
        int row = warp * 16 + r;
        float v[7];
        float mx = -1e30f;
#pragma unroll
        for (int k = 0; k < 7; k++) {
            int p = lane + 32 * k;
            v[k] = (p < HW) ? ss[row * SSP + p] : -1e30f;
            mx = fmaxf(mx, v[k]);
        }
#pragma unroll
        for (int off = 16; off > 0; off >>= 1)
            mx = fmaxf(mx, __shfl_xor_sync(0xffffffffu, mx, off));
        float s = 0.f;
#pragma unroll
        for (int k = 0; k < 7; k++) {
            int p = lane + 32 * k;
            if (p < HW) { v[k] = expf(v[k] - mx); s += v[k]; }
        }
#pragma unroll
        for (int off = 16; off > 0; off >>= 1)
            s += __shfl_xor_sync(0xffffffffu, s, off);
        float inv = 1.f / s;
        float* ao = attn_out + ((size_t)b * L_ + l0 + row) * HW;
        bf16* rh = (bf16*)(dynsm + (size_t)row * SS_ROW);
        bf16* rl = (bf16*)(dynsm + (size_t)row * SS_ROW + 456);
        const bf16 z = __float2bfloat16(0.f);
#pragma unroll
        for (int k = 0; k < 7; k++) {
            int p = lane + 32 * k;
            if (p < HW) {
                float a = v[k] * inv;
                ao[p] = a;
                bf16 hi, lo; split2(a, hi, lo);
                rh[p] = hi; rl[p] = lo;
            } else {
                rh[p] = z; rl[p] = z;
            }
        }
    }
    __syncthreads();

    // ================= Phase C: ctx GEMM (fragments from bf16 planes) =========
#pragma unroll 1
    for (int a0 = 0; a0 < 512; a0 += 64) {
#pragma unroll
        for (int i = 0; i < 28; i++) {
            int u = i * 256 + tid;
            int row = u / 112, pc = (u - row * 112) * 2;
            size_t gb = ((size_t)b * 512 + a0 + row) * PP + pc;
            *(unsigned*)&Bc_h[row * SSP + pc] = *(const unsigned*)&g_fh[gb];
            *(unsigned*)&Bc_l[row * SSP + pc] = *(const unsigned*)&g_fl[gb];
        }
        __syncthreads();

        float ac2[2][4][4];
#pragma unroll
        for (int mt = 0; mt < 2; mt++)
#pragma unroll
            for (int nt = 0; nt < 4; nt++)
#pragma unroll
                for (int j = 0; j < 4; j++) ac2[mt][nt][j] = 0.f;

#pragma unroll 2
        for (int p0 = 0; p0 < PP; p0 += 16) {
            const int kb = p0 + (lane & 3) * 2;
            unsigned ah[2][4], al[2][4];
#pragma unroll
            for (int mt = 0; mt < 2; mt++) {
                int rb = wm * 32 + mt * 16 + (lane >> 2);
#pragma unroll
                for (int f = 0; f < 4; f++) {
                    int rr = rb + ((f & 1) ? 8 : 0);
                    int cc = kb + ((f & 2) ? 8 : 0);
                    ah[mt][f] = *(const unsigned*)(dynsm + (size_t)rr * SS_ROW + cc * 2);
                    al[mt][f] = *(const unsigned*)(dynsm + (size_t)rr * SS_ROW + 456 + cc * 2);
                }
            }
#pragma unroll
            for (int nt = 0; nt < 4; nt++) {
                int col = wn * 32 + nt * 8 + (lane >> 2);
                unsigned bh0 = *(unsigned*)&Bc_h[col * SSP + kb];
                unsigned bh1 = *(unsigned*)&Bc_h[col * SSP + kb + 8];
                unsigned bl0 = *(unsigned*)&Bc_l[col * SSP + kb];
                unsigned bl1 = *(unsigned*)&Bc_l[col * SSP + kb + 8];
#pragma unroll
                for (int mt = 0; mt < 2; mt++) {
                    mma_bf16(ac2[mt][nt], ah[mt], bh0, bh1);
                    mma_bf16(ac2[mt][nt], ah[mt], bl0, bl1);
                    mma_bf16(ac2[mt][nt], al[mt], bh0, bh1);
                }
            }
        }

#pragma unroll
        for (int mt = 0; mt < 2; mt++)
#pragma unroll
            for (int nt = 0; nt < 4; nt++) {
                int r = wm * 32 + mt * 16 + (lane >> 2);
                int cl = wn * 32 + nt * 8 + (lane & 3) * 2;
                Cs[r * 65 + cl]           = ac2[mt][nt][0];
                Cs[r * 65 + cl + 1]       = ac2[mt][nt][1];
                Cs[(r + 8) * 65 + cl]     = ac2[mt][nt][2];
                Cs[(r + 8) * 65 + cl + 1] = ac2[mt][nt][3];
            }
        __syncthreads();

        // write ctx split bf16, layout (b, l, a), coalesced over a
#pragma unroll
        for (int i = 0; i < 32; i++) {
            int e = i * 256 + tid;
            int a = e & 63, l = e >> 6;
            float v = Cs[l * 65 + a];
            bf16 hi, lo; split2(v, hi, lo);
            size_t off = ((size_t)b * L_ + l0 + l) * 512 + a0 + a;
            g_cxh[off] = hi; g_cxl[off] = lo;
        }
        __syncthreads();
    }
}

// ---------------------------------------------------------------------------
extern "C" void kernel_launch(void* const* d_in, const int* in_sizes, int n_in,
                              void* d_out, int out_size) {
    (void)in_sizes; (void)n_in; (void)out_size;
    const float* x      = (const float*)d_in[0];
    const float* we     = (const float*)d_in[1];
    const float* img    = (const float*)d_in[2];
    /* d_in[3] prev_attn unused */
    const float* conv_v = (const float*)d_in[4];
    const float* conv_g = (const float*)d_in[5];
    const float* conv_b = (const float*)d_in[6];
    const float* fc1_w  = (const float*)d_in[7];
    const float* fc1_b  = (const float*)d_in[8];
    const float* fc2_w  = (const float*)d_in[9];
    const float* fc2_b  = (const float*)d_in[10];
    float* out = (float*)d_out;

    // passthrough copies
    cudaMemcpyAsync(out + OUT_WE, we, (size_t)B_ * L_ * DW * sizeof(float),
                    cudaMemcpyDeviceToDevice, 0);
    cudaMemcpyAsync(out + OUT_IMG, img, (size_t)B_ * DW * HW * sizeof(float),
                    cudaMemcpyDeviceToDevice, 0);

    void *p_w1p, *p_w2p;
    cudaGetSymbolAddress(&p_w1p, g_w1p);
    cudaGetSymbolAddress(&p_w2p, g_w2p);

    // prep
    wnorm_kernel<<<COUT, 256>>>(conv_v, conv_g);
    pack_conv_kernel<<<dim3(80, 8), 256>>>();
    pack_fc_kernel<<<dim3(16, 4, 8), 256>>>(fc1_w, fc2_w, (bf16*)p_w1p, (bf16*)p_w2p);
    xT_kernel<<<dim3(L_ / 32, CIN / 32, B_), dim3(32, 8)>>>(x);
    featT_kernel<<<dim3(PP / 32, 512 / 32, B_), dim3(32, 8)>>>(img);

    // opt-in dynamic smem
    cudaFuncSetAttribute(conv_gemm, cudaFuncAttributeMaxDynamicSharedMemorySize, CV_SMEM);
    cudaFuncSetAttribute(fc_gemm<1>, cudaFuncAttributeMaxDynamicSharedMemorySize, FC_SMEM);
    cudaFuncSetAttribute(fc_gemm<2>, cudaFuncAttributeMaxDynamicSharedMemorySize, FC_SMEM);
    cudaFuncSetAttribute(attn_tc_kernel, cudaFuncAttributeMaxDynamicSharedMemorySize,
                         ATTN_SMEM_BYTES);

    // conv + GLU  (M=1024 interleaved, N=1024, K=2560), tile 128x128
    conv_gemm<<<dim3(L_ / 128, 8, B_), 256, CV_SMEM>>>(conv_b);
    // fc1 (M=512, N=1024, K=512) -> q bf16 (b,l,a)
    fc_gemm<1><<<dim3(L_ / 128, 4, B_), 256, FC_SMEM>>>(fc1_b, we, nullptr);
    // tensor-core attention -> attn output + ctx (b,l,a)
    attn_tc_kernel<<<dim3(L_ / 128, B_), 256, ATTN_SMEM_BYTES>>>(out + OUT_ATTN);
    // fc2 + residuals (M=512, N=1024, K=512)
    fc_gemm<2><<<dim3(L_ / 128, 4, B_), 256, FC_SMEM>>>(fc2_b, x, out);
}

// round 15
// speedup vs baseline: 1.1976x; 1.0825x over previous
#include <cuda_runtime.h>
#include <cuda_bf16.h>
#include <math.h>

// Problem constants
#define B_  16
#define CIN 512
#define L_  1024
#define COUT 1024
#define K_  5
#define DW  512
#define HW  196
#define KCONV (CIN * K_)   // 2560
#define PP  224            // padded p dimension

// Output layout (concatenated tuple): out, word_embed, img_conv, attn
#define OUT_WE   8388608u
#define OUT_IMG  16777216u
#define OUT_ATTN 18382848u

typedef __nv_bfloat16 bf16;

// ---------------------------------------------------------------------------
// Scratch (device globals; allocation-free rule)
// ---------------------------------------------------------------------------
__device__ float g_w[COUT * KCONV];            // normalized conv weights (co, c, t)
__device__ bf16 g_xTh[B_ * L_ * CIN], g_xTl[B_ * L_ * CIN];   // x^T split (b, l, c)
__device__ bf16 g_cwp[8 * 80 * 8192];          // conv W fragment-packed tiles (16KB)
__device__ bf16 g_w1p[4 * 16 * 8192];          // fc1 W fragment-packed tiles (16KB)
__device__ bf16 g_w2p[4 * 16 * 8192];          // fc2 W fragment-packed tiles (16KB)
__device__ bf16 g_hTh[B_ * L_ * DW], g_hTl[B_ * L_ * DW];     // h split (b, l, c)
__device__ bf16 g_qh[B_ * L_ * DW],  g_ql[B_ * L_ * DW];      // q split (b, l, a)
__device__ bf16 g_cxh[B_ * L_ * DW], g_cxl[B_ * L_ * DW];     // ctx split (b, l, a)
__device__ bf16 g_fTh[B_ * PP * DW], g_fTl[B_ * PP * DW];     // feat^T split (b, p, a)
__device__ bf16 g_fh[B_ * DW * PP],  g_fl[B_ * DW * PP];      // feat split (b, a, p)

__device__ __forceinline__ void split2(float v, bf16& h, bf16& l) {
    h = __float2bfloat16(v);
    l = __float2bfloat16(v - __bfloat162float(h));
}

// ---- async copy primitives ----
__device__ __forceinline__ void cp16(void* dst, const void* src) {
    unsigned d = (unsigned)__cvta_generic_to_shared(dst);
    asm volatile("cp.async.cg.shared.global [%0], [%1], 16;\n" :: "r"(d), "l"(src));
}
#define CP_COMMIT() asm volatile("cp.async.commit_group;\n")
#define CP_WAIT0()  asm volatile("cp.async.wait_group 0;\n")

#define MBAR_INIT(addr, cnt) \
    asm volatile("mbarrier.init.shared.b64 [%0], %1;" :: "r"(addr), "r"(cnt) : "memory")
#define MBAR_EXPECT(addr, tx) \
    asm volatile("mbarrier.arrive.expect_tx.shared.b64 _, [%0], %1;" :: "r"(addr), "r"(tx) : "memory")

__device__ __forceinline__ void mbar_wait(unsigned mbar, unsigned parity) {
    asm volatile(
        "{\n\t.reg .pred P;\n\t"
        "W_%=:\n\t"
        "mbarrier.try_wait.parity.acquire.cta.shared::cta.b64 P, [%0], %1;\n\t"
        "@!P bra W_%=;\n\t}"
        :: "r"(mbar), "r"(parity) : "memory");
}

__device__ __forceinline__ void bulk_g2s(unsigned dst_smem, const void* src,
                                         unsigned bytes, unsigned mbar) {
    asm volatile(
        "cp.async.bulk.shared::cluster.global.mbarrier::complete_tx::bytes "
        "[%0], [%1], %2, [%3];"
        :: "r"(dst_smem), "l"(src), "r"(bytes), "r"(mbar) : "memory");
}

// ---------------------------------------------------------------------------
// Prep kernels
// ---------------------------------------------------------------------------
__global__ void wnorm_kernel(const float* __restrict__ v,
                             const float* __restrict__ g) {
    int co = blockIdx.x;
    const float* vr = v + (size_t)co * KCONV;
    float s = 0.f;
    for (int i = threadIdx.x; i < KCONV; i += 256) { float t = vr[i]; s += t * t; }
    __shared__ float red[256];
    red[threadIdx.x] = s;
    __syncthreads();
    for (int st = 128; st > 0; st >>= 1) {
        if (threadIdx.x < st) red[threadIdx.x] += red[threadIdx.x + st];
        __syncthreads();
    }
    float scale = g[co] / sqrtf(red[0]);
    float* wr = g_w + (size_t)co * KCONV;
    for (int i = threadIdx.x; i < KCONV; i += 256) wr[i] = scale * vr[i];
}

// Fragment-order pack layout (tile = 1024 16B-chunks = 16KB):
//   chunk u: lane=u&31, mt=(u>>5)&1, wm=(u>>6)&3, ks=(u>>8)&1, plane=(u>>9)&1
//   4 words w: row = wm*32+mt*16+(lane>>2)+((w&1)?8:0)
//              k   = ks*16+(lane&3)*2+(w>>1)*8   (2 bf16: k, k+1)

// conv: tile (mb, kc), kc = t*16 + ci; element k maps to c = ci*32 + k
__global__ void pack_conv_kernel() {
    const int kc = blockIdx.x, mb = blockIdx.y;
    const int t = kc / 16, ci = kc % 16;
    bf16* dst = g_cwp + (size_t)(mb * 80 + kc) * 8192;
    for (int u = threadIdx.x; u < 1024; u += 256) {
        int lane2 = u & 31, mt = (u >> 5) & 1, wm2 = (u >> 6) & 3;
        int ks = (u >> 8) & 1, plane = (u >> 9) & 1;
        int row0 = wm2 * 32 + mt * 16 + (lane2 >> 2);
        int kb = ks * 16 + (lane2 & 3) * 2;
        unsigned words[4];
#pragma unroll
        for (int w = 0; w < 4; w++) {
            int row = row0 + ((w & 1) ? 8 : 0);
            int k = kb + (w >> 1) * 8;
            int m = mb * 128 + row;
            int co = (m & 1) ? (512 + (m >> 1)) : (m >> 1);
            unsigned short p0, p1;
#pragma unroll
            for (int e = 0; e < 2; e++) {
                int c = ci * 32 + k + e;
                float v = g_w[(size_t)co * KCONV + c * K_ + t];
                bf16 hi, lo; split2(v, hi, lo);
                bf16 sel = plane ? lo : hi;
                unsigned short us = *(unsigned short*)&sel;
                if (e == 0) p0 = us; else p1 = us;
            }
            words[w] = (unsigned)p0 | ((unsigned)p1 << 16);
        }
        *(uint4*)(dst + u * 8) = make_uint4(words[0], words[1], words[2], words[3]);
    }
}

// fc pack (both W1 and W2 in one launch): blockIdx.z in [0,8): z>=4 -> W2
__global__ void pack_fc_kernel(const float* __restrict__ W1, const float* __restrict__ W2,
                               bf16* __restrict__ d1, bf16* __restrict__ d2) {
    const int kc = blockIdx.x, mb = blockIdx.y;
    const int zsel = blockIdx.z >> 2, zz = blockIdx.z & 3;
    const float* W = zsel ? W2 : W1;
    bf16* dst = (zsel ? d2 : d1) + (size_t)(mb * 16 + kc) * 8192;
    int u = zz * 256 + threadIdx.x;
    {
        int lane2 = u & 31, mt = (u >> 5) & 1, wm2 = (u >> 6) & 3;
        int ks = (u >> 8) & 1, plane = (u >> 9) & 1;
        int row0 = wm2 * 32 + mt * 16 + (lane2 >> 2);
        int kb = ks * 16 + (lane2 & 3) * 2;
        unsigned words[4];
#pragma unroll
        for (int w = 0; w < 4; w++) {
            int row = row0 + ((w & 1) ? 8 : 0);
            int k = kb + (w >> 1) * 8;
            unsigned short p0, p1;
#pragma unroll
            for (int e = 0; e < 2; e++) {
                float v = W[(size_t)(mb * 128 + row) * 512 + kc * 32 + k + e];
                bf16 hi, lo; split2(v, hi, lo);
                bf16 sel = plane ? lo : hi;
                unsigned short us = *(unsigned short*)&sel;
                if (e == 0) p0 = us; else p1 = us;
            }
            words[w] = (unsigned)p0 | ((unsigned)p1 << 16);
        }
        *(uint4*)(dst + u * 8) = make_uint4(words[0], words[1], words[2], words[3]);
    }
}

// x (b,c,l) -> xT split (b,l,c)
__global__ void xT_kernel(const float* __restrict__ x) {
    __shared__ float t[32][33];
    const int b = blockIdx.z, l0 = blockIdx.x * 32, c0 = blockIdx.y * 32;
    const int tx = threadIdx.x, ty0 = threadIdx.y;
#pragma unroll
    for (int j = 0; j < 4; j++) {
        int ty = ty0 + j * 8;
        t[ty][tx] = x[((size_t)b * CIN + c0 + ty) * L_ + l0 + tx];
    }
    __syncthreads();
#pragma unroll
    for (int j = 0; j < 4; j++) {
        int ty = ty0 + j * 8;
        float v = t[tx][ty];
        bf16 hi, lo; split2(v, hi, lo);
        size_t off = ((size_t)b * L_ + l0 + ty) * 512 + c0 + tx;
        g_xTh[off] = hi; g_xTl[off] = lo;
    }
}

// feat^T split (b, p, a) AND feat pad split (b, a, PP); p>=196 zero.
__global__ void featT_kernel(const float* __restrict__ img) {
    __shared__ float t[32][33];
    const int b = blockIdx.z, p0 = blockIdx.x * 32, a0 = blockIdx.y * 32;
    const int tx = threadIdx.x, ty0 = threadIdx.y;
#pragma unroll
    for (int j = 0; j < 4; j++) {
        int ty = ty0 + j * 8;
        int a = a0 + ty, p = p0 + tx;
        float v = (p < HW) ? img[((size_t)b * 512 + a) * HW + p] : 0.f;
        t[ty][tx] = v;
        bf16 hi, lo; split2(v, hi, lo);
        size_t offf = ((size_t)b * 512 + a) * PP + p;
        g_fh[offf] = hi; g_fl[offf] = lo;
    }
    __syncthreads();
#pragma unroll
    for (int j = 0; j < 4; j++) {
        int ty = ty0 + j * 8;
        float v = t[tx][ty];
        bf16 hi, lo; split2(v, hi, lo);
        size_t off = ((size_t)b * PP + p0 + ty) * 512 + a0 + tx;
        g_fTh[off] = hi; g_fTl[off] = lo;
    }
}

// ---------------------------------------------------------------------------
// MMA helper
// ---------------------------------------------------------------------------
__device__ __forceinline__ void mma_bf16(float* c, const unsigned* a,
                                         unsigned b0, unsigned b1) {
    asm volatile(
        "mma.sync.aligned.m16n8k16.row.col.f32.bf16.bf16.f32 "
        "{%0,%1,%2,%3}, {%4,%5,%6,%7}, {%8,%9}, {%0,%1,%2,%3};\n"
        : "+f"(c[0]), "+f"(c[1]), "+f"(c[2]), "+f"(c[3])
        : "r"(a[0]), "r"(a[1]), "r"(a[2]), "r"(a[3]), "r"(b0), "r"(b1));
}

#define APAD 40
#define BK 32

// ---------------------------------------------------------------------------
// Conv GEMM. Tile 128m x 128n, 2 CTA/SM, 8 warps (wm 4 x wn 2), 2mt x 8nt.
//   smem: A 2x16384 @0 ; B 2x21760 @32768 ; mbar @76288
// ---------------------------------------------------------------------------
#define CV_A_STAGE 16384
#define CV_B_OFF   32768
#define CV_B_STAGE 21760
#define CV_MBAR    76288
#define CV_SMEM    76416

__global__ __launch_bounds__(256, 2) void conv_gemm(const float* __restrict__ bias) {
    extern __shared__ __align__(16) unsigned char dynsm[];
    const int b = blockIdx.z, mb = blockIdx.y, l0 = blockIdx.x * 128;
    const int tid = threadIdx.x;
    const int lane = tid & 31, warp = tid >> 5;
    const int wm = warp >> 1, wn = warp & 1;

    unsigned smem_base = (unsigned)__cvta_generic_to_shared(dynsm);
    unsigned mbar0 = smem_base + CV_MBAR, mbar1 = mbar0 + 8;
    if (tid == 0) { MBAR_INIT(mbar0, 1); MBAR_INIT(mbar1, 1); }
    __syncthreads();

    float acc[2][8][4];
#pragma unroll
    for (int mt = 0; mt < 2; mt++)
#pragma unroll
        for (int nt = 0; nt < 8; nt++)
#pragma unroll
            for (int j = 0; j < 4; j++) acc[mt][nt][j] = 0.f;

    auto issueA = [&](int s, int kc) {
        if (tid == 0) {
            unsigned mbx = s ? mbar1 : mbar0;
            MBAR_EXPECT(mbx, CV_A_STAGE);
            const char* src = (const char*)g_cwp + (size_t)(mb * 80 + kc) * CV_A_STAGE;
            bulk_g2s(smem_base + s * CV_A_STAGE, src, CV_A_STAGE, mbx);
        }
    };
    auto issueB = [&](int sb, int ci) {
        int c0 = ci * 32;
        unsigned char* dst0 = dynsm + CV_B_OFF + sb * CV_B_STAGE;
#pragma unroll
        for (int ii = 0; ii < 5; ii++) {
            int u = ii * 256 + tid;
            if (u < 1056) {
                int plane = (u >= 528) ? 1 : 0;
                int v = u - plane * 528;
                int r = v >> 2, j = v & 3;
                if (!(l0 == 0 && r < 4)) {
                    const bf16* src = (plane ? g_xTl : g_xTh) +
                        ((size_t)b * L_ + l0 - 4 + r) * 512 + c0 + j * 8;
                    cp16(dst0 + plane * 10880 + r * 80 + j * 16, src);
                }
            }
        }
        if (l0 == 0 && tid < 160) {
            int plane = tid / 80, v = tid % 80, r = v / 20, w = v % 20;
            *(unsigned*)(dst0 + plane * 10880 + r * 80 + w * 4) = 0u;
        }
    };

    // prologue
    issueB(0, 0);
    CP_COMMIT();
    issueA(0, 0);
    int ph0 = 0, ph1 = 0;

    for (int i = 0; i < 80; i++) {
        const int ci = i / 5, t = i - ci * 5, s = i & 1;
        if (s == 0) { mbar_wait(mbar0, ph0); ph0 ^= 1; }
        else        { mbar_wait(mbar1, ph1); ph1 ^= 1; }
        if (t == 0) CP_WAIT0();
        __syncthreads();

        if (i + 1 < 80) {
            int ni = i + 1, nci = ni / 5, nt2 = ni - nci * 5;
            issueA(ni & 1, nt2 * 16 + nci);
            if (nt2 == 0) { issueB(nci & 1, nci); CP_COMMIT(); }
        }

        const unsigned char* Ab = dynsm + s * CV_A_STAGE;
        const bf16* Bh = (const bf16*)(dynsm + CV_B_OFF + (ci & 1) * CV_B_STAGE);
        const bf16* Bl = (const bf16*)((const unsigned char*)Bh + 10880);

#pragma unroll
        for (int ks = 0; ks < 2; ks++) {
            unsigned ah[2][4], al[2][4];
#pragma unroll
            for (int mt = 0; mt < 2; mt++) {
                int chunk = (((ks * 4 + wm) * 2 + mt) * 32 + lane) * 16;
                uint4 va = *(const uint4*)(Ab + chunk);
                ah[mt][0] = va.x; ah[mt][1] = va.y; ah[mt][2] = va.z; ah[mt][3] = va.w;
                uint4 vb = *(const uint4*)(Ab + 8192 + chunk);
                al[mt][0] = vb.x; al[mt][1] = vb.y; al[mt][2] = vb.z; al[mt][3] = vb.w;
            }
            const int kb = ks * 16 + (lane & 3) * 2;
#pragma unroll
            for (int nt = 0; nt < 8; nt++) {
                int row = wn * 64 + nt * 8 + (lane >> 2) + t;
                unsigned bh0 = *(const unsigned*)&Bh[row * APAD + kb];
                unsigned bh1 = *(const unsigned*)&Bh[row * APAD + kb + 8];
                unsigned bl0 = *(const unsigned*)&Bl[row * APAD + kb];
                unsigned bl1 = *(const unsigned*)&Bl[row * APAD + kb + 8];
#pragma unroll
                for (int mt = 0; mt < 2; mt++) {
                    mma_bf16(acc[mt][nt], ah[mt], bh0, bh1);
                    mma_bf16(acc[mt][nt], ah[mt], bl0, bl1);
                    mma_bf16(acc[mt][nt], al[mt], bh0, bh1);
                }
            }
        }
    }
    __syncthreads();

    // ---- epilogue: two 64-col passes through Cs[128][65] ----
    float* Cs = (float*)dynsm;
    const int ch0 = mb * 64;
#pragma unroll 1
    for (int p = 0; p < 2; p++) {
        if (wn == p) {
#pragma unroll
            for (int mt = 0; mt < 2; mt++)
#pragma unroll
                for (int nt = 0; nt < 8; nt++) {
                    int r = wm * 32 + mt * 16 + (lane >> 2);
                    int cl = nt * 8 + (lane & 3) * 2;
                    Cs[r * 65 + cl]           = acc[mt][nt][0];
                    Cs[r * 65 + cl + 1]       = acc[mt][nt][1];
                    Cs[(r + 8) * 65 + cl]     = acc[mt][nt][2];
                    Cs[(r + 8) * 65 + cl + 1] = acc[mt][nt][3];
                }
        }
        __syncthreads();
        const int lbase = l0 + p * 64;
        // GLU, stash hv into Cs a-half rows (no fp32 h output anymore)
#pragma unroll
        for (int i = 0; i < 16; i++) {
            int e = i * 256 + tid;
            int chl = e >> 6, ll = e & 63;
            float av = Cs[(chl * 2) * 65 + ll] + __ldg(&bias[ch0 + chl]);
            float bv = Cs[(chl * 2 + 1) * 65 + ll] + __ldg(&bias[512 + ch0 + chl]);
            float hv = av / (1.f + expf(-bv));
            Cs[(chl * 2) * 65 + ll] = hv;
        }
        __syncthreads();
        // transposed bf16 split write (c-fast) -> hT (b,l,c)
#pragma unroll
        for (int i = 0; i < 16; i++) {
            int e = i * 256 + tid;
            int chl = e & 63, ll = e >> 6;
            float hv = Cs[(chl * 2) * 65 + ll];
            bf16 hi, lo; split2(hv, hi, lo);
            size_t off = ((size_t)b * L_ + lbase + ll) * 512 + ch0 + chl;
            g_hTh[off] = hi; g_hTl[off] = lo;
        }
        __syncthreads();
    }
}

// ---------------------------------------------------------------------------
// fc GEMM (MODE 1: fc1, MODE 2: fc2), fragment-order A, single sync/iter.
//   smem: A 2x16384 @0 ; B 2x20480 @32768 ; mbar @73728
// ---------------------------------------------------------------------------
#define FC_A_STAGE 16384
#define FC_B_OFF   32768
#define FC_B_STAGE 20480
#define FC_MBAR    73728
#define FC_SMEM    73856

template <int MODE>
__global__ __launch_bounds__(256, 2) void fc_gemm(
    const float* __restrict__ bias, const float* __restrict__ e1,
    float* __restrict__ outp) {
    extern __shared__ __align__(16) unsigned char dynsm[];
    const int b = blockIdx.z, mb = blockIdx.y, l0 = blockIdx.x * 128;
    const int m0 = mb * 128;
    const int tid = threadIdx.x;
    const int lane = tid & 31, warp = tid >> 5;
    const int wm = warp >> 1, wn = warp & 1;

    const bf16* Wp  = (MODE == 1) ? g_w1p : g_w2p;
    const bf16* Bgh = (MODE == 1) ? g_hTh : g_cxh;   // (b, l, k)
    const bf16* Bgl = (MODE == 1) ? g_hTl : g_cxl;

    unsigned smem_base = (unsigned)__cvta_generic_to_shared(dynsm);
    unsigned mbar0 = smem_base + FC_MBAR, mbar1 = mbar0 + 8;
    if (tid == 0) { MBAR_INIT(mbar0, 1); MBAR_INIT(mbar1, 1); }
    __syncthreads();

    float acc[2][8][4];
#pragma unroll
    for (int mt = 0; mt < 2; mt++)
#pragma unroll
        for (int nt = 0; nt < 8; nt++)
#pragma unroll
            for (int j = 0; j < 4; j++) acc[mt][nt][j] = 0.f;

    auto issueA = [&](int s, int kc) {
        if (tid == 0) {
            unsigned mbx = s ? mbar1 : mbar0;
            MBAR_EXPECT(mbx, FC_A_STAGE);
            const char* src = (const char*)Wp + (size_t)(mb * 16 + kc) * FC_A_STAGE;
            bulk_g2s(smem_base + s * FC_A_STAGE, src, FC_A_STAGE, mbx);
        }
    };
    auto issueB = [&](int s, int kc) {
        unsigned char* dst0 = dynsm + FC_B_OFF + s * FC_B_STAGE;
#pragma unroll
        for (int ii = 0; ii < 4; ii++) {
            int u = ii * 256 + tid;
            int plane = u >> 9, v = u & 511;
            int r = v >> 2, j = v & 3;
            const bf16* src = (plane ? Bgl : Bgh) +
                ((size_t)b * L_ + l0 + r) * 512 + kc * 32 + j * 8;
            cp16(dst0 + plane * 10240 + r * 80 + j * 16, src);
        }
    };

    issueA(0, 0);
    issueB(0, 0);
    CP_COMMIT();
    int ph0 = 0, ph1 = 0;

    for (int i = 0; i < 16; i++) {
        const int s = i & 1;
        if (s == 0) { mbar_wait(mbar0, ph0); ph0 ^= 1; }
        else        { mbar_wait(mbar1, ph1); ph1 ^= 1; }
        CP_WAIT0();
        __syncthreads();

        if (i < 15) {
            issueA(s ^ 1, i + 1);
            issueB(s ^ 1, i + 1);
            CP_COMMIT();
        }

        const unsigned char* Ab = dynsm + s * FC_A_STAGE;
        const bf16* Bh = (const bf16*)(dynsm + FC_B_OFF + s * FC_B_STAGE);
        const bf16* Bl = (const bf16*)((const unsigned char*)Bh + 10240);

#pragma unroll
        for (int ks = 0; ks < 2; ks++) {
            unsigned ah[2][4], al[2][4];
#pragma unroll
            for (int mt = 0; mt < 2; mt++) {
                int chunk = (((ks * 4 + wm) * 2 + mt) * 32 + lane) * 16;
                uint4 va = *(const uint4*)(Ab + chunk);
                ah[mt][0] = va.x; ah[mt][1] = va.y; ah[mt][2] = va.z; ah[mt][3] = va.w;
                uint4 vb = *(const uint4*)(Ab + 8192 + chunk);
                al[mt][0] = vb.x; al[mt][1] = vb.y; al[mt][2] = vb.z; al[mt][3] = vb.w;
            }
            const int kb = ks * 16 + (lane & 3) * 2;
#pragma unroll
            for (int nt = 0; nt < 8; nt++) {
                int col = wn * 64 + nt * 8 + (lane >> 2);
                unsigned bh0 = *(const unsigned*)&Bh[col * APAD + kb];
                unsigned bh1 = *(const unsigned*)&Bh[col * APAD + kb + 8];
                unsigned bl0 = *(const unsigned*)&Bl[col * APAD + kb];
                unsigned bl1 = *(const unsigned*)&Bl[col * APAD + kb + 8];
#pragma unroll
                for (int mt = 0; mt < 2; mt++) {
                    mma_bf16(acc[mt][nt], ah[mt], bh0, bh1);
                    mma_bf16(acc[mt][nt], ah[mt], bl0, bl1);
                    mma_bf16(acc[mt][nt], al[mt], bh0, bh1);
                }
            }
        }
    }
    __syncthreads();

    // ---- epilogue ----
    float* Cs = (float*)dynsm;
#pragma unroll 1
    for (int p = 0; p < 2; p++) {
        if (wn == p) {
#pragma unroll
            for (int mt = 0; mt < 2; mt++)
#pragma unroll
                for (int nt = 0; nt < 8; nt++) {
                    int r = wm * 32 + mt * 16 + (lane >> 2);
                    int cl = nt * 8 + (lane & 3) * 2;
                    Cs[r * 65 + cl]           = acc[mt][nt][0];
                    Cs[r * 65 + cl + 1]       = acc[mt][nt][1];
                    Cs[(r + 8) * 65 + cl]     = acc[mt][nt][2];
                    Cs[(r + 8) * 65 + cl + 1] = acc[mt][nt][3];
                }
        }
        __syncthreads();
        const int lbase = l0 + p * 64;
        if (MODE == 1) {
#pragma unroll
            for (int i = 0; i < 32; i++) {
                int e = i * 256 + tid;
                int a = e & 127, ll = e >> 7;
                Cs[a * 65 + ll] += __ldg(&bias[m0 + a]) +
                    e1[((size_t)b * L_ + lbase + ll) * 512 + m0 + a];
            }
            __syncthreads();
#pragma unroll
            for (int i = 0; i < 32; i++) {
                int e = i * 256 + tid;
                int a = e & 127, ll = e >> 7;
                float v = Cs[a * 65 + ll];
                bf16 hi, lo; split2(v, hi, lo);
                size_t off = ((size_t)b * L_ + lbase + ll) * 512 + m0 + a;
                g_qh[off] = hi; g_ql[off] = lo;
            }
        } else {
            // pass A (c-fast, coalesced hT reads): Cs += b2 + (hTh + hTl)
#pragma unroll
            for (int i = 0; i < 32; i++) {
                int e = i * 256 + tid;
                int c = e & 127, ll = e >> 7;
                size_t hoff = ((size_t)b * L_ + lbase + ll) * 512 + m0 + c;
                Cs[c * 65 + ll] += __ldg(&bias[m0 + c]) +
                    __bfloat162float(g_hTh[hoff]) + __bfloat162float(g_hTl[hoff]);
            }
            __syncthreads();
            // pass B (l-fast, coalesced out/x): out = Cs + x
#pragma unroll
            for (int i = 0; i < 32; i++) {
                int e = i * 256 + tid;
                int cl_ = e >> 6, ll = e & 63;
                size_t off = ((size_t)b * 512 + m0 + cl_) * L_ + lbase + ll;
                outp[off] = Cs[cl_ * 65 + ll] + e1[off];
            }
        }
        __syncthreads();
    }
}

// ---------------------------------------------------------------------------
// Tensor-core attention (R15): phase S double-buffered cp.async staging,
// stage buffers alias the score region (scores materialize after the k-loop).
// Softmax writes probs in place as bf16 hi/lo planes inside each row's 904B
// footprint (hi @ +0, lo @ +452). Phase C: Bc via cp16, pitch 232 elems.
// smem: stages 2x56320 @0 (phase S) | ss [128][226] fp32 @0 (115712)
//       Bc_h @115712 (29696), Bc_l @145408 (29696), Cs [128][65] @175104 (33280)
// ---------------------------------------------------------------------------
#define SSP 226
#define SS_ROW 904
#define ATTN_STAGE 56320
#define ATTN_BC_H 115712
#define ATTN_BC_L 145408
#define ATTN_CS   175104
#define ATTN_SMEM_BYTES 208384
#define BCP 232   // Bc pitch in bf16 elems (464B rows)

__global__ __launch_bounds__(256, 1) void attn_tc_kernel(float* __restrict__ attn_out) {
    extern __shared__ __align__(16) unsigned char dynsm[];
    const int b  = blockIdx.y;
    const int l0 = blockIdx.x * 128;
    const int tid = threadIdx.x;
    const int lane = tid & 31, warp = tid >> 5;
    const int wm = warp >> 1, wn = warp & 1;

    // ================= Phase S: score GEMM, cp.async double-buffered ========
    float acc[2][14][4];
#pragma unroll
    for (int mt = 0; mt < 2; mt++)
#pragma unroll
        for (int nt = 0; nt < 14; nt++)
#pragma unroll
            for (int j = 0; j < 4; j++) acc[mt][nt][j] = 0.f;

    auto issueS = [&](int s, int k0) {
        unsigned char* st = dynsm + s * ATTN_STAGE;
#pragma unroll
        for (int ii = 0; ii < 11; ii++) {
            int u = ii * 256 + tid;
            if (u < 1024) {
                int plane = (u >= 512) ? 1 : 0;
                int v = u - plane * 512;
                int row = v >> 2, j = v & 3;
                const bf16* src = (plane ? g_ql : g_qh) +
                    ((size_t)b * L_ + l0 + row) * 512 + k0 + j * 8;
                cp16(st + plane * 10240 + row * 80 + j * 16, src);
            } else {
                int w = u - 1024;              // < 1792
                int plane = (w >= 896) ? 1 : 0;
                int v = w - plane * 896;
                int row = v >> 2, j = v & 3;
                const bf16* src = (plane ? g_fTl : g_fTh) +
                    ((size_t)b * PP + row) * 512 + k0 + j * 8;
                cp16(st + 20480 + plane * 17920 + row * 80 + j * 16, src);
            }
        }
    };

    issueS(0, 0);
    CP_COMMIT();

    for (int it = 0; it < 16; it++) {
        CP_WAIT0();
        __syncthreads();
        if (it < 15) { issueS((it + 1) & 1, (it + 1) * 32); CP_COMMIT(); }

        const unsigned char* st = dynsm + (it & 1) * ATTN_STAGE;
        const bf16* As_h = (const bf16*)st;
        const bf16* As_l = (const bf16*)(st + 10240);
        const bf16* Bs_h = (const bf16*)(st + 20480);
        const bf16* Bs_l = (const bf16*)(st + 38400);

#pragma unroll
        for (int ks = 0; ks < BK; ks += 16) {
            const int kb = ks + (lane & 3) * 2;
            unsigned ah[2][4], al[2][4];
#pragma unroll
            for (int mt = 0; mt < 2; mt++) {
                int rb = wm * 32 + mt * 16 + (lane >> 2);
                ah[mt][0] = *(const unsigned*)&As_h[rb * APAD + kb];
                ah[mt][1] = *(const unsigned*)&As_h[(rb + 8) * APAD + kb];
                ah[mt][2] = *(const unsigned*)&As_h[rb * APAD + kb + 8];
                ah[mt][3] = *(const unsigned*)&As_h[(rb + 8) * APAD + kb + 8];
                al[mt][0] = *(const unsigned*)&As_l[rb * APAD + kb];
                al[mt][1] = *(const unsigned*)&As_l[(rb + 8) * APAD + kb];
                al[mt][2] = *(const unsigned*)&As_l[rb * APAD + kb + 8];
                al[mt][3] = *(const unsigned*)&As_l[(rb + 8) * APAD + kb + 8];
            }
#pragma unroll
            for (int nt = 0; nt < 14; nt++) {
                int col = wn * 112 + nt * 8 + (lane >> 2);
                unsigned bh0 = *(const unsigned*)&Bs_h[col * APAD + kb];
                unsigned bh1 = *(const unsigned*)&Bs_h[col * APAD + kb + 8];
                unsigned bl0 = *(const unsigned*)&Bs_l[col * APAD + kb];
                unsigned bl1 = *(const unsigned*)&Bs_l[col * APAD + kb + 8];
#pragma unroll
                for (int mt = 0; mt < 2; mt++) {
                    mma_bf16(acc[mt][nt], ah[mt], bh0, bh1);
                    mma_bf16(acc[mt][nt], ah[mt], bl0, bl1);
                    mma_bf16(acc[mt][nt], al[mt], bh0, bh1);
                }
            }
        }
    }
    __syncthreads();   // stage buffers dead; ss region becomes live

    // scatter scores to ss [128][SSP] fp32
    float* ss = (float*)dynsm;
#pragma unroll
    for (int mt = 0; mt < 2; mt++)
#pragma unroll
        for (int nt = 0; nt < 14; nt++) {
            int r = wm * 32 + mt * 16 + (lane >> 2);
            int cl = wn * 112 + nt * 8 + (lane & 3) * 2;
            ss[r * SSP + cl]           = acc[mt][nt][0];
            ss[r * SSP + cl + 1]       = acc[mt][nt][1];
            ss[(r + 8) * SSP + cl]     = acc[mt][nt][2];
            ss[(r + 8) * SSP + cl + 1] = acc[mt][nt][3];
        }
    __syncthreads();

    // ===== Softmax: reads fp32 row, writes attn_out + in-place bf16 planes =====
    for (int r = 0; r < 16; r++) {
        int row = warp * 16 + r;
        float v[7];
        float mx = -1e30f;
#pragma unroll
        for (int k = 0; k < 7; k++) {
            int p = lane + 32 * k;
            v[k] = (p < HW) ? ss[row * SSP + p] : -1e30f;
            mx = fmaxf(mx, v[k]);
        }
#pragma unroll
        for (int off = 16; off > 0; off >>= 1)
            mx = fmaxf(mx, __shfl_xor_sync(0xffffffffu, mx, off));
        float s = 0.f;
#pragma unroll
        for (int k = 0; k < 7; k++) {
            int p = lane + 32 * k;
            if (p < HW) { v[k] = expf(v[k] - mx); s += v[k]; }
        }
#pragma unroll
        for (int off = 16; off > 0; off >>= 1)
            s += __shfl_xor_sync(0xffffffffu, s, off);
        float inv = 1.f / s;
        float* ao = attn_out + ((size_t)b * L_ + l0 + row) * HW;
        bf16* rh = (bf16*)(dynsm + (size_t)row * SS_ROW);
        bf16* rl = (bf16*)(dynsm + (size_t)row * SS_ROW + 452);
        const bf16 z = __float2bfloat16(0.f);
#pragma unroll
        for (int k = 0; k < 7; k++) {
            int p = lane + 32 * k;
            if (p < HW) {
                float a = v[k] * inv;
                ao[p] = a;
                bf16 hi, lo; split2(a, hi, lo);
                rh[p] = hi; rl[p] = lo;
            } else {
                rh[p] = z; rl[p] = z;
            }
        }
    }
    __syncthreads();

    // ================= Phase C: ctx GEMM (fragments from bf16 planes) =========
    bf16* Bc_h = (bf16*)(dynsm + ATTN_BC_H);
    bf16* Bc_l = (bf16*)(dynsm + ATTN_BC_L);
    float* Cs  = (float*)(dynsm + ATTN_CS);

#pragma unroll 1
    for (int a0 = 0; a0 < 512; a0 += 64) {
        // stage Bc [64 a][224 p] hi/lo via cp16 (pitch BCP=232 elems / 464B)
#pragma unroll
        for (int ii = 0; ii < 14; ii++) {
            int u = ii * 256 + tid;
            int plane = (u >= 1792) ? 1 : 0;
            int v = u - plane * 1792;
            int row = v / 28, j = v - row * 28;
            const bf16* src = (plane ? g_fl : g_fh) +
                ((size_t)b * 512 + a0 + row) * PP + j * 8;
            bf16* dstp = plane ? Bc_l : Bc_h;
            cp16((unsigned char*)dstp + row * 464 + j * 16, src);
        }
        CP_COMMIT();
        CP_WAIT0();
        __syncthreads();

        float ac2[2][4][4];
#pragma unroll
        for (int mt = 0; mt < 2; mt++)
#pragma unroll
            for (int nt = 0; nt < 4; nt++)
#pragma unroll
                for (int j = 0; j < 4; j++) ac2[mt][nt][j] = 0.f;

#pragma unroll 2
        for (int p0 = 0; p0 < PP; p0 += 16) {
            const int kb = p0 + (lane & 3) * 2;
            unsigned ah[2][4], al[2][4];
#pragma unroll
            for (int mt = 0; mt < 2; mt++) {
                int rb = wm * 32 + mt * 16 + (lane >> 2);
#pragma unroll
                for (int f = 0; f < 4; f++) {
                    int rr = rb + ((f & 1) ? 8 : 0);
                    int cc = kb + ((f & 2) ? 8 : 0);
                    ah[mt][f] = *(const unsigned*)(dynsm + (size_t)rr * SS_ROW + cc * 2);
                    al[mt][f] = *(const unsigned*)(dynsm + (size_t)rr * SS_ROW + 452 + cc * 2);
                }
            }
#pragma unroll
            for (int nt = 0; nt < 4; nt++) {
                int col = wn * 32 + nt * 8 + (lane >> 2);
                unsigned bh0 = *(const unsigned*)&Bc_h[col * BCP + kb];
                unsigned bh1 = *(const unsigned*)&Bc_h[col * BCP + kb + 8];
                unsigned bl0 = *(const unsigned*)&Bc_l[col * BCP + kb];
                unsigned bl1 = *(const unsigned*)&Bc_l[col * BCP + kb + 8];
#pragma unroll
                for (int mt = 0; mt < 2; mt++) {
                    mma_bf16(ac2[mt][nt], ah[mt], bh0, bh1);
                    mma_bf16(ac2[mt][nt], ah[mt], bl0, bl1);
                    mma_bf16(ac2[mt][nt], al[mt], bh0, bh1);
                }
            }
        }

#pragma unroll
        for (int mt = 0; mt < 2; mt++)
#pragma unroll
            for (int nt = 0; nt < 4; nt++) {
                int r = wm * 32 + mt * 16 + (lane >> 2);
                int cl = wn * 32 + nt * 8 + (lane & 3) * 2;
                Cs[r * 65 + cl]           = ac2[mt][nt][0];
                Cs[r * 65 + cl + 1]       = ac2[mt][nt][1];
                Cs[(r + 8) * 65 + cl]     = ac2[mt][nt][2];
                Cs[(r + 8) * 65 + cl + 1] = ac2[mt][nt][3];
            }
        __syncthreads();

        // write ctx split bf16, layout (b, l, a), coalesced over a
#pragma unroll
        for (int i = 0; i < 32; i++) {
            int e = i * 256 + tid;
            int a = e & 63, l = e >> 6;
            float v = Cs[l * 65 + a];
            bf16 hi, lo; split2(v, hi, lo);
            size_t off = ((size_t)b * L_ + l0 + l) * 512 + a0 + a;
            g_cxh[off] = hi; g_cxl[off] = lo;
        }
        __syncthreads();
    }
}

// ---------------------------------------------------------------------------
extern "C" void kernel_launch(void* const* d_in, const int* in_sizes, int n_in,
                              void* d_out, int out_size) {
    (void)in_sizes; (void)n_in; (void)out_size;
    const float* x      = (const float*)d_in[0];
    const float* we     = (const float*)d_in[1];
    const float* img    = (const float*)d_in[2];
    /* d_in[3] prev_attn unused */
    const float* conv_v = (const float*)d_in[4];
    const float* conv_g = (const float*)d_in[5];
    const float* conv_b = (const float*)d_in[6];
    const float* fc1_w  = (const float*)d_in[7];
    const float* fc1_b  = (const float*)d_in[8];
    const float* fc2_w  = (const float*)d_in[9];
    const float* fc2_b  = (const float*)d_in[10];
    float* out = (float*)d_out;

    // passthrough copies
    cudaMemcpyAsync(out + OUT_WE, we, (size_t)B_ * L_ * DW * sizeof(float),
                    cudaMemcpyDeviceToDevice, 0);
    cudaMemcpyAsync(out + OUT_IMG, img, (size_t)B_ * DW * HW * sizeof(float),
                    cudaMemcpyDeviceToDevice, 0);

    void *p_w1p, *p_w2p;
    cudaGetSymbolAddress(&p_w1p, g_w1p);
    cudaGetSymbolAddress(&p_w2p, g_w2p);

    // prep
    wnorm_kernel<<<COUT, 256>>>(conv_v, conv_g);
    pack_conv_kernel<<<dim3(80, 8), 256>>>();
    pack_fc_kernel<<<dim3(16, 4, 8), 256>>>(fc1_w, fc2_w, (bf16*)p_w1p, (bf16*)p_w2p);
    xT_kernel<<<dim3(L_ / 32, CIN / 32, B_), dim3(32, 8)>>>(x);
    featT_kernel<<<dim3(PP / 32, 512 / 32, B_), dim3(32, 8)>>>(img);

    // opt-in dynamic smem
    cudaFuncSetAttribute(conv_gemm, cudaFuncAttributeMaxDynamicSharedMemorySize, CV_SMEM);
    cudaFuncSetAttribute(fc_gemm<1>, cudaFuncAttributeMaxDynamicSharedMemorySize, FC_SMEM);
    cudaFuncSetAttribute(fc_gemm<2>, cudaFuncAttributeMaxDynamicSharedMemorySize, FC_SMEM);
    cudaFuncSetAttribute(attn_tc_kernel, cudaFuncAttributeMaxDynamicSharedMemorySize,
                         ATTN_SMEM_BYTES);

    // conv + GLU  (M=1024 interleaved, N=1024, K=2560), tile 128x128
    conv_gemm<<<dim3(L_ / 128, 8, B_), 256, CV_SMEM>>>(conv_b);
    // fc1 (M=512, N=1024, K=512) -> q bf16 (b,l,a)
    fc_gemm<1><<<dim3(L_ / 128, 4, B_), 256, FC_SMEM>>>(fc1_b, we, nullptr);
    // tensor-core attention -> attn output + ctx (b,l,a)
    attn_tc_kernel<<<dim3(L_ / 128, B_), 256, ATTN_SMEM_BYTES>>>(out + OUT_ATTN);
    // fc2 + residuals (M=512, N=1024, K=512)
    fc_gemm<2><<<dim3(L_ / 128, 4, B_), 256, FC_SMEM>>>(fc2_b, x, out);
}

// round 16
// speedup vs baseline: 1.1977x; 1.0001x over previous
#include <cuda_runtime.h>
#include <cuda_bf16.h>
#include <math.h>

// Problem constants
#define B_  16
#define CIN 512
#define L_  1024
#define COUT 1024
#define K_  5
#define DW  512
#define HW  196
#define KCONV (CIN * K_)   // 2560
#define PP  224            // padded p dimension

// Output layout (concatenated tuple): out, word_embed, img_conv, attn
#define OUT_WE   8388608u
#define OUT_IMG  16777216u
#define OUT_ATTN 18382848u

typedef __nv_bfloat16 bf16;

// ---------------------------------------------------------------------------
// Scratch (device globals; allocation-free rule)
// ---------------------------------------------------------------------------
__device__ float g_w[COUT * KCONV];            // normalized conv weights (co, c, t)
__device__ bf16 g_xTh[B_ * L_ * CIN], g_xTl[B_ * L_ * CIN];   // x^T split (b, l, c)
__device__ bf16 g_cwp[8 * 80 * 8192];          // conv W fragment-packed tiles (16KB)
__device__ bf16 g_w1p[4 * 16 * 8192];          // fc1 W fragment-packed tiles (16KB)
__device__ bf16 g_w2p[4 * 16 * 8192];          // fc2 W fragment-packed tiles (16KB)
__device__ bf16 g_hTh[B_ * L_ * DW], g_hTl[B_ * L_ * DW];     // h split (b, l, c)
__device__ bf16 g_qh[B_ * L_ * DW],  g_ql[B_ * L_ * DW];      // q split (b, l, a)
__device__ bf16 g_cxh[B_ * L_ * DW], g_cxl[B_ * L_ * DW];     // ctx split (b, l, a)
__device__ bf16 g_fTh[B_ * PP * DW], g_fTl[B_ * PP * DW];     // feat^T split (b, p, a)
__device__ bf16 g_fh[B_ * DW * PP],  g_fl[B_ * DW * PP];      // feat split (b, a, p)

__device__ __forceinline__ void split2(float v, bf16& h, bf16& l) {
    h = __float2bfloat16(v);
    l = __float2bfloat16(v - __bfloat162float(h));
}

// ---- async copy primitives ----
__device__ __forceinline__ void cp16(void* dst, const void* src) {
    unsigned d = (unsigned)__cvta_generic_to_shared(dst);
    asm volatile("cp.async.cg.shared.global [%0], [%1], 16;\n" :: "r"(d), "l"(src));
}
#define CP_COMMIT() asm volatile("cp.async.commit_group;\n")
#define CP_WAIT0()  asm volatile("cp.async.wait_group 0;\n")

#define MBAR_INIT(addr, cnt) \
    asm volatile("mbarrier.init.shared.b64 [%0], %1;" :: "r"(addr), "r"(cnt) : "memory")
#define MBAR_EXPECT(addr, tx) \
    asm volatile("mbarrier.arrive.expect_tx.shared.b64 _, [%0], %1;" :: "r"(addr), "r"(tx) : "memory")

__device__ __forceinline__ void mbar_wait(unsigned mbar, unsigned parity) {
    asm volatile(
        "{\n\t.reg .pred P;\n\t"
        "W_%=:\n\t"
        "mbarrier.try_wait.parity.acquire.cta.shared::cta.b64 P, [%0], %1;\n\t"
        "@!P bra W_%=;\n\t}"
        :: "r"(mbar), "r"(parity) : "memory");
}

__device__ __forceinline__ void bulk_g2s(unsigned dst_smem, const void* src,
                                         unsigned bytes, unsigned mbar) {
    asm volatile(
        "cp.async.bulk.shared::cluster.global.mbarrier::complete_tx::bytes "
        "[%0], [%1], %2, [%3];"
        :: "r"(dst_smem), "l"(src), "r"(bytes), "r"(mbar) : "memory");
}

// ---------------------------------------------------------------------------
// Prep kernels
// ---------------------------------------------------------------------------
__global__ void wnorm_kernel(const float* __restrict__ v,
                             const float* __restrict__ g) {
    int co = blockIdx.x;
    const float* vr = v + (size_t)co * KCONV;
    float s = 0.f;
    for (int i = threadIdx.x; i < KCONV; i += 256) { float t = vr[i]; s += t * t; }
    __shared__ float red[256];
    red[threadIdx.x] = s;
    __syncthreads();
    for (int st = 128; st > 0; st >>= 1) {
        if (threadIdx.x < st) red[threadIdx.x] += red[threadIdx.x + st];
        __syncthreads();
    }
    float scale = g[co] / sqrtf(red[0]);
    float* wr = g_w + (size_t)co * KCONV;
    for (int i = threadIdx.x; i < KCONV; i += 256) wr[i] = scale * vr[i];
}

// Fragment-order pack layout (tile = 1024 16B-chunks = 16KB):
//   chunk u: lane=u&31, mt=(u>>5)&1, wm=(u>>6)&3, ks=(u>>8)&1, plane=(u>>9)&1
//   4 words w: row = wm*32+mt*16+(lane>>2)+((w&1)?8:0)
//              k   = ks*16+(lane&3)*2+(w>>1)*8   (2 bf16: k, k+1)

// conv: tile (mb, kc), kc = t*16 + ci; element k maps to c = ci*32 + k
__global__ void pack_conv_kernel() {
    const int kc = blockIdx.x, mb = blockIdx.y;
    const int t = kc / 16, ci = kc % 16;
    bf16* dst = g_cwp + (size_t)(mb * 80 + kc) * 8192;
    for (int u = threadIdx.x; u < 1024; u += 256) {
        int lane2 = u & 31, mt = (u >> 5) & 1, wm2 = (u >> 6) & 3;
        int ks = (u >> 8) & 1, plane = (u >> 9) & 1;
        int row0 = wm2 * 32 + mt * 16 + (lane2 >> 2);
        int kb = ks * 16 + (lane2 & 3) * 2;
        unsigned words[4];
#pragma unroll
        for (int w = 0; w < 4; w++) {
            int row = row0 + ((w & 1) ? 8 : 0);
            int k = kb + (w >> 1) * 8;
            int m = mb * 128 + row;
            int co = (m & 1) ? (512 + (m >> 1)) : (m >> 1);
            unsigned short p0, p1;
#pragma unroll
            for (int e = 0; e < 2; e++) {
                int c = ci * 32 + k + e;
                float v = g_w[(size_t)co * KCONV + c * K_ + t];
                bf16 hi, lo; split2(v, hi, lo);
                bf16 sel = plane ? lo : hi;
                unsigned short us = *(unsigned short*)&sel;
                if (e == 0) p0 = us; else p1 = us;
            }
            words[w] = (unsigned)p0 | ((unsigned)p1 << 16);
        }
        *(uint4*)(dst + u * 8) = make_uint4(words[0], words[1], words[2], words[3]);
    }
}

// fc pack (both W1 and W2 in one launch): blockIdx.z in [0,8): z>=4 -> W2
__global__ void pack_fc_kernel(const float* __restrict__ W1, const float* __restrict__ W2,
                               bf16* __restrict__ d1, bf16* __restrict__ d2) {
    const int kc = blockIdx.x, mb = blockIdx.y;
    const int zsel = blockIdx.z >> 2, zz = blockIdx.z & 3;
    const float* W = zsel ? W2 : W1;
    bf16* dst = (zsel ? d2 : d1) + (size_t)(mb * 16 + kc) * 8192;
    int u = zz * 256 + threadIdx.x;
    {
        int lane2 = u & 31, mt = (u >> 5) & 1, wm2 = (u >> 6) & 3;
        int ks = (u >> 8) & 1, plane = (u >> 9) & 1;
        int row0 = wm2 * 32 + mt * 16 + (lane2 >> 2);
        int kb = ks * 16 + (lane2 & 3) * 2;
        unsigned words[4];
#pragma unroll
        for (int w = 0; w < 4; w++) {
            int row = row0 + ((w & 1) ? 8 : 0);
            int k = kb + (w >> 1) * 8;
            unsigned short p0, p1;
#pragma unroll
            for (int e = 0; e < 2; e++) {
                float v = W[(size_t)(mb * 128 + row) * 512 + kc * 32 + k + e];
                bf16 hi, lo; split2(v, hi, lo);
                bf16 sel = plane ? lo : hi;
                unsigned short us = *(unsigned short*)&sel;
                if (e == 0) p0 = us; else p1 = us;
            }
            words[w] = (unsigned)p0 | ((unsigned)p1 << 16);
        }
        *(uint4*)(dst + u * 8) = make_uint4(words[0], words[1], words[2], words[3]);
    }
}

// x (b,c,l) -> xT split (b,l,c)
__global__ void xT_kernel(const float* __restrict__ x) {
    __shared__ float t[32][33];
    const int b = blockIdx.z, l0 = blockIdx.x * 32, c0 = blockIdx.y * 32;
    const int tx = threadIdx.x, ty0 = threadIdx.y;
#pragma unroll
    for (int j = 0; j < 4; j++) {
        int ty = ty0 + j * 8;
        t[ty][tx] = x[((size_t)b * CIN + c0 + ty) * L_ + l0 + tx];
    }
    __syncthreads();
#pragma unroll
    for (int j = 0; j < 4; j++) {
        int ty = ty0 + j * 8;
        float v = t[tx][ty];
        bf16 hi, lo; split2(v, hi, lo);
        size_t off = ((size_t)b * L_ + l0 + ty) * 512 + c0 + tx;
        g_xTh[off] = hi; g_xTl[off] = lo;
    }
}

// feat^T split (b, p, a) AND feat pad split (b, a, PP); p>=196 zero.
__global__ void featT_kernel(const float* __restrict__ img) {
    __shared__ float t[32][33];
    const int b = blockIdx.z, p0 = blockIdx.x * 32, a0 = blockIdx.y * 32;
    const int tx = threadIdx.x, ty0 = threadIdx.y;
#pragma unroll
    for (int j = 0; j < 4; j++) {
        int ty = ty0 + j * 8;
        int a = a0 + ty, p = p0 + tx;
        float v = (p < HW) ? img[((size_t)b * 512 + a) * HW + p] : 0.f;
        t[ty][tx] = v;
        bf16 hi, lo; split2(v, hi, lo);
        size_t offf = ((size_t)b * 512 + a) * PP + p;
        g_fh[offf] = hi; g_fl[offf] = lo;
    }
    __syncthreads();
#pragma unroll
    for (int j = 0; j < 4; j++) {
        int ty = ty0 + j * 8;
        float v = t[tx][ty];
        bf16 hi, lo; split2(v, hi, lo);
        size_t off = ((size_t)b * PP + p0 + ty) * 512 + a0 + tx;
        g_fTh[off] = hi; g_fTl[off] = lo;
    }
}

// ---------------------------------------------------------------------------
// MMA helper
// ---------------------------------------------------------------------------
__device__ __forceinline__ void mma_bf16(float* c, const unsigned* a,
                                         unsigned b0, unsigned b1) {
    asm volatile(
        "mma.sync.aligned.m16n8k16.row.col.f32.bf16.bf16.f32 "
        "{%0,%1,%2,%3}, {%4,%5,%6,%7}, {%8,%9}, {%0,%1,%2,%3};\n"
        : "+f"(c[0]), "+f"(c[1]), "+f"(c[2]), "+f"(c[3])
        : "r"(a[0]), "r"(a[1]), "r"(a[2]), "r"(a[3]), "r"(b0), "r"(b1));
}

#define APAD 40
#define BK 32

// ---------------------------------------------------------------------------
// Conv GEMM. Tile 128m x 128n, 2 CTA/SM, 8 warps (wm 4 x wn 2), 2mt x 8nt.
//   smem: A 2x16384 @0 ; B 2x21760 @32768 ; mbar @76288
// ---------------------------------------------------------------------------
#define CV_A_STAGE 16384
#define CV_B_OFF   32768
#define CV_B_STAGE 21760
#define CV_MBAR    76288
#define CV_SMEM    76416

__global__ __launch_bounds__(256, 2) void conv_gemm(const float* __restrict__ bias) {
    extern __shared__ __align__(16) unsigned char dynsm[];
    const int b = blockIdx.z, mb = blockIdx.y, l0 = blockIdx.x * 128;
    const int tid = threadIdx.x;
    const int lane = tid & 31, warp = tid >> 5;
    const int wm = warp >> 1, wn = warp & 1;

    unsigned smem_base = (unsigned)__cvta_generic_to_shared(dynsm);
    unsigned mbar0 = smem_base + CV_MBAR, mbar1 = mbar0 + 8;
    if (tid == 0) { MBAR_INIT(mbar0, 1); MBAR_INIT(mbar1, 1); }
    __syncthreads();

    float acc[2][8][4];
#pragma unroll
    for (int mt = 0; mt < 2; mt++)
#pragma unroll
        for (int nt = 0; nt < 8; nt++)
#pragma unroll
            for (int j = 0; j < 4; j++) acc[mt][nt][j] = 0.f;

    auto issueA = [&](int s, int kc) {
        if (tid == 0) {
            unsigned mbx = s ? mbar1 : mbar0;
            MBAR_EXPECT(mbx, CV_A_STAGE);
            const char* src = (const char*)g_cwp + (size_t)(mb * 80 + kc) * CV_A_STAGE;
            bulk_g2s(smem_base + s * CV_A_STAGE, src, CV_A_STAGE, mbx);
        }
    };
    auto issueB = [&](int sb, int ci) {
        int c0 = ci * 32;
        unsigned char* dst0 = dynsm + CV_B_OFF + sb * CV_B_STAGE;
#pragma unroll
        for (int ii = 0; ii < 5; ii++) {
            int u = ii * 256 + tid;
            if (u < 1056) {
                int plane = (u >= 528) ? 1 : 0;
                int v = u - plane * 528;
                int r = v >> 2, j = v & 3;
                if (!(l0 == 0 && r < 4)) {
                    const bf16* src = (plane ? g_xTl : g_xTh) +
                        ((size_t)b * L_ + l0 - 4 + r) * 512 + c0 + j * 8;
                    cp16(dst0 + plane * 10880 + r * 80 + j * 16, src);
                }
            }
        }
        if (l0 == 0 && tid < 160) {
            int plane = tid / 80, v = tid % 80, r = v / 20, w = v % 20;
            *(unsigned*)(dst0 + plane * 10880 + r * 80 + w * 4) = 0u;
        }
    };

    // prologue
    issueB(0, 0);
    CP_COMMIT();
    issueA(0, 0);
    int ph0 = 0, ph1 = 0;

    for (int i = 0; i < 80; i++) {
        const int ci = i / 5, t = i - ci * 5, s = i & 1;
        if (s == 0) { mbar_wait(mbar0, ph0); ph0 ^= 1; }
        else        { mbar_wait(mbar1, ph1); ph1 ^= 1; }
        if (t == 0) CP_WAIT0();
        __syncthreads();

        if (i + 1 < 80) {
            int ni = i + 1, nci = ni / 5, nt2 = ni - nci * 5;
            issueA(ni & 1, nt2 * 16 + nci);
            if (nt2 == 0) { issueB(nci & 1, nci); CP_COMMIT(); }
        }

        const unsigned char* Ab = dynsm + s * CV_A_STAGE;
        const bf16* Bh = (const bf16*)(dynsm + CV_B_OFF + (ci & 1) * CV_B_STAGE);
        const bf16* Bl = (const bf16*)((const unsigned char*)Bh + 10880);

#pragma unroll
        for (int ks = 0; ks < 2; ks++) {
            unsigned ah[2][4], al[2][4];
#pragma unroll
            for (int mt = 0; mt < 2; mt++) {
                int chunk = (((ks * 4 + wm) * 2 + mt) * 32 + lane) * 16;
                uint4 va = *(const uint4*)(Ab + chunk);
                ah[mt][0] = va.x; ah[mt][1] = va.y; ah[mt][2] = va.z; ah[mt][3] = va.w;
                uint4 vb = *(const uint4*)(Ab + 8192 + chunk);
                al[mt][0] = vb.x; al[mt][1] = vb.y; al[mt][2] = vb.z; al[mt][3] = vb.w;
            }
            const int kb = ks * 16 + (lane & 3) * 2;
#pragma unroll
            for (int nt = 0; nt < 8; nt++) {
                int row = wn * 64 + nt * 8 + (lane >> 2) + t;
                unsigned bh0 = *(const unsigned*)&Bh[row * APAD + kb];
                unsigned bh1 = *(const unsigned*)&Bh[row * APAD + kb + 8];
                unsigned bl0 = *(const unsigned*)&Bl[row * APAD + kb];
                unsigned bl1 = *(const unsigned*)&Bl[row * APAD + kb + 8];
#pragma unroll
                for (int mt = 0; mt < 2; mt++) {
                    mma_bf16(acc[mt][nt], ah[mt], bh0, bh1);
                    mma_bf16(acc[mt][nt], ah[mt], bl0, bl1);
                    mma_bf16(acc[mt][nt], al[mt], bh0, bh1);
                }
            }
        }
    }
    __syncthreads();

    // ---- epilogue: two 64-col passes through Cs[128][65] ----
    float* Cs = (float*)dynsm;
    const int ch0 = mb * 64;
#pragma unroll 1
    for (int p = 0; p < 2; p++) {
        if (wn == p) {
#pragma unroll
            for (int mt = 0; mt < 2; mt++)
#pragma unroll
                for (int nt = 0; nt < 8; nt++) {
                    int r = wm * 32 + mt * 16 + (lane >> 2);
                    int cl = nt * 8 + (lane & 3) * 2;
                    Cs[r * 65 + cl]           = acc[mt][nt][0];
                    Cs[r * 65 + cl + 1]       = acc[mt][nt][1];
                    Cs[(r + 8) * 65 + cl]     = acc[mt][nt][2];
                    Cs[(r + 8) * 65 + cl + 1] = acc[mt][nt][3];
                }
        }
        __syncthreads();
        const int lbase = l0 + p * 64;
        // GLU, stash hv into Cs a-half rows (no fp32 h output anymore)
#pragma unroll
        for (int i = 0; i < 16; i++) {
            int e = i * 256 + tid;
            int chl = e >> 6, ll = e & 63;
            float av = Cs[(chl * 2) * 65 + ll] + __ldg(&bias[ch0 + chl]);
            float bv = Cs[(chl * 2 + 1) * 65 + ll] + __ldg(&bias[512 + ch0 + chl]);
            float hv = av / (1.f + expf(-bv));
            Cs[(chl * 2) * 65 + ll] = hv;
        }
        __syncthreads();
        // transposed bf16 split write (c-fast) -> hT (b,l,c)
#pragma unroll
        for (int i = 0; i < 16; i++) {
            int e = i * 256 + tid;
            int chl = e & 63, ll = e >> 6;
            float hv = Cs[(chl * 2) * 65 + ll];
            bf16 hi, lo; split2(hv, hi, lo);
            size_t off = ((size_t)b * L_ + lbase + ll) * 512 + ch0 + chl;
            g_hTh[off] = hi; g_hTl[off] = lo;
        }
        __syncthreads();
    }
}

// ---------------------------------------------------------------------------
// fc GEMM (MODE 1: fc1, MODE 2: fc2), fragment-order A, single sync/iter.
//   smem: A 2x16384 @0 ; B 2x20480 @32768 ; mbar @73728
// ---------------------------------------------------------------------------
#define FC_A_STAGE 16384
#define FC_B_OFF   32768
#define FC_B_STAGE 20480
#define FC_MBAR    73728
#define FC_SMEM    73856

template <int MODE>
__global__ __launch_bounds__(256, 2) void fc_gemm(
    const float* __restrict__ bias, const float* __restrict__ e1,
    float* __restrict__ outp) {
    extern __shared__ __align__(16) unsigned char dynsm[];
    const int b = blockIdx.z, mb = blockIdx.y, l0 = blockIdx.x * 128;
    const int m0 = mb * 128;
    const int tid = threadIdx.x;
    const int lane = tid & 31, warp = tid >> 5;
    const int wm = warp >> 1, wn = warp & 1;

    const bf16* Wp  = (MODE == 1) ? g_w1p : g_w2p;
    const bf16* Bgh = (MODE == 1) ? g_hTh : g_cxh;   // (b, l, k)
    const bf16* Bgl = (MODE == 1) ? g_hTl : g_cxl;

    unsigned smem_base = (unsigned)__cvta_generic_to_shared(dynsm);
    unsigned mbar0 = smem_base + FC_MBAR, mbar1 = mbar0 + 8;
    if (tid == 0) { MBAR_INIT(mbar0, 1); MBAR_INIT(mbar1, 1); }
    __syncthreads();

    float acc[2][8][4];
#pragma unroll
    for (int mt = 0; mt < 2; mt++)
#pragma unroll
        for (int nt = 0; nt < 8; nt++)
#pragma unroll
            for (int j = 0; j < 4; j++) acc[mt][nt][j] = 0.f;

    auto issueA = [&](int s, int kc) {
        if (tid == 0) {
            unsigned mbx = s ? mbar1 : mbar0;
            MBAR_EXPECT(mbx, FC_A_STAGE);
            const char* src = (const char*)Wp + (size_t)(mb * 16 + kc) * FC_A_STAGE;
            bulk_g2s(smem_base + s * FC_A_STAGE, src, FC_A_STAGE, mbx);
        }
    };
    auto issueB = [&](int s, int kc) {
        unsigned char* dst0 = dynsm + FC_B_OFF + s * FC_B_STAGE;
#pragma unroll
        for (int ii = 0; ii < 4; ii++) {
            int u = ii * 256 + tid;
            int plane = u >> 9, v = u & 511;
            int r = v >> 2, j = v & 3;
            const bf16* src = (plane ? Bgl : Bgh) +
                ((size_t)b * L_ + l0 + r) * 512 + kc * 32 + j * 8;
            cp16(dst0 + plane * 10240 + r * 80 + j * 16, src);
        }
    };

    issueA(0, 0);
    issueB(0, 0);
    CP_COMMIT();
    int ph0 = 0, ph1 = 0;

    for (int i = 0; i < 16; i++) {
        const int s = i & 1;
        if (s == 0) { mbar_wait(mbar0, ph0); ph0 ^= 1; }
        else        { mbar_wait(mbar1, ph1); ph1 ^= 1; }
        CP_WAIT0();
        __syncthreads();

        if (i < 15) {
            issueA(s ^ 1, i + 1);
            issueB(s ^ 1, i + 1);
            CP_COMMIT();
        }

        const unsigned char* Ab = dynsm + s * FC_A_STAGE;
        const bf16* Bh = (const bf16*)(dynsm + FC_B_OFF + s * FC_B_STAGE);
        const bf16* Bl = (const bf16*)((const unsigned char*)Bh + 10240);

#pragma unroll
        for (int ks = 0; ks < 2; ks++) {
            unsigned ah[2][4], al[2][4];
#pragma unroll
            for (int mt = 0; mt < 2; mt++) {
                int chunk = (((ks * 4 + wm) * 2 + mt) * 32 + lane) * 16;
                uint4 va = *(const uint4*)(Ab + chunk);
                ah[mt][0] = va.x; ah[mt][1] = va.y; ah[mt][2] = va.z; ah[mt][3] = va.w;
                uint4 vb = *(const uint4*)(Ab + 8192 + chunk);
                al[mt][0] = vb.x; al[mt][1] = vb.y; al[mt][2] = vb.z; al[mt][3] = vb.w;
            }
            const int kb = ks * 16 + (lane & 3) * 2;
#pragma unroll
            for (int nt = 0; nt < 8; nt++) {
                int col = wn * 64 + nt * 8 + (lane >> 2);
                unsigned bh0 = *(const unsigned*)&Bh[col * APAD + kb];
                unsigned bh1 = *(const unsigned*)&Bh[col * APAD + kb + 8];
                unsigned bl0 = *(const unsigned*)&Bl[col * APAD + kb];
                unsigned bl1 = *(const unsigned*)&Bl[col * APAD + kb + 8];
#pragma unroll
                for (int mt = 0; mt < 2; mt++) {
                    mma_bf16(acc[mt][nt], ah[mt], bh0, bh1);
                    mma_bf16(acc[mt][nt], ah[mt], bl0, bl1);
                    mma_bf16(acc[mt][nt], al[mt], bh0, bh1);
                }
            }
        }
    }
    __syncthreads();

    // ---- epilogue ----
    float* Cs = (float*)dynsm;
#pragma unroll 1
    for (int p = 0; p < 2; p++) {
        if (wn == p) {
#pragma unroll
            for (int mt = 0; mt < 2; mt++)
#pragma unroll
                for (int nt = 0; nt < 8; nt++) {
                    int r = wm * 32 + mt * 16 + (lane >> 2);
                    int cl = nt * 8 + (lane & 3) * 2;
                    Cs[r * 65 + cl]           = acc[mt][nt][0];
                    Cs[r * 65 + cl + 1]       = acc[mt][nt][1];
                    Cs[(r + 8) * 65 + cl]     = acc[mt][nt][2];
                    Cs[(r + 8) * 65 + cl + 1] = acc[mt][nt][3];
                }
        }
        __syncthreads();
        const int lbase = l0 + p * 64;
        if (MODE == 1) {
#pragma unroll
            for (int i = 0; i < 32; i++) {
                int e = i * 256 + tid;
                int a = e & 127, ll = e >> 7;
                Cs[a * 65 + ll] += __ldg(&bias[m0 + a]) +
                    e1[((size_t)b * L_ + lbase + ll) * 512 + m0 + a];
            }
            __syncthreads();
#pragma unroll
            for (int i = 0; i < 32; i++) {
                int e = i * 256 + tid;
                int a = e & 127, ll = e >> 7;
                float v = Cs[a * 65 + ll];
                bf16 hi, lo; split2(v, hi, lo);
                size_t off = ((size_t)b * L_ + lbase + ll) * 512 + m0 + a;
                g_qh[off] = hi; g_ql[off] = lo;
            }
        } else {
            // pass A (c-fast, coalesced hT reads): Cs += b2 + (hTh + hTl)
#pragma unroll
            for (int i = 0; i < 32; i++) {
                int e = i * 256 + tid;
                int c = e & 127, ll = e >> 7;
                size_t hoff = ((size_t)b * L_ + lbase + ll) * 512 + m0 + c;
                Cs[c * 65 + ll] += __ldg(&bias[m0 + c]) +
                    __bfloat162float(g_hTh[hoff]) + __bfloat162float(g_hTl[hoff]);
            }
            __syncthreads();
            // pass B (l-fast, coalesced out/x): out = Cs + x
#pragma unroll
            for (int i = 0; i < 32; i++) {
                int e = i * 256 + tid;
                int cl_ = e >> 6, ll = e & 63;
                size_t off = ((size_t)b * 512 + m0 + cl_) * L_ + lbase + ll;
                outp[off] = Cs[cl_ * 65 + ll] + e1[off];
            }
        }
        __syncthreads();
    }
}

// ---------------------------------------------------------------------------
// Tensor-core attention (R15): phase S double-buffered cp.async staging,
// stage buffers alias the score region (scores materialize after the k-loop).
// Softmax writes probs in place as bf16 hi/lo planes inside each row's 904B
// footprint (hi @ +0, lo @ +452). Phase C: Bc via cp16, pitch 232 elems.
// smem: stages 2x56320 @0 (phase S) | ss [128][226] fp32 @0 (115712)
//       Bc_h @115712 (29696), Bc_l @145408 (29696), Cs [128][65] @175104 (33280)
// ---------------------------------------------------------------------------
#define SSP 226
#define SS_ROW 904
#define ATTN_STAGE 56320
#define ATTN_BC_H 115712
#define ATTN_BC_L 145408
#define ATTN_CS   175104
#define ATTN_SMEM_BYTES 208384
#define BCP 232   // Bc pitch in bf16 elems (464B rows)

__global__ __launch_bounds__(256, 1) void attn_tc_kernel(float* __restrict__ attn_out) {
    extern __shared__ __align__(16) unsigned char dynsm[];
    const int b  = blockIdx.y;
    const int l0 = blockIdx.x * 128;
    const int tid = threadIdx.x;
    const int lane = tid & 31, warp = tid >> 5;
    const int wm = warp >> 1, wn = warp & 1;

    // ================= Phase S: score GEMM, cp.async double-buffered ========
    float acc[2][14][4];
#pragma unroll
    for (int mt = 0; mt < 2; mt++)
#pragma unroll
        for (int nt = 0; nt < 14; nt++)
#pragma unroll
            for (int j = 0; j < 4; j++) acc[mt][nt][j] = 0.f;

    auto issueS = [&](int s, int k0) {
        unsigned char* st = dynsm + s * ATTN_STAGE;
#pragma unroll
        for (int ii = 0; ii < 11; ii++) {
            int u = ii * 256 + tid;
            if (u < 1024) {
                int plane = (u >= 512) ? 1 : 0;
                int v = u - plane * 512;
                int row = v >> 2, j = v & 3;
                const bf16* src = (plane ? g_ql : g_qh) +
                    ((size_t)b * L_ + l0 + row) * 512 + k0 + j * 8;
                cp16(st + plane * 10240 + row * 80 + j * 16, src);
            } else {
                int w = u - 1024;              // < 1792
                int plane = (w >= 896) ? 1 : 0;
                int v = w - plane * 896;
                int row = v >> 2, j = v & 3;
                const bf16* src = (plane ? g_fTl : g_fTh) +
                    ((size_t)b * PP + row) * 512 + k0 + j * 8;
                cp16(st + 20480 + plane * 17920 + row * 80 + j * 16, src);
            }
        }
    };

    issueS(0, 0);
    CP_COMMIT();

    for (int it = 0; it < 16; it++) {
        CP_WAIT0();
        __syncthreads();
        if (it < 15) { issueS((it + 1) & 1, (it + 1) * 32); CP_COMMIT(); }

        const unsigned char* st = dynsm + (it & 1) * ATTN_STAGE;
        const bf16* As_h = (const bf16*)st;
        const bf16* As_l = (const bf16*)(st + 10240);
        const bf16* Bs_h = (const bf16*)(st + 20480);
        const bf16* Bs_l = (const bf16*)(st + 38400);

#pragma unroll
        for (int ks = 0; ks < BK; ks += 16) {
            const int kb = ks + (lane & 3) * 2;
            unsigned ah[2][4], al[2][4];
#pragma unroll
            for (int mt = 0; mt < 2; mt++) {
                int rb = wm * 32 + mt * 16 + (lane >> 2);
                ah[mt][0] = *(const unsigned*)&As_h[rb * APAD + kb];
                ah[mt][1] = *(const unsigned*)&As_h[(rb + 8) * APAD + kb];
                ah[mt][2] = *(const unsigned*)&As_h[rb * APAD + kb + 8];
                ah[mt][3] = *(const unsigned*)&As_h[(rb + 8) * APAD + kb + 8];
                al[mt][0] = *(const unsigned*)&As_l[rb * APAD + kb];
                al[mt][1] = *(const unsigned*)&As_l[(rb + 8) * APAD + kb];
                al[mt][2] = *(const unsigned*)&As_l[rb * APAD + kb + 8];
                al[mt][3] = *(const unsigned*)&As_l[(rb + 8) * APAD + kb + 8];
            }
#pragma unroll
            for (int nt = 0; nt < 14; nt++) {
                int col = wn * 112 + nt * 8 + (lane >> 2);
                unsigned bh0 = *(const unsigned*)&Bs_h[col * APAD + kb];
                unsigned bh1 = *(const unsigned*)&Bs_h[col * APAD + kb + 8];
                unsigned bl0 = *(const unsigned*)&Bs_l[col * APAD + kb];
                unsigned bl1 = *(const unsigned*)&Bs_l[col * APAD + kb + 8];
#pragma unroll
                for (int mt = 0; mt < 2; mt++) {
                    mma_bf16(acc[mt][nt], ah[mt], bh0, bh1);
                    mma_bf16(acc[mt][nt], ah[mt], bl0, bl1);
                    mma_bf16(acc[mt][nt], al[mt], bh0, bh1);
                }
            }
        }
    }
    __syncthreads();   // stage buffers dead; ss region becomes live

    // scatter scores to ss [128][SSP] fp32
    float* ss = (float*)dynsm;
#pragma unroll
    for (int mt = 0; mt < 2; mt++)
#pragma unroll
        for (int nt = 0; nt < 14; nt++) {
            int r = wm * 32 + mt * 16 + (lane >> 2);
            int cl = wn * 112 + nt * 8 + (lane & 3) * 2;
            ss[r * SSP + cl]           = acc[mt][nt][0];
            ss[r * SSP + cl + 1]       = acc[mt][nt][1];
            ss[(r + 8) * SSP + cl]     = acc[mt][nt][2];
            ss[(r + 8) * SSP + cl + 1] = acc[mt][nt][3];
        }
    __syncthreads();

    // ===== Softmax: reads fp32 row, writes attn_out + in-place bf16 planes =====
    for (int r = 0; r < 16; r++) {
        int row = warp * 16 + r;
        float v[7];
        float mx = -1e30f;
#pragma unroll
        for (int k = 0; k < 7; k++) {
            int p = lane + 32 * k;
            v[k] = (p < HW) ? ss[row * SSP + p] : -1e30f;
            mx = fmaxf(mx, v[k]);
        }
#pragma unroll
        for (int off = 16; off > 0; off >>= 1)
            mx = fmaxf(mx, __shfl_xor_sync(0xffffffffu, mx, off));
        float s = 0.f;
#pragma unroll
        for (int k = 0; k < 7; k++) {
            int p = lane + 32 * k;
            if (p < HW) { v[k] = expf(v[k] - mx); s += v[k]; }
        }
#pragma unroll
        for (int off = 16; off > 0; off >>= 1)
            s += __shfl_xor_sync(0xffffffffu, s, off);
        float inv = 1.f / s;
        float* ao = attn_out + ((size_t)b * L_ + l0 + row) * HW;
        bf16* rh = (bf16*)(dynsm + (size_t)row * SS_ROW);
        bf16* rl = (bf16*)(dynsm + (size_t)row * SS_ROW + 452);
        const bf16 z = __float2bfloat16(0.f);
#pragma unroll
        for (int k = 0; k < 7; k++) {
            int p = lane + 32 * k;
            if (p < HW) {
                float a = v[k] * inv;
                ao[p] = a;
                bf16 hi, lo; split2(a, hi, lo);
                rh[p] = hi; rl[p] = lo;
            } else {
                rh[p] = z; rl[p] = z;
            }
        }
    }
    __syncthreads();

    // ================= Phase C: ctx GEMM (fragments from bf16 planes) =========
    bf16* Bc_h = (bf16*)(dynsm + ATTN_BC_H);
    bf16* Bc_l = (bf16*)(dynsm + ATTN_BC_L);
    float* Cs  = (float*)(dynsm + ATTN_CS);

#pragma unroll 1
    for (int a0 = 0; a0 < 512; a0 += 64) {
        // stage Bc [64 a][224 p] hi/lo via cp16 (pitch BCP=232 elems / 464B)
#pragma unroll
        for (int ii = 0; ii < 14; ii++) {
            int u = ii * 256 + tid;
            int plane = (u >= 1792) ? 1 : 0;
            int v = u - plane * 1792;
            int row = v / 28, j = v - row * 28;
            const bf16* src = (plane ? g_fl : g_fh) +
                ((size_t)b * 512 + a0 + row) * PP + j * 8;
            bf16* dstp = plane ? Bc_l : Bc_h;
            cp16((unsigned char*)dstp + row * 464 + j * 16, src);
        }
        CP_COMMIT();
        CP_WAIT0();
        __syncthreads();

        float ac2[2][4][4];
#pragma unroll
        for (int mt = 0; mt < 2; mt++)
#pragma unroll
            for (int nt = 0; nt < 4; nt++)
#pragma unroll
                for (int j = 0; j < 4; j++) ac2[mt][nt][j] = 0.f;

#pragma unroll 2
        for (int p0 = 0; p0 < PP; p0 += 16) {
            const int kb = p0 + (lane & 3) * 2;
            unsigned ah[2][4], al[2][4];
#pragma unroll
            for (int mt = 0; mt < 2; mt++) {
                int rb = wm * 32 + mt * 16 + (lane >> 2);
#pragma unroll
                for (int f = 0; f < 4; f++) {
                    int rr = rb + ((f & 1) ? 8 : 0);
                    int cc = kb + ((f & 2) ? 8 : 0);
                    ah[mt][f] = *(const unsigned*)(dynsm + (size_t)rr * SS_ROW + cc * 2);
                    al[mt][f] = *(const unsigned*)(dynsm + (size_t)rr * SS_ROW + 452 + cc * 2);
                }
            }
#pragma unroll
            for (int nt = 0; nt < 4; nt++) {
                int col = wn * 32 + nt * 8 + (lane >> 2);
                unsigned bh0 = *(const unsigned*)&Bc_h[col * BCP + kb];
                unsigned bh1 = *(const unsigned*)&Bc_h[col * BCP + kb + 8];
                unsigned bl0 = *(const unsigned*)&Bc_l[col * BCP + kb];
                unsigned bl1 = *(const unsigned*)&Bc_l[col * BCP + kb + 8];
#pragma unroll
                for (int mt = 0; mt < 2; mt++) {
                    mma_bf16(ac2[mt][nt], ah[mt], bh0, bh1);
                    mma_bf16(ac2[mt][nt], ah[mt], bl0, bl1);
                    mma_bf16(ac2[mt][nt], al[mt], bh0, bh1);
                }
            }
        }

#pragma unroll
        for (int mt = 0; mt < 2; mt++)
#pragma unroll
            for (int nt = 0; nt < 4; nt++) {
                int r = wm * 32 + mt * 16 + (lane >> 2);
                int cl = wn * 32 + nt * 8 + (lane & 3) * 2;
                Cs[r * 65 + cl]           = ac2[mt][nt][0];
                Cs[r * 65 + cl + 1]       = ac2[mt][nt][1];
                Cs[(r + 8) * 65 + cl]     = ac2[mt][nt][2];
                Cs[(r + 8) * 65 + cl + 1] = ac2[mt][nt][3];
            }
        __syncthreads();

        // write ctx split bf16, layout (b, l, a), coalesced over a
#pragma unroll
        for (int i = 0; i < 32; i++) {
            int e = i * 256 + tid;
            int a = e & 63, l = e >> 6;
            float v = Cs[l * 65 + a];
            bf16 hi, lo; split2(v, hi, lo);
            size_t off = ((size_t)b * L_ + l0 + l) * 512 + a0 + a;
            g_cxh[off] = hi; g_cxl[off] = lo;
        }
        __syncthreads();
    }
}

// ---------------------------------------------------------------------------
extern "C" void kernel_launch(void* const* d_in, const int* in_sizes, int n_in,
                              void* d_out, int out_size) {
    (void)in_sizes; (void)n_in; (void)out_size;
    const float* x      = (const float*)d_in[0];
    const float* we     = (const float*)d_in[1];
    const float* img    = (const float*)d_in[2];
    /* d_in[3] prev_attn unused */
    const float* conv_v = (const float*)d_in[4];
    const float* conv_g = (const float*)d_in[5];
    const float* conv_b = (const float*)d_in[6];
    const float* fc1_w  = (const float*)d_in[7];
    const float* fc1_b  = (const float*)d_in[8];
    const float* fc2_w  = (const float*)d_in[9];
    const float* fc2_b  = (const float*)d_in[10];
    float* out = (float*)d_out;

    // passthrough copies
    cudaMemcpyAsync(out + OUT_WE, we, (size_t)B_ * L_ * DW * sizeof(float),
                    cudaMemcpyDeviceToDevice, 0);
    cudaMemcpyAsync(out + OUT_IMG, img, (size_t)B_ * DW * HW * sizeof(float),
                    cudaMemcpyDeviceToDevice, 0);

    void *p_w1p, *p_w2p;
    cudaGetSymbolAddress(&p_w1p, g_w1p);
    cudaGetSymbolAddress(&p_w2p, g_w2p);

    // prep
    wnorm_kernel<<<COUT, 256>>>(conv_v, conv_g);
    pack_conv_kernel<<<dim3(80, 8), 256>>>();
    pack_fc_kernel<<<dim3(16, 4, 8), 256>>>(fc1_w, fc2_w, (bf16*)p_w1p, (bf16*)p_w2p);
    xT_kernel<<<dim3(L_ / 32, CIN / 32, B_), dim3(32, 8)>>>(x);
    featT_kernel<<<dim3(PP / 32, 512 / 32, B_), dim3(32, 8)>>>(img);

    // opt-in dynamic smem
    cudaFuncSetAttribute(conv_gemm, cudaFuncAttributeMaxDynamicSharedMemorySize, CV_SMEM);
    cudaFuncSetAttribute(fc_gemm<1>, cudaFuncAttributeMaxDynamicSharedMemorySize, FC_SMEM);
    cudaFuncSetAttribute(fc_gemm<2>, cudaFuncAttributeMaxDynamicSharedMemorySize, FC_SMEM);
    cudaFuncSetAttribute(attn_tc_kernel, cudaFuncAttributeMaxDynamicSharedMemorySize,
                         ATTN_SMEM_BYTES);

    // conv + GLU  (M=1024 interleaved, N=1024, K=2560), tile 128x128
    conv_gemm<<<dim3(L_ / 128, 8, B_), 256, CV_SMEM>>>(conv_b);
    // fc1 (M=512, N=1024, K=512) -> q bf16 (b,l,a)
    fc_gemm<1><<<dim3(L_ / 128, 4, B_), 256, FC_SMEM>>>(fc1_b, we, nullptr);
    // tensor-core attention -> attn output + ctx (b,l,a)
    attn_tc_kernel<<<dim3(L_ / 128, B_), 256, ATTN_SMEM_BYTES>>>(out + OUT_ATTN);
    // fc2 + residuals (M=512, N=1024, K=512)
    fc_gemm<2><<<dim3(L_ / 128, 4, B_), 256, FC_SMEM>>>(fc2_b, x, out);
}